// round 4
// baseline (speedup 1.0000x reference)
#include <cuda_runtime.h>
#include <cuda_bf16.h>
#include <math.h>
#include <stdint.h>

// Problem constants
#define BB 4
#define NNTOK 1024
#define DDIM 1024
#define HH 16
#define TT (BB*NNTOK)     // 4096 tokens
#define BHN (BB*HH)       // 64
#define QKLD 96           // padded lifted q/k leading dim

typedef __nv_bfloat16 bf16;

// ===================== scratch (device globals) =====================
__device__ __align__(128) bf16  g_lxh [TT*1024];
__device__ __align__(128) bf16  g_lxl [TT*1024];
__device__ __align__(128) bf16  g_WqTh[1024*1024];
__device__ __align__(128) bf16  g_WqTl[1024*1024];
__device__ __align__(128) bf16  g_WkTh[1024*1024];
__device__ __align__(128) bf16  g_WkTl[1024*1024];
__device__ __align__(128) bf16  g_WvTh[1024*1024];
__device__ __align__(128) bf16  g_WvTl[1024*1024];
__device__ __align__(128) bf16  g_WoTh[1024*1088];
__device__ __align__(128) bf16  g_WoTl[1024*1088];
__device__ __align__(128) bf16  g_WfcTh[4096*1024];
__device__ __align__(128) bf16  g_WfcTl[4096*1024];
__device__ __align__(128) bf16  g_WpjTh[1024*4096];
__device__ __align__(128) bf16  g_WpjTl[1024*4096];
__device__ __align__(128) float g_qs  [TT*1024];
__device__ __align__(128) float g_ks  [TT*1024];
__device__ __align__(128) float g_vs  [TT*1024];
__device__ __align__(128) bf16  g_qhh [BHN*1024*QKLD];
__device__ __align__(128) bf16  g_qhl [BHN*1024*QKLD];
__device__ __align__(128) bf16  g_khh [BHN*1024*QKLD];
__device__ __align__(128) bf16  g_khl [BHN*1024*QKLD];
__device__ __align__(128) bf16  g_vTh [BHN*128*1024];
__device__ __align__(128) bf16  g_vTl [BHN*128*1024];
__device__ __align__(128) float g_sc  [(size_t)BHN*1024*1024];  // 256MB
__device__ __align__(128) bf16  g_ph  [(size_t)BHN*1024*1024];
__device__ __align__(128) bf16  g_pl  [(size_t)BHN*1024*1024];
__device__ __align__(128) float g_mid [BHN*1024*65];
__device__ __align__(128) bf16  g_cath[TT*1088];
__device__ __align__(128) bf16  g_catl[TT*1088];
__device__ __align__(128) float g_axs [TT*1023];
__device__ __align__(128) float g_x1  [TT*1024];
__device__ __align__(128) bf16  g_h1h [TT*1024];
__device__ __align__(128) bf16  g_h1l [TT*1024];
__device__ __align__(128) float g_fcpre[(size_t)TT*4095];
__device__ __align__(128) bf16  g_fch [(size_t)TT*4096];
__device__ __align__(128) bf16  g_fcl [(size_t)TT*4096];
__device__ __align__(128) float g_pjs [TT*1023];

// ===================== PTX helpers =====================
__device__ __forceinline__ uint32_t smem_u32(const void* p) {
    uint32_t a;
    asm("{ .reg .u64 t; cvta.to.shared.u64 t, %1; cvt.u32.u64 %0, t; }" : "=r"(a) : "l"(p));
    return a;
}

#define CP_ASYNC16(dst, src) \
    asm volatile("cp.async.cg.shared.global [%0], [%1], 16;" :: "r"(dst), "l"(src))
#define CP_COMMIT() asm volatile("cp.async.commit_group;")
#define CP_WAIT1()  asm volatile("cp.async.wait_group 1;")
#define CP_WAIT0()  asm volatile("cp.async.wait_group 0;")

__device__ __forceinline__ void ldsm4(uint32_t* r, uint32_t addr) {
    asm volatile("ldmatrix.sync.aligned.m8n8.x4.shared.b16 {%0,%1,%2,%3}, [%4];"
        : "=r"(r[0]), "=r"(r[1]), "=r"(r[2]), "=r"(r[3]) : "r"(addr));
}

__device__ __forceinline__ void mma16816(float* c, const uint32_t* a, const uint32_t* b) {
    asm volatile(
        "mma.sync.aligned.m16n8k16.row.col.f32.bf16.bf16.f32 "
        "{%0,%1,%2,%3}, {%4,%5,%6,%7}, {%8,%9}, {%0,%1,%2,%3};"
        : "+f"(c[0]), "+f"(c[1]), "+f"(c[2]), "+f"(c[3])
        : "r"(a[0]), "r"(a[1]), "r"(a[2]), "r"(a[3]), "r"(b[0]), "r"(b[1]));
}

__device__ __forceinline__ void bsplit(float v, bf16& h, bf16& l) {
    h = __float2bfloat16(v);
    l = __float2bfloat16(v - __bfloat162float(h));
}

// ===================== block reductions =====================
__device__ __forceinline__ float blk_sum(float v, float* sbuf) {
    int tid = threadIdx.x;
    #pragma unroll
    for (int o = 16; o > 0; o >>= 1) v += __shfl_down_sync(0xffffffffu, v, o);
    if ((tid & 31) == 0) sbuf[tid >> 5] = v;
    __syncthreads();
    if (tid < 32) {
        int nw = (blockDim.x + 31) >> 5;
        float x = (tid < nw) ? sbuf[tid] : 0.f;
        #pragma unroll
        for (int o = 16; o > 0; o >>= 1) x += __shfl_down_sync(0xffffffffu, x, o);
        if (tid == 0) sbuf[0] = x;
    }
    __syncthreads();
    float r = sbuf[0];
    __syncthreads();
    return r;
}
__device__ __forceinline__ float blk_max(float v, float* sbuf) {
    int tid = threadIdx.x;
    #pragma unroll
    for (int o = 16; o > 0; o >>= 1) v = fmaxf(v, __shfl_down_sync(0xffffffffu, v, o));
    if ((tid & 31) == 0) sbuf[tid >> 5] = v;
    __syncthreads();
    if (tid < 32) {
        int nw = (blockDim.x + 31) >> 5;
        float x = (tid < nw) ? sbuf[tid] : -3.4e38f;
        #pragma unroll
        for (int o = 16; o > 0; o >>= 1) x = fmaxf(x, __shfl_down_sync(0xffffffffu, x, o));
        if (tid == 0) sbuf[0] = x;
    }
    __syncthreads();
    float r = sbuf[0];
    __syncthreads();
    return r;
}

// ===================== mma.sync GEMM (ldmatrix loads) =====================
// D[m0+r][c0+n] = alpha*(Ah·Bh^T + Ah·Bl^T + Al·Bh^T)[r][n] + cadd + bias[n]
// A (hi/lo): M x K bf16 row-major (lda); B (hi/lo): Npad x K bf16 row-major (ldb)
// C fp32 ldc; writes only n < Nreal. M mult of 128, K mult of 32.
#define STG_MAT 10240
#define STG_SZ  40960
#define SMEM_GEMM (2*STG_SZ)

__global__ __launch_bounds__(256)
void mma_gemm(const bf16* __restrict__ Ah, const bf16* __restrict__ Al,
              const bf16* __restrict__ Bh, const bf16* __restrict__ Bl,
              const float* __restrict__ bias, float* __restrict__ C,
              int lda, int ldb, int ldc, int c0, int Nreal, int K,
              long long sA, long long sB, long long sC,
              float alpha, float cadd)
{
    extern __shared__ char smem[];
    uint32_t sbase = smem_u32(smem);
    int tid = threadIdx.x, w = tid >> 5, lane = tid & 31;
    long long bz = blockIdx.z;
    Ah += bz * sA; Al += bz * sA;
    Bh += bz * sB; Bl += bz * sB;
    C  += bz * sC;
    int m0 = blockIdx.y * 128, n0 = blockIdx.x * 128;
    const int NC = K >> 5;

    auto load_stage = [&](int kofs, int s) {
        uint32_t stg = sbase + s * STG_SZ;
        #pragma unroll
        for (int i = 0; i < 8; i++) {
            int idx = tid + i * 256;          // 0..2047
            int mat = idx >> 9;               // 0:Ah 1:Al 2:Bh 3:Bl
            int cc  = idx & 511;
            int row = cc >> 2, kc = cc & 3;
            uint32_t dst = stg + mat * STG_MAT + row * 80 + kc * 16;
            const bf16* p = (mat == 0) ? Ah : (mat == 1) ? Al : (mat == 2) ? Bh : Bl;
            int b0 = (mat < 2) ? m0 : n0;
            int ld = (mat < 2) ? lda : ldb;
            CP_ASYNC16(dst, p + (size_t)(b0 + row) * ld + kofs + kc * 8);
        }
        CP_COMMIT();
    };

    load_stage(0, 0);
    if (NC > 1) load_stage(32, 1);

    int g = lane >> 2, t = lane & 3;
    int wm = (w & 3) * 32, wn = (w >> 2) * 64;

    // ldmatrix per-lane base offsets (80B row stride)
    uint32_t offA = (uint32_t)((wm + (lane & 15)) * 80 + ((lane >> 4) << 4));
    uint32_t offB = (uint32_t)((wn + (lane & 7) + ((lane >> 4) << 3)) * 80 + (((lane >> 3) & 1) << 4));

    float acc[2][8][4];
    #pragma unroll
    for (int mt = 0; mt < 2; mt++)
        #pragma unroll
        for (int nt = 0; nt < 8; nt++)
            #pragma unroll
            for (int r = 0; r < 4; r++) acc[mt][nt][r] = 0.f;

    for (int kc = 0; kc < NC; kc++) {
        if (kc + 1 < NC) { CP_WAIT1(); } else { CP_WAIT0(); }
        __syncthreads();
        uint32_t stg = sbase + (kc & 1) * STG_SZ;
        uint32_t aH_base = stg + offA;
        uint32_t aL_base = stg + STG_MAT + offA;
        uint32_t bH_base = stg + 2 * STG_MAT + offB;
        uint32_t bL_base = stg + 3 * STG_MAT + offB;

        #pragma unroll
        for (int ko = 0; ko < 32; ko += 16) {
            uint32_t aH[2][4], aL[2][4], b[4][4];
            ldsm4(aH[0], aH_base + ko * 2);
            ldsm4(aH[1], aH_base + 1280 + ko * 2);
            ldsm4(aL[0], aL_base + ko * 2);
            ldsm4(aL[1], aL_base + 1280 + ko * 2);
            #pragma unroll
            for (int j = 0; j < 4; j++) ldsm4(b[j], bH_base + j * 1280 + ko * 2);
            // Bh pass: acc += Ah*Bh + Al*Bh
            #pragma unroll
            for (int mt = 0; mt < 2; mt++)
                #pragma unroll
                for (int j = 0; j < 4; j++) {
                    mma16816(acc[mt][2 * j],     aH[mt], b[j]);
                    mma16816(acc[mt][2 * j],     aL[mt], b[j]);
                    mma16816(acc[mt][2 * j + 1], aH[mt], b[j] + 2);
                    mma16816(acc[mt][2 * j + 1], aL[mt], b[j] + 2);
                }
            // Bl pass: acc += Ah*Bl (reuse b regs)
            #pragma unroll
            for (int j = 0; j < 4; j++) ldsm4(b[j], bL_base + j * 1280 + ko * 2);
            #pragma unroll
            for (int mt = 0; mt < 2; mt++)
                #pragma unroll
                for (int j = 0; j < 4; j++) {
                    mma16816(acc[mt][2 * j],     aH[mt], b[j]);
                    mma16816(acc[mt][2 * j + 1], aH[mt], b[j] + 2);
                }
        }
        __syncthreads();
        if (kc + 2 < NC) load_stage((kc + 2) * 32, kc & 1);
    }

    // epilogue
    #pragma unroll
    for (int mt = 0; mt < 2; mt++) {
        int r0 = m0 + wm + mt * 16 + g;
        float* c0p = C + (size_t)r0 * ldc + c0;
        float* c1p = C + (size_t)(r0 + 8) * ldc + c0;
        #pragma unroll
        for (int nt = 0; nt < 8; nt++) {
            int n = n0 + wn + nt * 8 + t * 2;
            if (n < Nreal) {
                float bv = bias ? bias[n] : 0.f;
                c0p[n] = alpha * acc[mt][nt][0] + cadd + bv;
                c1p[n] = alpha * acc[mt][nt][2] + cadd + bv;
            }
            if (n + 1 < Nreal) {
                float bv = bias ? bias[n + 1] : 0.f;
                c0p[n + 1] = alpha * acc[mt][nt][1] + cadd + bv;
                c1p[n + 1] = alpha * acc[mt][nt][3] + cadd + bv;
            }
        }
    }
}

// ===================== transpose+split weights =====================
__global__ void k_tsplit(const float* __restrict__ W, bf16* __restrict__ Th,
                         bf16* __restrict__ Tl, int K, int N, int Kpad)
{
    __shared__ float t[32][33];
    int nb = blockIdx.x * 32, kb = blockIdx.y * 32;
    int tx = threadIdx.x, ty = threadIdx.y;
    #pragma unroll
    for (int i = 0; i < 32; i += 8) {
        int k = kb + ty + i, n = nb + tx;
        t[ty + i][tx] = (k < K && n < N) ? W[(size_t)k * N + n] : 0.f;
    }
    __syncthreads();
    #pragma unroll
    for (int i = 0; i < 32; i += 8) {
        int n = nb + ty + i, k = kb + tx;
        if (n < N && k < K) {
            float v = t[tx][ty + i];
            bf16 h, l; bsplit(v, h, l);
            Th[(size_t)n * Kpad + k] = h;
            Tl[(size_t)n * Kpad + k] = l;
        }
    }
}

// ===================== Lorentz layernorm -> hi/lo =====================
__global__ __launch_bounds__(256)
void k_ln(const float* __restrict__ x, const float* __restrict__ g,
          const float* __restrict__ b, bf16* __restrict__ oh, bf16* __restrict__ ol)
{
    __shared__ float sbuf[32];
    int t = blockIdx.x, tid = threadIdx.x;
    const float* xs = x + (size_t)t * 1024 + 1;
    float sv[4]; float s1 = 0.f, s2 = 0.f;
    #pragma unroll
    for (int j = 0; j < 4; j++) {
        int i = tid + j * 256;
        sv[j] = 0.f;
        if (i < 1023) { sv[j] = xs[i]; s1 += sv[j]; s2 += sv[j] * sv[j]; }
    }
    s1 = blk_sum(s1, sbuf);
    s2 = blk_sum(s2, sbuf);
    float mu = s1 * (1.f / 1023.f);
    float var = s2 * (1.f / 1023.f) - mu * mu;
    float rstd = rsqrtf(var + 1e-5f);
    float q = 0.f;
    float yv[4];
    #pragma unroll
    for (int j = 0; j < 4; j++) {
        int i = tid + j * 256;
        yv[j] = 0.f;
        if (i < 1023) {
            yv[j] = (sv[j] - mu) * rstd * g[i] + b[i];
            q += yv[j] * yv[j];
        }
    }
    q = blk_sum(q, sbuf);
    size_t base = (size_t)t * 1024;
    #pragma unroll
    for (int j = 0; j < 4; j++) {
        int i = tid + j * 256;
        if (i < 1023) {
            bf16 h, l; bsplit(yv[j], h, l);
            oh[base + 1 + i] = h; ol[base + 1 + i] = l;
        }
    }
    if (tid == 0) {
        bf16 h, l; bsplit(sqrtf(q + 1.f), h, l);
        oh[base] = h; ol[base] = l;
    }
}

// ===================== lift heads (q/k): (T,1024) -> (BH,N,QKLD) hi/lo =====================
__global__ __launch_bounds__(512)
void k_lift(const float* __restrict__ S, bf16* __restrict__ Oh, bf16* __restrict__ Ol, float sign)
{
    int t = blockIdx.x;
    int b = t >> 10, n = t & 1023;
    int w = threadIdx.x >> 5, lane = threadIdx.x & 31;
    const float* src = S + (size_t)t * 1024 + w * 64;
    float v0 = src[lane], v1 = src[lane + 32];
    float ss = v0 * v0 + v1 * v1;
    #pragma unroll
    for (int o = 16; o > 0; o >>= 1) ss += __shfl_down_sync(0xffffffffu, ss, o);
    ss = __shfl_sync(0xffffffffu, ss, 0);
    size_t base = ((size_t)(b * HH + w) * 1024 + n) * QKLD;
    bf16 h, l;
    bsplit(v0, h, l); Oh[base + 1 + lane] = h; Ol[base + 1 + lane] = l;
    bsplit(v1, h, l); Oh[base + 33 + lane] = h; Ol[base + 33 + lane] = l;
    if (lane == 0) {
        bsplit(sign * sqrtf(ss + 1.f), h, l);
        Oh[base] = h; Ol[base] = l;
    }
    // zero pads 65..QKLD-1
    for (int i = 65 + lane; i < QKLD; i += 32) {
        Oh[base + i] = __float2bfloat16(0.f);
        Ol[base + i] = __float2bfloat16(0.f);
    }
}

// ===================== lift+transpose v =====================
__global__ void k_liftT(const float* __restrict__ vs, bf16* __restrict__ Th, bf16* __restrict__ Tl)
{
    int blk = blockIdx.x;
    int bh = blk >> 5;
    int tg = blk & 31;
    int b = bh >> 4, h = bh & 15;
    __shared__ float sv[32][65];
    __shared__ float stime[32];
    int tx = threadIdx.x, ty = threadIdx.y;
    #pragma unroll
    for (int i = 0; i < 32; i += 8) {
        int tok = i + ty;
        const float* src = vs + (size_t)(b * 1024 + tg * 32 + tok) * 1024 + h * 64;
        sv[tok][1 + tx] = src[tx];
        sv[tok][33 + tx] = src[tx + 32];
    }
    __syncthreads();
    if (ty == 0) {
        float s = 0.f;
        #pragma unroll
        for (int d = 1; d <= 64; d++) { float x = sv[tx][d]; s += x * x; }
        stime[tx] = sqrtf(s + 1.f);
    }
    __syncthreads();
    size_t base = (size_t)bh * (128 * 1024) + (size_t)(tg * 32);
    for (int d = ty; d < 128; d += 8) {
        float v = (d == 0) ? stime[tx] : (d < 65 ? sv[tx][d] : 0.f);
        bf16 hh, ll; bsplit(v, hh, ll);
        Th[base + (size_t)d * 1024 + tx] = hh;
        Tl[base + (size_t)d * 1024 + tx] = ll;
    }
}

// ===================== softmax -> probs hi/lo =====================
__global__ __launch_bounds__(256)
void k_softmax(const float* __restrict__ sc, bf16* __restrict__ ph, bf16* __restrict__ pl)
{
    __shared__ float sbuf[32];
    size_t off = (size_t)blockIdx.x * 1024;
    const float* row = sc + off;
    int tid = threadIdx.x;
    float v[4];
    float m = -3.4e38f;
    #pragma unroll
    for (int j = 0; j < 4; j++) { v[j] = row[tid + j * 256]; m = fmaxf(m, v[j]); }
    m = blk_max(m, sbuf);
    float s = 0.f;
    #pragma unroll
    for (int j = 0; j < 4; j++) { v[j] = __expf(v[j] - m); s += v[j]; }
    s = blk_sum(s, sbuf);
    float inv = 1.f / s;
    #pragma unroll
    for (int j = 0; j < 4; j++) {
        float p = v[j] * inv;
        bf16 h, l; bsplit(p, h, l);
        ph[off + tid + j * 256] = h;
        pl[off + tid + j * 256] = l;
    }
}

// ===================== normalize mid + concat =====================
__global__ __launch_bounds__(512)
void k_normcat(const float* __restrict__ mid, bf16* __restrict__ ch, bf16* __restrict__ cl)
{
    int t = blockIdx.x;
    int b = t >> 10, n = t & 1023;
    int w = threadIdx.x >> 5, lane = threadIdx.x & 31;
    const float* src = mid + ((size_t)(b * HH + w) * 1024 + n) * 65;
    float tmv = src[0];
    float a0 = src[1 + lane], a1 = src[33 + lane];
    float ss = a0 * a0 + a1 * a1;
    #pragma unroll
    for (int o = 16; o > 0; o >>= 1) ss += __shfl_down_sync(0xffffffffu, ss, o);
    ss = __shfl_sync(0xffffffffu, ss, 0);
    float inv = rsqrtf(fmaxf(tmv * tmv - ss, 1e-8f));
    size_t base = (size_t)t * 1088 + w * 65;
    bf16 h, l;
    bsplit(a0 * inv, h, l); ch[base + 1 + lane] = h; cl[base + 1 + lane] = l;
    bsplit(a1 * inv, h, l); ch[base + 33 + lane] = h; cl[base + 33 + lane] = l;
    if (lane == 0) { bsplit(tmv * inv, h, l); ch[base] = h; cl[base] = l; }
}

// ===================== gelu + lift =====================
__global__ __launch_bounds__(256)
void k_gelu(const float* __restrict__ fcpre, bf16* __restrict__ fh, bf16* __restrict__ fl)
{
    __shared__ float sbuf[32];
    int t = blockIdx.x, tid = threadIdx.x;
    const float* rin = fcpre + (size_t)t * 4095;
    float gv[16];
    float q = 0.f;
    #pragma unroll
    for (int j = 0; j < 16; j++) {
        int i = tid + j * 256;
        gv[j] = 0.f;
        if (i < 4095) {
            float x = rin[i];
            gv[j] = 0.5f * x * (1.f + erff(x * 0.70710678118654752f));
            q += gv[j] * gv[j];
        }
    }
    q = blk_sum(q, sbuf);
    size_t base = (size_t)t * 4096;
    #pragma unroll
    for (int j = 0; j < 16; j++) {
        int i = tid + j * 256;
        if (i < 4095) {
            bf16 h, l; bsplit(gv[j], h, l);
            fh[base + 1 + i] = h; fl[base + 1 + i] = l;
        }
    }
    if (tid == 0) {
        bf16 h, l; bsplit(sqrtf(q + 1.f), h, l);
        fh[base] = h; fl[base] = l;
    }
}

// ===================== Lorentz residual =====================
__global__ __launch_bounds__(256)
void k_lresnet(const float* __restrict__ xin, const float* __restrict__ spart,
               const float* __restrict__ wp, float* __restrict__ out)
{
    __shared__ float sbuf[32];
    int t = blockIdx.x, tid = threadIdx.x;
    float w = wp[0];
    const float* xr = xin + (size_t)t * 1024;
    const float* ar = spart + (size_t)t * 1023;
    float xs[4], as[4];
    float sa = 0.f;
    #pragma unroll
    for (int j = 0; j < 4; j++) {
        int i = tid + j * 256;
        xs[j] = 0.f; as[j] = 0.f;
        if (i < 1023) { xs[j] = xr[1 + i]; as[j] = ar[i]; sa += as[j] * as[j]; }
    }
    sa = blk_sum(sa, sbuf);
    float axt = sqrtf(sa + 1.f);
    float zt = xr[0] + w * axt;
    float sz = 0.f;
    #pragma unroll
    for (int j = 0; j < 4; j++) {
        int i = tid + j * 256;
        if (i < 1023) { xs[j] = xs[j] + w * as[j]; sz += xs[j] * xs[j]; }
    }
    sz = blk_sum(sz, sbuf);
    float inv = rsqrtf(fmaxf(zt * zt - sz, 1e-8f));
    if (tid == 0) out[(size_t)t * 1024] = zt * inv;
    #pragma unroll
    for (int j = 0; j < 4; j++) {
        int i = tid + j * 256;
        if (i < 1023) out[(size_t)t * 1024 + 1 + i] = xs[j] * inv;
    }
}

// ===================== host =====================
extern "C" void kernel_launch(void* const* d_in, const int* in_sizes, int n_in,
                              void* d_out, int out_size)
{
    const float* x   = (const float*)d_in[0];
    const float* g1  = (const float*)d_in[1];
    const float* b1  = (const float*)d_in[2];
    const float* Wq  = (const float*)d_in[3];
    const float* bq  = (const float*)d_in[4];
    const float* Wk  = (const float*)d_in[5];
    const float* bk  = (const float*)d_in[6];
    const float* Wv  = (const float*)d_in[7];
    const float* bv  = (const float*)d_in[8];
    const float* Wo  = (const float*)d_in[9];
    const float* bo  = (const float*)d_in[10];
    const float* g2  = (const float*)d_in[11];
    const float* b2  = (const float*)d_in[12];
    const float* Wfc = (const float*)d_in[13];
    const float* bfc = (const float*)d_in[14];
    const float* Wpj = (const float*)d_in[15];
    const float* bpj = (const float*)d_in[16];
    const float* w1  = (const float*)d_in[17];
    const float* w2  = (const float*)d_in[18];
    float* out = (float*)d_out;

    cudaFuncSetAttribute(mma_gemm, cudaFuncAttributeMaxDynamicSharedMemorySize, SMEM_GEMM);

    #define SYM(p, s) do { void* _t; cudaGetSymbolAddress(&_t, s); p = decltype(p)(_t); } while (0)
    bf16 *lxh, *lxl, *WqTh, *WqTl, *WkTh, *WkTl, *WvTh, *WvTl, *WoTh, *WoTl;
    bf16 *WfcTh, *WfcTl, *WpjTh, *WpjTl;
    bf16 *qhh, *qhl, *khh, *khl, *vTh, *vTl, *ph, *pl, *cath, *catl, *h1h, *h1l, *fch, *fcl;
    float *qs, *ks, *vs, *sc, *mid, *axs, *x1, *fcpre, *pjs;
    SYM(lxh, g_lxh); SYM(lxl, g_lxl);
    SYM(WqTh, g_WqTh); SYM(WqTl, g_WqTl);
    SYM(WkTh, g_WkTh); SYM(WkTl, g_WkTl);
    SYM(WvTh, g_WvTh); SYM(WvTl, g_WvTl);
    SYM(WoTh, g_WoTh); SYM(WoTl, g_WoTl);
    SYM(WfcTh, g_WfcTh); SYM(WfcTl, g_WfcTl);
    SYM(WpjTh, g_WpjTh); SYM(WpjTl, g_WpjTl);
    SYM(qs, g_qs); SYM(ks, g_ks); SYM(vs, g_vs);
    SYM(qhh, g_qhh); SYM(qhl, g_qhl); SYM(khh, g_khh); SYM(khl, g_khl);
    SYM(vTh, g_vTh); SYM(vTl, g_vTl);
    SYM(sc, g_sc); SYM(ph, g_ph); SYM(pl, g_pl);
    SYM(mid, g_mid); SYM(cath, g_cath); SYM(catl, g_catl);
    SYM(axs, g_axs); SYM(x1, g_x1); SYM(h1h, g_h1h); SYM(h1l, g_h1l);
    SYM(fcpre, g_fcpre); SYM(fch, g_fch); SYM(fcl, g_fcl); SYM(pjs, g_pjs);

    dim3 tb(32, 8);
    // weight transposes (K, N, Kpad)
    k_tsplit<<<dim3(32, 32), tb>>>(Wq, WqTh, WqTl, 1024, 1024, 1024);
    k_tsplit<<<dim3(32, 32), tb>>>(Wk, WkTh, WkTl, 1024, 1024, 1024);
    k_tsplit<<<dim3(32, 32), tb>>>(Wv, WvTh, WvTl, 1024, 1024, 1024);
    k_tsplit<<<dim3(32, 33), tb>>>(Wo, WoTh, WoTl, 1040, 1023, 1088);
    k_tsplit<<<dim3(128, 32), tb>>>(Wfc, WfcTh, WfcTl, 1024, 4095, 1024);
    k_tsplit<<<dim3(32, 128), tb>>>(Wpj, WpjTh, WpjTl, 4096, 1023, 4096);

    // LN1
    k_ln<<<TT, 256>>>(x, g1, b1, lxh, lxl);

    // QKV
    {
        dim3 grid(8, 32, 1);
        mma_gemm<<<grid, 256, SMEM_GEMM>>>(lxh, lxl, WqTh, WqTl, bq, qs,
            1024, 1024, 1024, 0, 1024, 1024, 0, 0, 0, 1.f, 0.f);
        mma_gemm<<<grid, 256, SMEM_GEMM>>>(lxh, lxl, WkTh, WkTl, bk, ks,
            1024, 1024, 1024, 0, 1024, 1024, 0, 0, 0, 1.f, 0.f);
        mma_gemm<<<grid, 256, SMEM_GEMM>>>(lxh, lxl, WvTh, WvTl, bv, vs,
            1024, 1024, 1024, 0, 1024, 1024, 0, 0, 0, 1.f, 0.f);
    }

    // lifts
    k_lift<<<TT, 512>>>(qs, qhh, qhl, -1.f);
    k_lift<<<TT, 512>>>(ks, khh, khl, 1.f);
    k_liftT<<<BHN * 32, tb>>>(vs, vTh, vTl);

    // scores = 0.25 + 0.25*<q',k'>  (K=96; cols 65..95 are zero pads)
    mma_gemm<<<dim3(8, 8, BHN), 256, SMEM_GEMM>>>(qhh, qhl, khh, khl, nullptr, sc,
        QKLD, QKLD, 1024, 0, 1024, QKLD,
        (long long)1024 * QKLD, (long long)1024 * QKLD, (long long)1024 * 1024,
        0.25f, 0.25f);

    // softmax -> probs hi/lo
    k_softmax<<<BHN * 1024, 256>>>(sc, ph, pl);

    // mid = probs @ v_lift
    mma_gemm<<<dim3(1, 8, BHN), 256, SMEM_GEMM>>>(ph, pl, vTh, vTl, nullptr, mid,
        1024, 1024, 65, 0, 65, 1024,
        (long long)1024 * 1024, (long long)128 * 1024, (long long)1024 * 65,
        1.f, 0.f);

    // normalize + concat
    k_normcat<<<TT, 512>>>(mid, cath, catl);

    // Wo
    mma_gemm<<<dim3(8, 32, 1), 256, SMEM_GEMM>>>(cath, catl, WoTh, WoTl, bo, axs,
        1088, 1088, 1023, 0, 1023, 1088, 0, 0, 0, 1.f, 0.f);

    // residual 1
    k_lresnet<<<TT, 256>>>(x, axs, w1, x1);

    // LN2
    k_ln<<<TT, 256>>>(x1, g2, b2, h1h, h1l);

    // Wfc
    mma_gemm<<<dim3(32, 32, 1), 256, SMEM_GEMM>>>(h1h, h1l, WfcTh, WfcTl, bfc, fcpre,
        1024, 1024, 4095, 0, 4095, 1024, 0, 0, 0, 1.f, 0.f);

    // gelu + lift
    k_gelu<<<TT, 256>>>(fcpre, fch, fcl);

    // Wpj
    mma_gemm<<<dim3(8, 32, 1), 256, SMEM_GEMM>>>(fch, fcl, WpjTh, WpjTl, bpj, pjs,
        4096, 4096, 1023, 0, 1023, 4096, 0, 0, 0, 1.f, 0.f);

    // residual 2
    k_lresnet<<<TT, 256>>>(x1, pjs, w2, out);
}

// round 5
// speedup vs baseline: 1.6529x; 1.6529x over previous
#include <cuda_runtime.h>
#include <cuda_bf16.h>
#include <math.h>
#include <stdint.h>

// Problem constants
#define BB 4
#define NNTOK 1024
#define DDIM 1024
#define HH 16
#define TT (BB*NNTOK)     // 4096 tokens
#define BHN (BB*HH)       // 64
#define QKLD 96           // padded lifted q/k leading dim

typedef __nv_bfloat16 bf16;

// ===================== scratch (device globals) =====================
__device__ __align__(128) bf16  g_lxh [TT*1024];
__device__ __align__(128) bf16  g_lxl [TT*1024];
__device__ __align__(128) bf16  g_WqTh[1024*1024];
__device__ __align__(128) bf16  g_WqTl[1024*1024];
__device__ __align__(128) bf16  g_WkTh[1024*1024];
__device__ __align__(128) bf16  g_WkTl[1024*1024];
__device__ __align__(128) bf16  g_WvTh[1024*1024];
__device__ __align__(128) bf16  g_WvTl[1024*1024];
__device__ __align__(128) bf16  g_WoTh[1024*1088];
__device__ __align__(128) bf16  g_WoTl[1024*1088];
__device__ __align__(128) bf16  g_WfcTh[4096*1024];
__device__ __align__(128) bf16  g_WfcTl[4096*1024];
__device__ __align__(128) bf16  g_WpjTh[1024*4096];
__device__ __align__(128) bf16  g_WpjTl[1024*4096];
__device__ __align__(128) float g_qs  [TT*1024];
__device__ __align__(128) float g_ks  [TT*1024];
__device__ __align__(128) float g_vs  [TT*1024];
__device__ __align__(128) bf16  g_qhh [BHN*1024*QKLD];
__device__ __align__(128) bf16  g_qhl [BHN*1024*QKLD];
__device__ __align__(128) bf16  g_khh [BHN*1024*QKLD];
__device__ __align__(128) bf16  g_khl [BHN*1024*QKLD];
__device__ __align__(128) bf16  g_vTh [BHN*128*1024];
__device__ __align__(128) bf16  g_vTl [BHN*128*1024];
__device__ __align__(128) float g_sc  [(size_t)BHN*1024*1024];  // 256MB
__device__ __align__(128) bf16  g_ph  [(size_t)BHN*1024*1024];
__device__ __align__(128) bf16  g_pl  [(size_t)BHN*1024*1024];
__device__ __align__(128) float g_mid [BHN*1024*65];
__device__ __align__(128) bf16  g_cath[TT*1088];
__device__ __align__(128) bf16  g_catl[TT*1088];
__device__ __align__(128) float g_axs [TT*1023];
__device__ __align__(128) float g_x1  [TT*1024];
__device__ __align__(128) bf16  g_h1h [TT*1024];
__device__ __align__(128) bf16  g_h1l [TT*1024];
__device__ __align__(128) float g_fcpre[(size_t)TT*4095];
__device__ __align__(128) bf16  g_fch [(size_t)TT*4096];
__device__ __align__(128) bf16  g_fcl [(size_t)TT*4096];
__device__ __align__(128) float g_pjs [TT*1023];

// ===================== PTX helpers =====================
__device__ __forceinline__ uint32_t smem_u32(const void* p) {
    uint32_t a;
    asm("{ .reg .u64 t; cvta.to.shared.u64 t, %1; cvt.u32.u64 %0, t; }" : "=r"(a) : "l"(p));
    return a;
}

#define CP_ASYNC16(dst, src) \
    asm volatile("cp.async.cg.shared.global [%0], [%1], 16;" :: "r"(dst), "l"(src))
#define CP_COMMIT() asm volatile("cp.async.commit_group;")
#define CP_WAIT1()  asm volatile("cp.async.wait_group 1;")
#define CP_WAIT0()  asm volatile("cp.async.wait_group 0;")

__device__ __forceinline__ void mma16816(float* c, const uint32_t* a, const uint32_t* b) {
    asm volatile(
        "mma.sync.aligned.m16n8k16.row.col.f32.bf16.bf16.f32 "
        "{%0,%1,%2,%3}, {%4,%5,%6,%7}, {%8,%9}, {%0,%1,%2,%3};"
        : "+f"(c[0]), "+f"(c[1]), "+f"(c[2]), "+f"(c[3])
        : "r"(a[0]), "r"(a[1]), "r"(a[2]), "r"(a[3]), "r"(b[0]), "r"(b[1]));
}

__device__ __forceinline__ void bsplit(float v, bf16& h, bf16& l) {
    h = __float2bfloat16(v);
    l = __float2bfloat16(v - __bfloat162float(h));
}

// ===================== block reductions =====================
__device__ __forceinline__ float blk_sum(float v, float* sbuf) {
    int tid = threadIdx.x;
    #pragma unroll
    for (int o = 16; o > 0; o >>= 1) v += __shfl_down_sync(0xffffffffu, v, o);
    if ((tid & 31) == 0) sbuf[tid >> 5] = v;
    __syncthreads();
    if (tid < 32) {
        int nw = (blockDim.x + 31) >> 5;
        float x = (tid < nw) ? sbuf[tid] : 0.f;
        #pragma unroll
        for (int o = 16; o > 0; o >>= 1) x += __shfl_down_sync(0xffffffffu, x, o);
        if (tid == 0) sbuf[0] = x;
    }
    __syncthreads();
    float r = sbuf[0];
    __syncthreads();
    return r;
}
__device__ __forceinline__ float blk_max(float v, float* sbuf) {
    int tid = threadIdx.x;
    #pragma unroll
    for (int o = 16; o > 0; o >>= 1) v = fmaxf(v, __shfl_down_sync(0xffffffffu, v, o));
    if ((tid & 31) == 0) sbuf[tid >> 5] = v;
    __syncthreads();
    if (tid < 32) {
        int nw = (blockDim.x + 31) >> 5;
        float x = (tid < nw) ? sbuf[tid] : -3.4e38f;
        #pragma unroll
        for (int o = 16; o > 0; o >>= 1) x = fmaxf(x, __shfl_down_sync(0xffffffffu, x, o));
        if (tid == 0) sbuf[0] = x;
    }
    __syncthreads();
    float r = sbuf[0];
    __syncthreads();
    return r;
}

// ===================== mma.sync GEMM (scalar LDS fragment loads) =====================
// D[m0+r][c0+n] = alpha*(Ah·Bh^T + Ah·Bl^T + Al·Bh^T)[r][n] + cadd + bias[n]
// A (hi/lo): M x K bf16 row-major (lda); B (hi/lo): Npad x K bf16 row-major (ldb)
// C fp32 ldc; writes only n < Nreal. M mult of 128, K mult of KC.
// KC in {32, 64}; smem row stride = 2*KC+16 bytes (stride mod 128 = 80/16 -> conflict-free).
template<int KC>
__global__ __launch_bounds__(256)
void mma_gemm(const bf16* __restrict__ Ah, const bf16* __restrict__ Al,
              const bf16* __restrict__ Bh, const bf16* __restrict__ Bl,
              const float* __restrict__ bias, float* __restrict__ C,
              int lda, int ldb, int ldc, int c0, int Nreal, int K,
              long long sA, long long sB, long long sC,
              float alpha, float cadd)
{
    constexpr int ROWB = 2 * KC + 16;        // bytes per smem row
    constexpr int STG_MAT = 128 * ROWB;
    constexpr int STG_SZ = 4 * STG_MAT;
    constexpr int CPR = KC / 8;              // 16B chunks per row
    constexpr int LPT = KC / 4;              // cp.async per thread per stage

    extern __shared__ char smem[];
    int tid = threadIdx.x, w = tid >> 5, lane = tid & 31;
    long long bz = blockIdx.z;
    Ah += bz * sA; Al += bz * sA;
    Bh += bz * sB; Bl += bz * sB;
    C  += bz * sC;
    int m0 = blockIdx.y * 128, n0 = blockIdx.x * 128;
    const int NC = K / KC;

    auto load_stage = [&](int kofs, int s) {
        char* stg = smem + s * STG_SZ;
        #pragma unroll
        for (int i = 0; i < LPT; i++) {
            int idx = tid + i * 256;              // 0 .. 64*KC-1
            int mat = idx / (16 * KC);            // 0:Ah 1:Al 2:Bh 3:Bl
            int cc  = idx % (16 * KC);
            int row = cc / CPR, kc = cc % CPR;
            uint32_t dst = smem_u32(stg + mat * STG_MAT + row * ROWB + kc * 16);
            const bf16* p = (mat == 0) ? Ah : (mat == 1) ? Al : (mat == 2) ? Bh : Bl;
            int b0 = (mat < 2) ? m0 : n0;
            int ld = (mat < 2) ? lda : ldb;
            CP_ASYNC16(dst, p + (size_t)(b0 + row) * ld + kofs + kc * 8);
        }
        CP_COMMIT();
    };

    load_stage(0, 0);
    if (NC > 1) load_stage(KC, 1);

    int g = lane >> 2, t = lane & 3;
    int wm = (w & 3) * 32, wn = (w >> 2) * 64;

    float acc[2][8][4];
    #pragma unroll
    for (int mt = 0; mt < 2; mt++)
        #pragma unroll
        for (int nt = 0; nt < 8; nt++)
            #pragma unroll
            for (int r = 0; r < 4; r++) acc[mt][nt][r] = 0.f;

    for (int kc = 0; kc < NC; kc++) {
        if (kc + 1 < NC) { CP_WAIT1(); } else { CP_WAIT0(); }
        __syncthreads();
        const char* stg = smem + (kc & 1) * STG_SZ;
        const char* pAh = stg;
        const char* pAl = stg + STG_MAT;
        const char* pBh = stg + 2 * STG_MAT;
        const char* pBl = stg + 3 * STG_MAT;

        #pragma unroll
        for (int ko = 0; ko < KC; ko += 16) {
            uint32_t aH[2][4], aL[2][4], b[8][2];
            #pragma unroll
            for (int mt = 0; mt < 2; mt++) {
                int r0 = (wm + mt * 16 + g) * ROWB + (ko + t * 2) * 2;
                aH[mt][0] = *(const uint32_t*)(pAh + r0);
                aH[mt][1] = *(const uint32_t*)(pAh + r0 + 8 * ROWB);
                aH[mt][2] = *(const uint32_t*)(pAh + r0 + 16);
                aH[mt][3] = *(const uint32_t*)(pAh + r0 + 8 * ROWB + 16);
                aL[mt][0] = *(const uint32_t*)(pAl + r0);
                aL[mt][1] = *(const uint32_t*)(pAl + r0 + 8 * ROWB);
                aL[mt][2] = *(const uint32_t*)(pAl + r0 + 16);
                aL[mt][3] = *(const uint32_t*)(pAl + r0 + 8 * ROWB + 16);
            }
            // Bh pass: acc += Ah*Bh + Al*Bh
            #pragma unroll
            for (int nt = 0; nt < 8; nt++) {
                int r0 = (wn + nt * 8 + g) * ROWB + (ko + t * 2) * 2;
                b[nt][0] = *(const uint32_t*)(pBh + r0);
                b[nt][1] = *(const uint32_t*)(pBh + r0 + 16);
            }
            #pragma unroll
            for (int mt = 0; mt < 2; mt++)
                #pragma unroll
                for (int nt = 0; nt < 8; nt++) {
                    mma16816(acc[mt][nt], aH[mt], b[nt]);
                    mma16816(acc[mt][nt], aL[mt], b[nt]);
                }
            // Bl pass: acc += Ah*Bl
            #pragma unroll
            for (int nt = 0; nt < 8; nt++) {
                int r0 = (wn + nt * 8 + g) * ROWB + (ko + t * 2) * 2;
                b[nt][0] = *(const uint32_t*)(pBl + r0);
                b[nt][1] = *(const uint32_t*)(pBl + r0 + 16);
            }
            #pragma unroll
            for (int mt = 0; mt < 2; mt++)
                #pragma unroll
                for (int nt = 0; nt < 8; nt++)
                    mma16816(acc[mt][nt], aH[mt], b[nt]);
        }
        __syncthreads();
        if (kc + 2 < NC) load_stage((kc + 2) * KC, kc & 1);
    }

    // epilogue
    #pragma unroll
    for (int mt = 0; mt < 2; mt++) {
        int r0 = m0 + wm + mt * 16 + g;
        float* c0p = C + (size_t)r0 * ldc + c0;
        float* c1p = C + (size_t)(r0 + 8) * ldc + c0;
        #pragma unroll
        for (int nt = 0; nt < 8; nt++) {
            int n = n0 + wn + nt * 8 + t * 2;
            if (n < Nreal) {
                float bv = bias ? bias[n] : 0.f;
                c0p[n] = alpha * acc[mt][nt][0] + cadd + bv;
                c1p[n] = alpha * acc[mt][nt][2] + cadd + bv;
            }
            if (n + 1 < Nreal) {
                float bv = bias ? bias[n + 1] : 0.f;
                c0p[n + 1] = alpha * acc[mt][nt][1] + cadd + bv;
                c1p[n + 1] = alpha * acc[mt][nt][3] + cadd + bv;
            }
        }
    }
}

#define SMEM_G32 (2 * 4 * 128 * 80)    // 81920
#define SMEM_G64 (2 * 4 * 128 * 144)   // 147456

// ===================== transpose+split weights =====================
__global__ void k_tsplit(const float* __restrict__ W, bf16* __restrict__ Th,
                         bf16* __restrict__ Tl, int K, int N, int Kpad)
{
    __shared__ float t[32][33];
    int nb = blockIdx.x * 32, kb = blockIdx.y * 32;
    int tx = threadIdx.x, ty = threadIdx.y;
    #pragma unroll
    for (int i = 0; i < 32; i += 8) {
        int k = kb + ty + i, n = nb + tx;
        t[ty + i][tx] = (k < K && n < N) ? W[(size_t)k * N + n] : 0.f;
    }
    __syncthreads();
    #pragma unroll
    for (int i = 0; i < 32; i += 8) {
        int n = nb + ty + i, k = kb + tx;
        if (n < N && k < K) {
            float v = t[tx][ty + i];
            bf16 h, l; bsplit(v, h, l);
            Th[(size_t)n * Kpad + k] = h;
            Tl[(size_t)n * Kpad + k] = l;
        }
    }
}

// ===================== Lorentz layernorm -> hi/lo =====================
__global__ __launch_bounds__(256)
void k_ln(const float* __restrict__ x, const float* __restrict__ g,
          const float* __restrict__ b, bf16* __restrict__ oh, bf16* __restrict__ ol)
{
    __shared__ float sbuf[32];
    int t = blockIdx.x, tid = threadIdx.x;
    const float* xs = x + (size_t)t * 1024 + 1;
    float sv[4]; float s1 = 0.f, s2 = 0.f;
    #pragma unroll
    for (int j = 0; j < 4; j++) {
        int i = tid + j * 256;
        sv[j] = 0.f;
        if (i < 1023) { sv[j] = xs[i]; s1 += sv[j]; s2 += sv[j] * sv[j]; }
    }
    s1 = blk_sum(s1, sbuf);
    s2 = blk_sum(s2, sbuf);
    float mu = s1 * (1.f / 1023.f);
    float var = s2 * (1.f / 1023.f) - mu * mu;
    float rstd = rsqrtf(var + 1e-5f);
    float q = 0.f;
    float yv[4];
    #pragma unroll
    for (int j = 0; j < 4; j++) {
        int i = tid + j * 256;
        yv[j] = 0.f;
        if (i < 1023) {
            yv[j] = (sv[j] - mu) * rstd * g[i] + b[i];
            q += yv[j] * yv[j];
        }
    }
    q = blk_sum(q, sbuf);
    size_t base = (size_t)t * 1024;
    #pragma unroll
    for (int j = 0; j < 4; j++) {
        int i = tid + j * 256;
        if (i < 1023) {
            bf16 h, l; bsplit(yv[j], h, l);
            oh[base + 1 + i] = h; ol[base + 1 + i] = l;
        }
    }
    if (tid == 0) {
        bf16 h, l; bsplit(sqrtf(q + 1.f), h, l);
        oh[base] = h; ol[base] = l;
    }
}

// ===================== lift heads (q/k): (T,1024) -> (BH,N,QKLD) hi/lo =====================
__global__ __launch_bounds__(512)
void k_lift(const float* __restrict__ S, bf16* __restrict__ Oh, bf16* __restrict__ Ol, float sign)
{
    int t = blockIdx.x;
    int b = t >> 10, n = t & 1023;
    int w = threadIdx.x >> 5, lane = threadIdx.x & 31;
    const float* src = S + (size_t)t * 1024 + w * 64;
    float v0 = src[lane], v1 = src[lane + 32];
    float ss = v0 * v0 + v1 * v1;
    #pragma unroll
    for (int o = 16; o > 0; o >>= 1) ss += __shfl_down_sync(0xffffffffu, ss, o);
    ss = __shfl_sync(0xffffffffu, ss, 0);
    size_t base = ((size_t)(b * HH + w) * 1024 + n) * QKLD;
    bf16 h, l;
    bsplit(v0, h, l); Oh[base + 1 + lane] = h; Ol[base + 1 + lane] = l;
    bsplit(v1, h, l); Oh[base + 33 + lane] = h; Ol[base + 33 + lane] = l;
    if (lane == 0) {
        bsplit(sign * sqrtf(ss + 1.f), h, l);
        Oh[base] = h; Ol[base] = l;
    }
    for (int i = 65 + lane; i < QKLD; i += 32) {
        Oh[base + i] = __float2bfloat16(0.f);
        Ol[base + i] = __float2bfloat16(0.f);
    }
}

// ===================== lift+transpose v =====================
__global__ void k_liftT(const float* __restrict__ vs, bf16* __restrict__ Th, bf16* __restrict__ Tl)
{
    int blk = blockIdx.x;
    int bh = blk >> 5;
    int tg = blk & 31;
    int b = bh >> 4, h = bh & 15;
    __shared__ float sv[32][65];
    __shared__ float stime[32];
    int tx = threadIdx.x, ty = threadIdx.y;
    #pragma unroll
    for (int i = 0; i < 32; i += 8) {
        int tok = i + ty;
        const float* src = vs + (size_t)(b * 1024 + tg * 32 + tok) * 1024 + h * 64;
        sv[tok][1 + tx] = src[tx];
        sv[tok][33 + tx] = src[tx + 32];
    }
    __syncthreads();
    if (ty == 0) {
        float s = 0.f;
        #pragma unroll
        for (int d = 1; d <= 64; d++) { float x = sv[tx][d]; s += x * x; }
        stime[tx] = sqrtf(s + 1.f);
    }
    __syncthreads();
    size_t base = (size_t)bh * (128 * 1024) + (size_t)(tg * 32);
    for (int d = ty; d < 128; d += 8) {
        float v = (d == 0) ? stime[tx] : (d < 65 ? sv[tx][d] : 0.f);
        bf16 hh, ll; bsplit(v, hh, ll);
        Th[base + (size_t)d * 1024 + tx] = hh;
        Tl[base + (size_t)d * 1024 + tx] = ll;
    }
}

// ===================== softmax -> probs hi/lo =====================
__global__ __launch_bounds__(256)
void k_softmax(const float* __restrict__ sc, bf16* __restrict__ ph, bf16* __restrict__ pl)
{
    __shared__ float sbuf[32];
    size_t off = (size_t)blockIdx.x * 1024;
    const float* row = sc + off;
    int tid = threadIdx.x;
    float v[4];
    float m = -3.4e38f;
    #pragma unroll
    for (int j = 0; j < 4; j++) { v[j] = row[tid + j * 256]; m = fmaxf(m, v[j]); }
    m = blk_max(m, sbuf);
    float s = 0.f;
    #pragma unroll
    for (int j = 0; j < 4; j++) { v[j] = __expf(v[j] - m); s += v[j]; }
    s = blk_sum(s, sbuf);
    float inv = 1.f / s;
    #pragma unroll
    for (int j = 0; j < 4; j++) {
        float p = v[j] * inv;
        bf16 h, l; bsplit(p, h, l);
        ph[off + tid + j * 256] = h;
        pl[off + tid + j * 256] = l;
    }
}

// ===================== normalize mid + concat =====================
__global__ __launch_bounds__(512)
void k_normcat(const float* __restrict__ mid, bf16* __restrict__ ch, bf16* __restrict__ cl)
{
    int t = blockIdx.x;
    int b = t >> 10, n = t & 1023;
    int w = threadIdx.x >> 5, lane = threadIdx.x & 31;
    const float* src = mid + ((size_t)(b * HH + w) * 1024 + n) * 65;
    float tmv = src[0];
    float a0 = src[1 + lane], a1 = src[33 + lane];
    float ss = a0 * a0 + a1 * a1;
    #pragma unroll
    for (int o = 16; o > 0; o >>= 1) ss += __shfl_down_sync(0xffffffffu, ss, o);
    ss = __shfl_sync(0xffffffffu, ss, 0);
    float inv = rsqrtf(fmaxf(tmv * tmv - ss, 1e-8f));
    size_t base = (size_t)t * 1088 + w * 65;
    bf16 h, l;
    bsplit(a0 * inv, h, l); ch[base + 1 + lane] = h; cl[base + 1 + lane] = l;
    bsplit(a1 * inv, h, l); ch[base + 33 + lane] = h; cl[base + 33 + lane] = l;
    if (lane == 0) { bsplit(tmv * inv, h, l); ch[base] = h; cl[base] = l; }
}

// ===================== gelu + lift =====================
__global__ __launch_bounds__(256)
void k_gelu(const float* __restrict__ fcpre, bf16* __restrict__ fh, bf16* __restrict__ fl)
{
    __shared__ float sbuf[32];
    int t = blockIdx.x, tid = threadIdx.x;
    const float* rin = fcpre + (size_t)t * 4095;
    float gv[16];
    float q = 0.f;
    #pragma unroll
    for (int j = 0; j < 16; j++) {
        int i = tid + j * 256;
        gv[j] = 0.f;
        if (i < 4095) {
            float x = rin[i];
            gv[j] = 0.5f * x * (1.f + erff(x * 0.70710678118654752f));
            q += gv[j] * gv[j];
        }
    }
    q = blk_sum(q, sbuf);
    size_t base = (size_t)t * 4096;
    #pragma unroll
    for (int j = 0; j < 16; j++) {
        int i = tid + j * 256;
        if (i < 4095) {
            bf16 h, l; bsplit(gv[j], h, l);
            fh[base + 1 + i] = h; fl[base + 1 + i] = l;
        }
    }
    if (tid == 0) {
        bf16 h, l; bsplit(sqrtf(q + 1.f), h, l);
        fh[base] = h; fl[base] = l;
    }
}

// ===================== Lorentz residual =====================
__global__ __launch_bounds__(256)
void k_lresnet(const float* __restrict__ xin, const float* __restrict__ spart,
               const float* __restrict__ wp, float* __restrict__ out)
{
    __shared__ float sbuf[32];
    int t = blockIdx.x, tid = threadIdx.x;
    float w = wp[0];
    const float* xr = xin + (size_t)t * 1024;
    const float* ar = spart + (size_t)t * 1023;
    float xs[4], as[4];
    float sa = 0.f;
    #pragma unroll
    for (int j = 0; j < 4; j++) {
        int i = tid + j * 256;
        xs[j] = 0.f; as[j] = 0.f;
        if (i < 1023) { xs[j] = xr[1 + i]; as[j] = ar[i]; sa += as[j] * as[j]; }
    }
    sa = blk_sum(sa, sbuf);
    float axt = sqrtf(sa + 1.f);
    float zt = xr[0] + w * axt;
    float sz = 0.f;
    #pragma unroll
    for (int j = 0; j < 4; j++) {
        int i = tid + j * 256;
        if (i < 1023) { xs[j] = xs[j] + w * as[j]; sz += xs[j] * xs[j]; }
    }
    sz = blk_sum(sz, sbuf);
    float inv = rsqrtf(fmaxf(zt * zt - sz, 1e-8f));
    if (tid == 0) out[(size_t)t * 1024] = zt * inv;
    #pragma unroll
    for (int j = 0; j < 4; j++) {
        int i = tid + j * 256;
        if (i < 1023) out[(size_t)t * 1024 + 1 + i] = xs[j] * inv;
    }
}

// ===================== host =====================
extern "C" void kernel_launch(void* const* d_in, const int* in_sizes, int n_in,
                              void* d_out, int out_size)
{
    const float* x   = (const float*)d_in[0];
    const float* g1  = (const float*)d_in[1];
    const float* b1  = (const float*)d_in[2];
    const float* Wq  = (const float*)d_in[3];
    const float* bq  = (const float*)d_in[4];
    const float* Wk  = (const float*)d_in[5];
    const float* bk  = (const float*)d_in[6];
    const float* Wv  = (const float*)d_in[7];
    const float* bv  = (const float*)d_in[8];
    const float* Wo  = (const float*)d_in[9];
    const float* bo  = (const float*)d_in[10];
    const float* g2  = (const float*)d_in[11];
    const float* b2  = (const float*)d_in[12];
    const float* Wfc = (const float*)d_in[13];
    const float* bfc = (const float*)d_in[14];
    const float* Wpj = (const float*)d_in[15];
    const float* bpj = (const float*)d_in[16];
    const float* w1  = (const float*)d_in[17];
    const float* w2  = (const float*)d_in[18];
    float* out = (float*)d_out;

    cudaFuncSetAttribute(mma_gemm<32>, cudaFuncAttributeMaxDynamicSharedMemorySize, SMEM_G32);
    cudaFuncSetAttribute(mma_gemm<64>, cudaFuncAttributeMaxDynamicSharedMemorySize, SMEM_G64);

    #define SYM(p, s) do { void* _t; cudaGetSymbolAddress(&_t, s); p = decltype(p)(_t); } while (0)
    bf16 *lxh, *lxl, *WqTh, *WqTl, *WkTh, *WkTl, *WvTh, *WvTl, *WoTh, *WoTl;
    bf16 *WfcTh, *WfcTl, *WpjTh, *WpjTl;
    bf16 *qhh, *qhl, *khh, *khl, *vTh, *vTl, *ph, *pl, *cath, *catl, *h1h, *h1l, *fch, *fcl;
    float *qs, *ks, *vs, *sc, *mid, *axs, *x1, *fcpre, *pjs;
    SYM(lxh, g_lxh); SYM(lxl, g_lxl);
    SYM(WqTh, g_WqTh); SYM(WqTl, g_WqTl);
    SYM(WkTh, g_WkTh); SYM(WkTl, g_WkTl);
    SYM(WvTh, g_WvTh); SYM(WvTl, g_WvTl);
    SYM(WoTh, g_WoTh); SYM(WoTl, g_WoTl);
    SYM(WfcTh, g_WfcTh); SYM(WfcTl, g_WfcTl);
    SYM(WpjTh, g_WpjTh); SYM(WpjTl, g_WpjTl);
    SYM(qs, g_qs); SYM(ks, g_ks); SYM(vs, g_vs);
    SYM(qhh, g_qhh); SYM(qhl, g_qhl); SYM(khh, g_khh); SYM(khl, g_khl);
    SYM(vTh, g_vTh); SYM(vTl, g_vTl);
    SYM(sc, g_sc); SYM(ph, g_ph); SYM(pl, g_pl);
    SYM(mid, g_mid); SYM(cath, g_cath); SYM(catl, g_catl);
    SYM(axs, g_axs); SYM(x1, g_x1); SYM(h1h, g_h1h); SYM(h1l, g_h1l);
    SYM(fcpre, g_fcpre); SYM(fch, g_fch); SYM(fcl, g_fcl); SYM(pjs, g_pjs);

    dim3 tb(32, 8);
    // weight transposes (K, N, Kpad)
    k_tsplit<<<dim3(32, 32), tb>>>(Wq, WqTh, WqTl, 1024, 1024, 1024);
    k_tsplit<<<dim3(32, 32), tb>>>(Wk, WkTh, WkTl, 1024, 1024, 1024);
    k_tsplit<<<dim3(32, 32), tb>>>(Wv, WvTh, WvTl, 1024, 1024, 1024);
    k_tsplit<<<dim3(32, 33), tb>>>(Wo, WoTh, WoTl, 1040, 1023, 1088);
    k_tsplit<<<dim3(128, 32), tb>>>(Wfc, WfcTh, WfcTl, 1024, 4095, 1024);
    k_tsplit<<<dim3(32, 128), tb>>>(Wpj, WpjTh, WpjTl, 4096, 1023, 4096);

    // LN1
    k_ln<<<TT, 256>>>(x, g1, b1, lxh, lxl);

    // QKV
    {
        dim3 grid(8, 32, 1);
        mma_gemm<64><<<grid, 256, SMEM_G64>>>(lxh, lxl, WqTh, WqTl, bq, qs,
            1024, 1024, 1024, 0, 1024, 1024, 0, 0, 0, 1.f, 0.f);
        mma_gemm<64><<<grid, 256, SMEM_G64>>>(lxh, lxl, WkTh, WkTl, bk, ks,
            1024, 1024, 1024, 0, 1024, 1024, 0, 0, 0, 1.f, 0.f);
        mma_gemm<64><<<grid, 256, SMEM_G64>>>(lxh, lxl, WvTh, WvTl, bv, vs,
            1024, 1024, 1024, 0, 1024, 1024, 0, 0, 0, 1.f, 0.f);
    }

    // lifts
    k_lift<<<TT, 512>>>(qs, qhh, qhl, -1.f);
    k_lift<<<TT, 512>>>(ks, khh, khl, 1.f);
    k_liftT<<<BHN * 32, tb>>>(vs, vTh, vTl);

    // scores = 0.25 + 0.25*<q',k'>  (K=96; cols 65..95 zero pads)
    mma_gemm<32><<<dim3(8, 8, BHN), 256, SMEM_G32>>>(qhh, qhl, khh, khl, nullptr, sc,
        QKLD, QKLD, 1024, 0, 1024, QKLD,
        (long long)1024 * QKLD, (long long)1024 * QKLD, (long long)1024 * 1024,
        0.25f, 0.25f);

    // softmax -> probs hi/lo
    k_softmax<<<BHN * 1024, 256>>>(sc, ph, pl);

    // mid = probs @ v_lift
    mma_gemm<64><<<dim3(1, 8, BHN), 256, SMEM_G64>>>(ph, pl, vTh, vTl, nullptr, mid,
        1024, 1024, 65, 0, 65, 1024,
        (long long)1024 * 1024, (long long)128 * 1024, (long long)1024 * 65,
        1.f, 0.f);

    // normalize + concat
    k_normcat<<<TT, 512>>>(mid, cath, catl);

    // Wo
    mma_gemm<64><<<dim3(8, 32, 1), 256, SMEM_G64>>>(cath, catl, WoTh, WoTl, bo, axs,
        1088, 1088, 1023, 0, 1023, 1088, 0, 0, 0, 1.f, 0.f);

    // residual 1
    k_lresnet<<<TT, 256>>>(x, axs, w1, x1);

    // LN2
    k_ln<<<TT, 256>>>(x1, g2, b2, h1h, h1l);

    // Wfc
    mma_gemm<64><<<dim3(32, 32, 1), 256, SMEM_G64>>>(h1h, h1l, WfcTh, WfcTl, bfc, fcpre,
        1024, 1024, 4095, 0, 4095, 1024, 0, 0, 0, 1.f, 0.f);

    // gelu + lift
    k_gelu<<<TT, 256>>>(fcpre, fch, fcl);

    // Wpj
    mma_gemm<64><<<dim3(8, 32, 1), 256, SMEM_G64>>>(fch, fcl, WpjTh, WpjTl, bpj, pjs,
        4096, 4096, 1023, 0, 1023, 4096, 0, 0, 0, 1.f, 0.f);

    // residual 2
    k_lresnet<<<TT, 256>>>(x1, pjs, w2, out);
}

// round 6
// speedup vs baseline: 1.8671x; 1.1296x over previous
#include <cuda_runtime.h>
#include <cuda_bf16.h>
#include <math.h>
#include <stdint.h>

// Problem constants
#define BB 4
#define NNTOK 1024
#define DDIM 1024
#define HH 16
#define TT (BB*NNTOK)     // 4096 tokens
#define BHN (BB*HH)       // 64
#define QKLD 80           // padded lifted q/k leading dim (65 -> 80)

typedef __nv_bfloat16 bf16;

// ===================== scratch (device globals) =====================
__device__ __align__(128) bf16  g_lxh [TT*1024];
__device__ __align__(128) bf16  g_lxl [TT*1024];
__device__ __align__(128) bf16  g_WqTh[1024*1024];
__device__ __align__(128) bf16  g_WqTl[1024*1024];
__device__ __align__(128) bf16  g_WkTh[1024*1024];
__device__ __align__(128) bf16  g_WkTl[1024*1024];
__device__ __align__(128) bf16  g_WvTh[1024*1024];
__device__ __align__(128) bf16  g_WvTl[1024*1024];
__device__ __align__(128) bf16  g_WoTh[1024*1088];
__device__ __align__(128) bf16  g_WoTl[1024*1088];
__device__ __align__(128) bf16  g_WfcTh[4096*1024];
__device__ __align__(128) bf16  g_WfcTl[4096*1024];
__device__ __align__(128) bf16  g_WpjTh[1024*4096];
__device__ __align__(128) bf16  g_WpjTl[1024*4096];
__device__ __align__(128) float g_qs  [TT*1024];
__device__ __align__(128) float g_ks  [TT*1024];
__device__ __align__(128) float g_vs  [TT*1024];
__device__ __align__(128) bf16  g_qhh [(size_t)BHN*1024*QKLD];
__device__ __align__(128) bf16  g_qhl [(size_t)BHN*1024*QKLD];
__device__ __align__(128) bf16  g_khh [(size_t)BHN*1024*QKLD];
__device__ __align__(128) bf16  g_khl [(size_t)BHN*1024*QKLD];
__device__ __align__(128) bf16  g_vTh [(size_t)BHN*72*1024];
__device__ __align__(128) bf16  g_vTl [(size_t)BHN*72*1024];
__device__ __align__(128) bf16  g_cath[TT*1088];
__device__ __align__(128) bf16  g_catl[TT*1088];
__device__ __align__(128) float g_axs [TT*1023];
__device__ __align__(128) float g_x1  [TT*1024];
__device__ __align__(128) bf16  g_h1h [TT*1024];
__device__ __align__(128) bf16  g_h1l [TT*1024];
__device__ __align__(128) float g_fcpre[(size_t)TT*4095];
__device__ __align__(128) bf16  g_fch [(size_t)TT*4096];
__device__ __align__(128) bf16  g_fcl [(size_t)TT*4096];
__device__ __align__(128) float g_pjs [TT*1023];

// ===================== PTX helpers =====================
__device__ __forceinline__ uint32_t smem_u32(const void* p) {
    uint32_t a;
    asm("{ .reg .u64 t; cvta.to.shared.u64 t, %1; cvt.u32.u64 %0, t; }" : "=r"(a) : "l"(p));
    return a;
}

#define CP_ASYNC16(dst, src) \
    asm volatile("cp.async.cg.shared.global [%0], [%1], 16;" :: "r"(dst), "l"(src))
#define CP_COMMIT() asm volatile("cp.async.commit_group;")
#define CP_WAIT1()  asm volatile("cp.async.wait_group 1;")
#define CP_WAIT0()  asm volatile("cp.async.wait_group 0;")

__device__ __forceinline__ void mma16816(float* c, const uint32_t* a, const uint32_t* b) {
    asm volatile(
        "mma.sync.aligned.m16n8k16.row.col.f32.bf16.bf16.f32 "
        "{%0,%1,%2,%3}, {%4,%5,%6,%7}, {%8,%9}, {%0,%1,%2,%3};"
        : "+f"(c[0]), "+f"(c[1]), "+f"(c[2]), "+f"(c[3])
        : "r"(a[0]), "r"(a[1]), "r"(a[2]), "r"(a[3]), "r"(b[0]), "r"(b[1]));
}

__device__ __forceinline__ void bsplit(float v, bf16& h, bf16& l) {
    h = __float2bfloat16(v);
    l = __float2bfloat16(v - __bfloat162float(h));
}

__device__ __forceinline__ uint32_t pack_hi2(float a, float b) {
    __nv_bfloat162 r = __floats2bfloat162_rn(a, b);
    return *(uint32_t*)&r;
}
__device__ __forceinline__ uint32_t pack_lo2(float a, float b) {
    float ra = a - __bfloat162float(__float2bfloat16(a));
    float rb = b - __bfloat162float(__float2bfloat16(b));
    __nv_bfloat162 r = __floats2bfloat162_rn(ra, rb);
    return *(uint32_t*)&r;
}

// ===================== block reductions =====================
__device__ __forceinline__ float blk_sum(float v, float* sbuf) {
    int tid = threadIdx.x;
    #pragma unroll
    for (int o = 16; o > 0; o >>= 1) v += __shfl_down_sync(0xffffffffu, v, o);
    if ((tid & 31) == 0) sbuf[tid >> 5] = v;
    __syncthreads();
    if (tid < 32) {
        int nw = (blockDim.x + 31) >> 5;
        float x = (tid < nw) ? sbuf[tid] : 0.f;
        #pragma unroll
        for (int o = 16; o > 0; o >>= 1) x += __shfl_down_sync(0xffffffffu, x, o);
        if (tid == 0) sbuf[0] = x;
    }
    __syncthreads();
    float r = sbuf[0];
    __syncthreads();
    return r;
}

// ===================== mma.sync GEMM (weights path; unchanged from R5) =====================
template<int KC>
__global__ __launch_bounds__(256)
void mma_gemm(const bf16* __restrict__ Ah, const bf16* __restrict__ Al,
              const bf16* __restrict__ Bh, const bf16* __restrict__ Bl,
              const float* __restrict__ bias, float* __restrict__ C,
              int lda, int ldb, int ldc, int c0, int Nreal, int K,
              long long sA, long long sB, long long sC,
              float alpha, float cadd)
{
    constexpr int ROWB = 2 * KC + 16;
    constexpr int STG_MAT = 128 * ROWB;
    constexpr int STG_SZ = 4 * STG_MAT;
    constexpr int CPR = KC / 8;
    constexpr int LPT = KC / 4;

    extern __shared__ char smem[];
    int tid = threadIdx.x, w = tid >> 5, lane = tid & 31;
    long long bz = blockIdx.z;
    Ah += bz * sA; Al += bz * sA;
    Bh += bz * sB; Bl += bz * sB;
    C  += bz * sC;
    int m0 = blockIdx.y * 128, n0 = blockIdx.x * 128;
    const int NC = K / KC;

    auto load_stage = [&](int kofs, int s) {
        char* stg = smem + s * STG_SZ;
        #pragma unroll
        for (int i = 0; i < LPT; i++) {
            int idx = tid + i * 256;
            int mat = idx / (16 * KC);
            int cc  = idx % (16 * KC);
            int row = cc / CPR, kc = cc % CPR;
            uint32_t dst = smem_u32(stg + mat * STG_MAT + row * ROWB + kc * 16);
            const bf16* p = (mat == 0) ? Ah : (mat == 1) ? Al : (mat == 2) ? Bh : Bl;
            int b0 = (mat < 2) ? m0 : n0;
            int ld = (mat < 2) ? lda : ldb;
            CP_ASYNC16(dst, p + (size_t)(b0 + row) * ld + kofs + kc * 8);
        }
        CP_COMMIT();
    };

    load_stage(0, 0);
    if (NC > 1) load_stage(KC, 1);

    int g = lane >> 2, t = lane & 3;
    int wm = (w & 3) * 32, wn = (w >> 2) * 64;

    float acc[2][8][4];
    #pragma unroll
    for (int mt = 0; mt < 2; mt++)
        #pragma unroll
        for (int nt = 0; nt < 8; nt++)
            #pragma unroll
            for (int r = 0; r < 4; r++) acc[mt][nt][r] = 0.f;

    for (int kc = 0; kc < NC; kc++) {
        if (kc + 1 < NC) { CP_WAIT1(); } else { CP_WAIT0(); }
        __syncthreads();
        const char* stg = smem + (kc & 1) * STG_SZ;
        const char* pAh = stg;
        const char* pAl = stg + STG_MAT;
        const char* pBh = stg + 2 * STG_MAT;
        const char* pBl = stg + 3 * STG_MAT;

        #pragma unroll
        for (int ko = 0; ko < KC; ko += 16) {
            uint32_t aH[2][4], aL[2][4], b[8][2];
            #pragma unroll
            for (int mt = 0; mt < 2; mt++) {
                int r0 = (wm + mt * 16 + g) * ROWB + (ko + t * 2) * 2;
                aH[mt][0] = *(const uint32_t*)(pAh + r0);
                aH[mt][1] = *(const uint32_t*)(pAh + r0 + 8 * ROWB);
                aH[mt][2] = *(const uint32_t*)(pAh + r0 + 16);
                aH[mt][3] = *(const uint32_t*)(pAh + r0 + 8 * ROWB + 16);
                aL[mt][0] = *(const uint32_t*)(pAl + r0);
                aL[mt][1] = *(const uint32_t*)(pAl + r0 + 8 * ROWB);
                aL[mt][2] = *(const uint32_t*)(pAl + r0 + 16);
                aL[mt][3] = *(const uint32_t*)(pAl + r0 + 8 * ROWB + 16);
            }
            #pragma unroll
            for (int nt = 0; nt < 8; nt++) {
                int r0 = (wn + nt * 8 + g) * ROWB + (ko + t * 2) * 2;
                b[nt][0] = *(const uint32_t*)(pBh + r0);
                b[nt][1] = *(const uint32_t*)(pBh + r0 + 16);
            }
            #pragma unroll
            for (int mt = 0; mt < 2; mt++)
                #pragma unroll
                for (int nt = 0; nt < 8; nt++) {
                    mma16816(acc[mt][nt], aH[mt], b[nt]);
                    mma16816(acc[mt][nt], aL[mt], b[nt]);
                }
            #pragma unroll
            for (int nt = 0; nt < 8; nt++) {
                int r0 = (wn + nt * 8 + g) * ROWB + (ko + t * 2) * 2;
                b[nt][0] = *(const uint32_t*)(pBl + r0);
                b[nt][1] = *(const uint32_t*)(pBl + r0 + 16);
            }
            #pragma unroll
            for (int mt = 0; mt < 2; mt++)
                #pragma unroll
                for (int nt = 0; nt < 8; nt++)
                    mma16816(acc[mt][nt], aH[mt], b[nt]);
        }
        __syncthreads();
        if (kc + 2 < NC) load_stage((kc + 2) * KC, kc & 1);
    }

    #pragma unroll
    for (int mt = 0; mt < 2; mt++) {
        int r0 = m0 + wm + mt * 16 + g;
        float* c0p = C + (size_t)r0 * ldc + c0;
        float* c1p = C + (size_t)(r0 + 8) * ldc + c0;
        #pragma unroll
        for (int nt = 0; nt < 8; nt++) {
            int n = n0 + wn + nt * 8 + t * 2;
            if (n < Nreal) {
                float bv = bias ? bias[n] : 0.f;
                c0p[n] = alpha * acc[mt][nt][0] + cadd + bv;
                c1p[n] = alpha * acc[mt][nt][2] + cadd + bv;
            }
            if (n + 1 < Nreal) {
                float bv = bias ? bias[n + 1] : 0.f;
                c0p[n + 1] = alpha * acc[mt][nt][1] + cadd + bv;
                c1p[n + 1] = alpha * acc[mt][nt][3] + cadd + bv;
            }
        }
    }
}

#define SMEM_G64 (2 * 4 * 128 * 144)   // 147456

// ===================== fused flash attention =====================
// grid: (8 q-tiles of 128, 64 bh). 256 threads, 8 warps; warp w -> rows w*16..+15.
// Q/K rows: QKLD=80 bf16 -> 160B + 16 = 176B row stride.
// V: 72 d-rows x 64 tokens -> 128B + 16 = 144B row stride.
#define FQ_ROWB 176
#define FV_ROWB 144
#define FSM_QMAT (128*FQ_ROWB)                  // 22528
#define FSM_KMAT (64*FQ_ROWB)                   // 11264
#define FSM_VMAT (72*FV_ROWB)                   // 10368
#define FSM_KSTG (2*FSM_KMAT)                   // 22528 (hi+lo)
#define FSM_VSTG (2*FSM_VMAT)                   // 20736
#define FSM_K0   (2*FSM_QMAT)                   // 45056
#define FSM_V0   (FSM_K0 + 2*FSM_KSTG)          // 90112
#define FSM_TOTAL (FSM_V0 + 2*FSM_VSTG)         // 131584

__global__ __launch_bounds__(256)
void flash_attn(const bf16* __restrict__ qhh, const bf16* __restrict__ qhl,
                const bf16* __restrict__ khh, const bf16* __restrict__ khl,
                const bf16* __restrict__ vth, const bf16* __restrict__ vtl,
                bf16* __restrict__ cath, bf16* __restrict__ catl)
{
    extern __shared__ char smem[];
    int tid = threadIdx.x, w = tid >> 5, lane = tid & 31;
    int g = lane >> 2, t = lane & 3;
    int bh = blockIdx.y;
    int q0 = blockIdx.x * 128;

    // load Q tile (group 0)
    {
        #pragma unroll
        for (int i = 0; i < 10; i++) {
            int idx = tid + i * 256;           // 0..2559
            int mat = idx / 1280;
            int cc = idx % 1280;
            int row = cc / 10, ch = cc % 10;
            const bf16* src = (mat ? qhl : qhh) +
                ((size_t)bh * 1024 + q0 + row) * QKLD + ch * 8;
            uint32_t dst = smem_u32(smem + mat * FSM_QMAT + row * FQ_ROWB + ch * 16);
            CP_ASYNC16(dst, src);
        }
        CP_COMMIT();
    }

    auto load_kv = [&](int kt, int s) {
        char* kb = smem + FSM_K0 + s * FSM_KSTG;
        #pragma unroll
        for (int i = 0; i < 5; i++) {
            int idx = tid + i * 256;           // 0..1279
            int mat = idx / 640;
            int cc = idx % 640;
            int row = cc / 10, ch = cc % 10;
            const bf16* src = (mat ? khl : khh) +
                ((size_t)bh * 1024 + kt * 64 + row) * QKLD + ch * 8;
            uint32_t dst = smem_u32(kb + mat * FSM_KMAT + row * FQ_ROWB + ch * 16);
            CP_ASYNC16(dst, src);
        }
        char* vb = smem + FSM_V0 + s * FSM_VSTG;
        #pragma unroll
        for (int i = 0; i < 5; i++) {
            int idx = tid + i * 256;
            if (idx < 1152) {
                int mat = idx / 576;
                int cc = idx % 576;
                int row = cc / 8, ch = cc % 8;
                const bf16* src = (mat ? vtl : vth) +
                    ((size_t)bh * 72 + row) * 1024 + kt * 64 + ch * 8;
                uint32_t dst = smem_u32(vb + mat * FSM_VMAT + row * FV_ROWB + ch * 16);
                CP_ASYNC16(dst, src);
            }
        }
        CP_COMMIT();
    };

    load_kv(0, 0);

    float O[9][4];
    #pragma unroll
    for (int nv = 0; nv < 9; nv++)
        #pragma unroll
        for (int r = 0; r < 4; r++) O[nv][r] = 0.f;
    float m0 = -INFINITY, m1 = -INFINITY, l0 = 0.f, l1 = 0.f;

    for (int kt = 0; kt < 16; kt++) {
        if (kt + 1 < 16) { load_kv(kt + 1, (kt + 1) & 1); CP_WAIT1(); }
        else { CP_WAIT0(); }
        __syncthreads();
        const char* kb = smem + FSM_K0 + (kt & 1) * FSM_KSTG;
        const char* vb = smem + FSM_V0 + (kt & 1) * FSM_VSTG;
        const char* pKh = kb;
        const char* pKl = kb + FSM_KMAT;
        const char* pVh = vb;
        const char* pVl = vb + FSM_VMAT;

        // S = Q K^T (3-pass), warp rows w*16..+15, cols = 64 tokens
        float S[8][4];
        #pragma unroll
        for (int nt = 0; nt < 8; nt++)
            #pragma unroll
            for (int r = 0; r < 4; r++) S[nt][r] = 0.f;

        #pragma unroll
        for (int kk = 0; kk < 5; kk++) {
            uint32_t aH[4], aL[4], b[2];
            int r0 = (w * 16 + g) * FQ_ROWB + (kk * 16 + t * 2) * 2;
            aH[0] = *(const uint32_t*)(smem + r0);
            aH[1] = *(const uint32_t*)(smem + r0 + 8 * FQ_ROWB);
            aH[2] = *(const uint32_t*)(smem + r0 + 16);
            aH[3] = *(const uint32_t*)(smem + r0 + 8 * FQ_ROWB + 16);
            aL[0] = *(const uint32_t*)(smem + FSM_QMAT + r0);
            aL[1] = *(const uint32_t*)(smem + FSM_QMAT + r0 + 8 * FQ_ROWB);
            aL[2] = *(const uint32_t*)(smem + FSM_QMAT + r0 + 16);
            aL[3] = *(const uint32_t*)(smem + FSM_QMAT + r0 + 8 * FQ_ROWB + 16);
            #pragma unroll
            for (int nt = 0; nt < 8; nt++) {
                int rb = (nt * 8 + g) * FQ_ROWB + (kk * 16 + t * 2) * 2;
                b[0] = *(const uint32_t*)(pKh + rb);
                b[1] = *(const uint32_t*)(pKh + rb + 16);
                mma16816(S[nt], aH, b);
                mma16816(S[nt], aL, b);
                b[0] = *(const uint32_t*)(pKl + rb);
                b[1] = *(const uint32_t*)(pKl + rb + 16);
                mma16816(S[nt], aH, b);
            }
        }

        // scale + online softmax
        #pragma unroll
        for (int nt = 0; nt < 8; nt++)
            #pragma unroll
            for (int r = 0; r < 4; r++) S[nt][r] *= 0.25f;

        float lm0 = -INFINITY, lm1 = -INFINITY;
        #pragma unroll
        for (int nt = 0; nt < 8; nt++) {
            lm0 = fmaxf(lm0, fmaxf(S[nt][0], S[nt][1]));
            lm1 = fmaxf(lm1, fmaxf(S[nt][2], S[nt][3]));
        }
        lm0 = fmaxf(lm0, __shfl_xor_sync(0xffffffffu, lm0, 1));
        lm0 = fmaxf(lm0, __shfl_xor_sync(0xffffffffu, lm0, 2));
        lm1 = fmaxf(lm1, __shfl_xor_sync(0xffffffffu, lm1, 1));
        lm1 = fmaxf(lm1, __shfl_xor_sync(0xffffffffu, lm1, 2));
        float mn0 = fmaxf(m0, lm0), mn1 = fmaxf(m1, lm1);
        float sc0 = __expf(m0 - mn0), sc1 = __expf(m1 - mn1);
        m0 = mn0; m1 = mn1;
        l0 *= sc0; l1 *= sc1;
        #pragma unroll
        for (int nv = 0; nv < 9; nv++) {
            O[nv][0] *= sc0; O[nv][1] *= sc0;
            O[nv][2] *= sc1; O[nv][3] *= sc1;
        }
        #pragma unroll
        for (int nt = 0; nt < 8; nt++) {
            S[nt][0] = __expf(S[nt][0] - mn0);
            S[nt][1] = __expf(S[nt][1] - mn0);
            S[nt][2] = __expf(S[nt][2] - mn1);
            S[nt][3] = __expf(S[nt][3] - mn1);
            l0 += S[nt][0] + S[nt][1];
            l1 += S[nt][2] + S[nt][3];
        }

        // PV: O += P V (3-pass)
        #pragma unroll
        for (int ks = 0; ks < 4; ks++) {
            uint32_t pH[4], pL[4], b[2];
            pH[0] = pack_hi2(S[2 * ks][0], S[2 * ks][1]);
            pH[1] = pack_hi2(S[2 * ks][2], S[2 * ks][3]);
            pH[2] = pack_hi2(S[2 * ks + 1][0], S[2 * ks + 1][1]);
            pH[3] = pack_hi2(S[2 * ks + 1][2], S[2 * ks + 1][3]);
            pL[0] = pack_lo2(S[2 * ks][0], S[2 * ks][1]);
            pL[1] = pack_lo2(S[2 * ks][2], S[2 * ks][3]);
            pL[2] = pack_lo2(S[2 * ks + 1][0], S[2 * ks + 1][1]);
            pL[3] = pack_lo2(S[2 * ks + 1][2], S[2 * ks + 1][3]);
            #pragma unroll
            for (int nv = 0; nv < 9; nv++) {
                int rb = (nv * 8 + g) * FV_ROWB + (ks * 16 + t * 2) * 2;
                b[0] = *(const uint32_t*)(pVh + rb);
                b[1] = *(const uint32_t*)(pVh + rb + 16);
                mma16816(O[nv], pH, b);
                mma16816(O[nv], pL, b);
                b[0] = *(const uint32_t*)(pVl + rb);
                b[1] = *(const uint32_t*)(pVl + rb + 16);
                mma16816(O[nv], pH, b);
            }
        }
        __syncthreads();
    }

    // epilogue: mid = O / l, Lorentz normalize, write cat hi/lo
    l0 += __shfl_xor_sync(0xffffffffu, l0, 1);
    l0 += __shfl_xor_sync(0xffffffffu, l0, 2);
    l1 += __shfl_xor_sync(0xffffffffu, l1, 1);
    l1 += __shfl_xor_sync(0xffffffffu, l1, 2);
    float r0 = 1.f / l0, r1 = 1.f / l1;
    #pragma unroll
    for (int nv = 0; nv < 9; nv++) {
        O[nv][0] *= r0; O[nv][1] *= r0;
        O[nv][2] *= r1; O[nv][3] *= r1;
    }
    float t0 = __shfl_sync(0xffffffffu, O[0][0], lane & ~3);
    float t1 = __shfl_sync(0xffffffffu, O[0][2], lane & ~3);
    float ss0 = 0.f, ss1 = 0.f;
    #pragma unroll
    for (int nv = 0; nv < 9; nv++) {
        int c = nv * 8 + 2 * t;
        if (c >= 1 && c < 65) { ss0 += O[nv][0] * O[nv][0]; ss1 += O[nv][2] * O[nv][2]; }
        if (c + 1 >= 1 && c + 1 < 65) { ss0 += O[nv][1] * O[nv][1]; ss1 += O[nv][3] * O[nv][3]; }
    }
    ss0 += __shfl_xor_sync(0xffffffffu, ss0, 1);
    ss0 += __shfl_xor_sync(0xffffffffu, ss0, 2);
    ss1 += __shfl_xor_sync(0xffffffffu, ss1, 1);
    ss1 += __shfl_xor_sync(0xffffffffu, ss1, 2);
    float inv0 = rsqrtf(fmaxf(t0 * t0 - ss0, 1e-8f));
    float inv1 = rsqrtf(fmaxf(t1 * t1 - ss1, 1e-8f));

    int b = bh >> 4, h = bh & 15;
    int tr0 = b * 1024 + q0 + w * 16 + g;
    size_t base0 = (size_t)tr0 * 1088 + h * 65;
    size_t base1 = (size_t)(tr0 + 8) * 1088 + h * 65;
    #pragma unroll
    for (int nv = 0; nv < 9; nv++) {
        int c = nv * 8 + 2 * t;
        if (c < 65) {
            bf16 hh, ll;
            bsplit(O[nv][0] * inv0, hh, ll); cath[base0 + c] = hh; catl[base0 + c] = ll;
            bsplit(O[nv][2] * inv1, hh, ll); cath[base1 + c] = hh; catl[base1 + c] = ll;
        }
        if (c + 1 < 65) {
            bf16 hh, ll;
            bsplit(O[nv][1] * inv0, hh, ll); cath[base0 + c + 1] = hh; catl[base0 + c + 1] = ll;
            bsplit(O[nv][3] * inv1, hh, ll); cath[base1 + c + 1] = hh; catl[base1 + c + 1] = ll;
        }
    }
}

// ===================== transpose+split weights =====================
__global__ void k_tsplit(const float* __restrict__ W, bf16* __restrict__ Th,
                         bf16* __restrict__ Tl, int K, int N, int Kpad)
{
    __shared__ float t[32][33];
    int nb = blockIdx.x * 32, kb = blockIdx.y * 32;
    int tx = threadIdx.x, ty = threadIdx.y;
    #pragma unroll
    for (int i = 0; i < 32; i += 8) {
        int k = kb + ty + i, n = nb + tx;
        t[ty + i][tx] = (k < K && n < N) ? W[(size_t)k * N + n] : 0.f;
    }
    __syncthreads();
    #pragma unroll
    for (int i = 0; i < 32; i += 8) {
        int n = nb + ty + i, k = kb + tx;
        if (n < N && k < K) {
            float v = t[tx][ty + i];
            bf16 h, l; bsplit(v, h, l);
            Th[(size_t)n * Kpad + k] = h;
            Tl[(size_t)n * Kpad + k] = l;
        }
    }
}

// ===================== Lorentz layernorm -> hi/lo =====================
__global__ __launch_bounds__(256)
void k_ln(const float* __restrict__ x, const float* __restrict__ g,
          const float* __restrict__ b, bf16* __restrict__ oh, bf16* __restrict__ ol)
{
    __shared__ float sbuf[32];
    int t = blockIdx.x, tid = threadIdx.x;
    const float* xs = x + (size_t)t * 1024 + 1;
    float sv[4]; float s1 = 0.f, s2 = 0.f;
    #pragma unroll
    for (int j = 0; j < 4; j++) {
        int i = tid + j * 256;
        sv[j] = 0.f;
        if (i < 1023) { sv[j] = xs[i]; s1 += sv[j]; s2 += sv[j] * sv[j]; }
    }
    s1 = blk_sum(s1, sbuf);
    s2 = blk_sum(s2, sbuf);
    float mu = s1 * (1.f / 1023.f);
    float var = s2 * (1.f / 1023.f) - mu * mu;
    float rstd = rsqrtf(var + 1e-5f);
    float q = 0.f;
    float yv[4];
    #pragma unroll
    for (int j = 0; j < 4; j++) {
        int i = tid + j * 256;
        yv[j] = 0.f;
        if (i < 1023) {
            yv[j] = (sv[j] - mu) * rstd * g[i] + b[i];
            q += yv[j] * yv[j];
        }
    }
    q = blk_sum(q, sbuf);
    size_t base = (size_t)t * 1024;
    #pragma unroll
    for (int j = 0; j < 4; j++) {
        int i = tid + j * 256;
        if (i < 1023) {
            bf16 h, l; bsplit(yv[j], h, l);
            oh[base + 1 + i] = h; ol[base + 1 + i] = l;
        }
    }
    if (tid == 0) {
        bf16 h, l; bsplit(sqrtf(q + 1.f), h, l);
        oh[base] = h; ol[base] = l;
    }
}

// ===================== lift heads (q/k): (T,1024) -> (BH,N,QKLD) hi/lo =====================
__global__ __launch_bounds__(512)
void k_lift(const float* __restrict__ S, bf16* __restrict__ Oh, bf16* __restrict__ Ol, float sign)
{
    int t = blockIdx.x;
    int b = t >> 10, n = t & 1023;
    int w = threadIdx.x >> 5, lane = threadIdx.x & 31;
    const float* src = S + (size_t)t * 1024 + w * 64;
    float v0 = src[lane], v1 = src[lane + 32];
    float ss = v0 * v0 + v1 * v1;
    #pragma unroll
    for (int o = 16; o > 0; o >>= 1) ss += __shfl_down_sync(0xffffffffu, ss, o);
    ss = __shfl_sync(0xffffffffu, ss, 0);
    size_t base = ((size_t)(b * HH + w) * 1024 + n) * QKLD;
    bf16 h, l;
    bsplit(v0, h, l); Oh[base + 1 + lane] = h; Ol[base + 1 + lane] = l;
    bsplit(v1, h, l); Oh[base + 33 + lane] = h; Ol[base + 33 + lane] = l;
    if (lane == 0) {
        bsplit(sign * sqrtf(ss + 1.f), h, l);
        Oh[base] = h; Ol[base] = l;
    }
    for (int i = 65 + lane; i < QKLD; i += 32) {
        Oh[base + i] = __float2bfloat16(0.f);
        Ol[base + i] = __float2bfloat16(0.f);
    }
}

// ===================== lift+transpose v: -> (BH,72,1024) hi/lo =====================
__global__ void k_liftT(const float* __restrict__ vs, bf16* __restrict__ Th, bf16* __restrict__ Tl)
{
    int blk = blockIdx.x;
    int bh = blk >> 5;
    int tg = blk & 31;
    int b = bh >> 4, h = bh & 15;
    __shared__ float sv[32][65];
    __shared__ float stime[32];
    int tx = threadIdx.x, ty = threadIdx.y;
    #pragma unroll
    for (int i = 0; i < 32; i += 8) {
        int tok = i + ty;
        const float* src = vs + (size_t)(b * 1024 + tg * 32 + tok) * 1024 + h * 64;
        sv[tok][1 + tx] = src[tx];
        sv[tok][33 + tx] = src[tx + 32];
    }
    __syncthreads();
    if (ty == 0) {
        float s = 0.f;
        #pragma unroll
        for (int d = 1; d <= 64; d++) { float x = sv[tx][d]; s += x * x; }
        stime[tx] = sqrtf(s + 1.f);
    }
    __syncthreads();
    size_t base = (size_t)bh * (72 * 1024) + (size_t)(tg * 32);
    for (int d = ty; d < 72; d += 8) {
        float v = (d == 0) ? stime[tx] : (d < 65 ? sv[tx][d] : 0.f);
        bf16 hh, ll; bsplit(v, hh, ll);
        Th[base + (size_t)d * 1024 + tx] = hh;
        Tl[base + (size_t)d * 1024 + tx] = ll;
    }
}

// ===================== gelu + lift =====================
__global__ __launch_bounds__(256)
void k_gelu(const float* __restrict__ fcpre, bf16* __restrict__ fh, bf16* __restrict__ fl)
{
    __shared__ float sbuf[32];
    int t = blockIdx.x, tid = threadIdx.x;
    const float* rin = fcpre + (size_t)t * 4095;
    float gv[16];
    float q = 0.f;
    #pragma unroll
    for (int j = 0; j < 16; j++) {
        int i = tid + j * 256;
        gv[j] = 0.f;
        if (i < 4095) {
            float x = rin[i];
            gv[j] = 0.5f * x * (1.f + erff(x * 0.70710678118654752f));
            q += gv[j] * gv[j];
        }
    }
    q = blk_sum(q, sbuf);
    size_t base = (size_t)t * 4096;
    #pragma unroll
    for (int j = 0; j < 16; j++) {
        int i = tid + j * 256;
        if (i < 4095) {
            bf16 h, l; bsplit(gv[j], h, l);
            fh[base + 1 + i] = h; fl[base + 1 + i] = l;
        }
    }
    if (tid == 0) {
        bf16 h, l; bsplit(sqrtf(q + 1.f), h, l);
        fh[base] = h; fl[base] = l;
    }
}

// ===================== Lorentz residual =====================
__global__ __launch_bounds__(256)
void k_lresnet(const float* __restrict__ xin, const float* __restrict__ spart,
               const float* __restrict__ wp, float* __restrict__ out)
{
    __shared__ float sbuf[32];
    int t = blockIdx.x, tid = threadIdx.x;
    float w = wp[0];
    const float* xr = xin + (size_t)t * 1024;
    const float* ar = spart + (size_t)t * 1023;
    float xs[4], as[4];
    float sa = 0.f;
    #pragma unroll
    for (int j = 0; j < 4; j++) {
        int i = tid + j * 256;
        xs[j] = 0.f; as[j] = 0.f;
        if (i < 1023) { xs[j] = xr[1 + i]; as[j] = ar[i]; sa += as[j] * as[j]; }
    }
    sa = blk_sum(sa, sbuf);
    float axt = sqrtf(sa + 1.f);
    float zt = xr[0] + w * axt;
    float sz = 0.f;
    #pragma unroll
    for (int j = 0; j < 4; j++) {
        int i = tid + j * 256;
        if (i < 1023) { xs[j] = xs[j] + w * as[j]; sz += xs[j] * xs[j]; }
    }
    sz = blk_sum(sz, sbuf);
    float inv = rsqrtf(fmaxf(zt * zt - sz, 1e-8f));
    if (tid == 0) out[(size_t)t * 1024] = zt * inv;
    #pragma unroll
    for (int j = 0; j < 4; j++) {
        int i = tid + j * 256;
        if (i < 1023) out[(size_t)t * 1024 + 1 + i] = xs[j] * inv;
    }
}

// ===================== host =====================
extern "C" void kernel_launch(void* const* d_in, const int* in_sizes, int n_in,
                              void* d_out, int out_size)
{
    const float* x   = (const float*)d_in[0];
    const float* g1  = (const float*)d_in[1];
    const float* b1  = (const float*)d_in[2];
    const float* Wq  = (const float*)d_in[3];
    const float* bq  = (const float*)d_in[4];
    const float* Wk  = (const float*)d_in[5];
    const float* bk  = (const float*)d_in[6];
    const float* Wv  = (const float*)d_in[7];
    const float* bv  = (const float*)d_in[8];
    const float* Wo  = (const float*)d_in[9];
    const float* bo  = (const float*)d_in[10];
    const float* g2  = (const float*)d_in[11];
    const float* b2  = (const float*)d_in[12];
    const float* Wfc = (const float*)d_in[13];
    const float* bfc = (const float*)d_in[14];
    const float* Wpj = (const float*)d_in[15];
    const float* bpj = (const float*)d_in[16];
    const float* w1  = (const float*)d_in[17];
    const float* w2  = (const float*)d_in[18];
    float* out = (float*)d_out;

    cudaFuncSetAttribute(mma_gemm<64>, cudaFuncAttributeMaxDynamicSharedMemorySize, SMEM_G64);
    cudaFuncSetAttribute(flash_attn, cudaFuncAttributeMaxDynamicSharedMemorySize, FSM_TOTAL);

    #define SYM(p, s) do { void* _t; cudaGetSymbolAddress(&_t, s); p = decltype(p)(_t); } while (0)
    bf16 *lxh, *lxl, *WqTh, *WqTl, *WkTh, *WkTl, *WvTh, *WvTl, *WoTh, *WoTl;
    bf16 *WfcTh, *WfcTl, *WpjTh, *WpjTl;
    bf16 *qhh, *qhl, *khh, *khl, *vTh, *vTl, *cath, *catl, *h1h, *h1l, *fch, *fcl;
    float *qs, *ks, *vs, *axs, *x1, *fcpre, *pjs;
    SYM(lxh, g_lxh); SYM(lxl, g_lxl);
    SYM(WqTh, g_WqTh); SYM(WqTl, g_WqTl);
    SYM(WkTh, g_WkTh); SYM(WkTl, g_WkTl);
    SYM(WvTh, g_WvTh); SYM(WvTl, g_WvTl);
    SYM(WoTh, g_WoTh); SYM(WoTl, g_WoTl);
    SYM(WfcTh, g_WfcTh); SYM(WfcTl, g_WfcTl);
    SYM(WpjTh, g_WpjTh); SYM(WpjTl, g_WpjTl);
    SYM(qs, g_qs); SYM(ks, g_ks); SYM(vs, g_vs);
    SYM(qhh, g_qhh); SYM(qhl, g_qhl); SYM(khh, g_khh); SYM(khl, g_khl);
    SYM(vTh, g_vTh); SYM(vTl, g_vTl);
    SYM(cath, g_cath); SYM(catl, g_catl);
    SYM(axs, g_axs); SYM(x1, g_x1); SYM(h1h, g_h1h); SYM(h1l, g_h1l);
    SYM(fcpre, g_fcpre); SYM(fch, g_fch); SYM(fcl, g_fcl); SYM(pjs, g_pjs);

    dim3 tb(32, 8);
    // launches 1-5 (so launch 6 = mma_gemm for ncu)
    k_tsplit<<<dim3(32, 32), tb>>>(Wq, WqTh, WqTl, 1024, 1024, 1024);
    k_tsplit<<<dim3(32, 32), tb>>>(Wk, WkTh, WkTl, 1024, 1024, 1024);
    k_tsplit<<<dim3(32, 32), tb>>>(Wv, WvTh, WvTl, 1024, 1024, 1024);
    k_tsplit<<<dim3(32, 33), tb>>>(Wo, WoTh, WoTl, 1040, 1023, 1088);
    k_ln<<<TT, 256>>>(x, g1, b1, lxh, lxl);

    // QKV (launch 6 profiled)
    {
        dim3 grid(8, 32, 1);
        mma_gemm<64><<<grid, 256, SMEM_G64>>>(lxh, lxl, WqTh, WqTl, bq, qs,
            1024, 1024, 1024, 0, 1024, 1024, 0, 0, 0, 1.f, 0.f);
        mma_gemm<64><<<grid, 256, SMEM_G64>>>(lxh, lxl, WkTh, WkTl, bk, ks,
            1024, 1024, 1024, 0, 1024, 1024, 0, 0, 0, 1.f, 0.f);
        mma_gemm<64><<<grid, 256, SMEM_G64>>>(lxh, lxl, WvTh, WvTl, bv, vs,
            1024, 1024, 1024, 0, 1024, 1024, 0, 0, 0, 1.f, 0.f);
    }

    // remaining weight transposes
    k_tsplit<<<dim3(128, 32), tb>>>(Wfc, WfcTh, WfcTl, 1024, 4095, 1024);
    k_tsplit<<<dim3(32, 128), tb>>>(Wpj, WpjTh, WpjTl, 4096, 1023, 4096);

    // lifts
    k_lift<<<TT, 512>>>(qs, qhh, qhl, -1.f);
    k_lift<<<TT, 512>>>(ks, khh, khl, 1.f);
    k_liftT<<<BHN * 32, tb>>>(vs, vTh, vTl);

    // fused flash attention -> cat (replaces scores GEMM + softmax + AV GEMM + normcat)
    flash_attn<<<dim3(8, BHN), 256, FSM_TOTAL>>>(qhh, qhl, khh, khl, vTh, vTl, cath, catl);

    // Wo
    mma_gemm<64><<<dim3(8, 32, 1), 256, SMEM_G64>>>(cath, catl, WoTh, WoTl, bo, axs,
        1088, 1088, 1023, 0, 1023, 1088, 0, 0, 0, 1.f, 0.f);

    // residual 1
    k_lresnet<<<TT, 256>>>(x, axs, w1, x1);

    // LN2
    k_ln<<<TT, 256>>>(x1, g2, b2, h1h, h1l);

    // Wfc
    mma_gemm<64><<<dim3(32, 32, 1), 256, SMEM_G64>>>(h1h, h1l, WfcTh, WfcTl, bfc, fcpre,
        1024, 1024, 4095, 0, 4095, 1024, 0, 0, 0, 1.f, 0.f);

    // gelu + lift
    k_gelu<<<TT, 256>>>(fcpre, fch, fcl);

    // Wpj
    mma_gemm<64><<<dim3(8, 32, 1), 256, SMEM_G64>>>(fch, fcl, WpjTh, WpjTl, bpj, pjs,
        4096, 4096, 1023, 0, 1023, 4096, 0, 0, 0, 1.f, 0.f);

    // residual 2
    k_lresnet<<<TT, 256>>>(x1, pjs, w2, out);
}

// round 7
// speedup vs baseline: 2.2498x; 1.2050x over previous
#include <cuda_runtime.h>
#include <cuda_bf16.h>
#include <cuda_fp16.h>
#include <math.h>
#include <stdint.h>

// Problem constants
#define BB 4
#define NNTOK 1024
#define DDIM 1024
#define HH 16
#define TT (BB*NNTOK)     // 4096 tokens
#define BHN (BB*HH)       // 64
#define QKLD 80           // padded lifted q/k leading dim (65 -> 80)

typedef __nv_bfloat16 bf16;
typedef __half f16;

// ===================== scratch (device globals) =====================
__device__ __align__(128) f16   g_lxh [TT*1024];
__device__ __align__(128) f16   g_lxl [TT*1024];
__device__ __align__(128) f16   g_WqTh[1024*1024];
__device__ __align__(128) f16   g_WkTh[1024*1024];
__device__ __align__(128) f16   g_WvTh[1024*1024];
__device__ __align__(128) bf16  g_WoTh[1024*1088];
__device__ __align__(128) bf16  g_WoTl[1024*1088];
__device__ __align__(128) f16   g_WfcTh[4096*1024];
__device__ __align__(128) f16   g_WpjTh[1024*4096];
__device__ __align__(128) float g_qs  [TT*1024];
__device__ __align__(128) float g_ks  [TT*1024];
__device__ __align__(128) float g_vs  [TT*1024];
__device__ __align__(128) bf16  g_qhh [(size_t)BHN*1024*QKLD];
__device__ __align__(128) bf16  g_qhl [(size_t)BHN*1024*QKLD];
__device__ __align__(128) bf16  g_khh [(size_t)BHN*1024*QKLD];
__device__ __align__(128) bf16  g_khl [(size_t)BHN*1024*QKLD];
__device__ __align__(128) bf16  g_vTh [(size_t)BHN*72*1024];
__device__ __align__(128) bf16  g_vTl [(size_t)BHN*72*1024];
__device__ __align__(128) bf16  g_cath[TT*1088];
__device__ __align__(128) bf16  g_catl[TT*1088];
__device__ __align__(128) float g_axs [TT*1023];
__device__ __align__(128) float g_x1  [TT*1024];
__device__ __align__(128) f16   g_h1h [TT*1024];
__device__ __align__(128) f16   g_h1l [TT*1024];
__device__ __align__(128) float g_fcpre[(size_t)TT*4095];
__device__ __align__(128) f16   g_fch [(size_t)TT*4096];
__device__ __align__(128) f16   g_fcl [(size_t)TT*4096];
__device__ __align__(128) float g_pjs [TT*1023];

// ===================== PTX helpers =====================
__device__ __forceinline__ uint32_t smem_u32(const void* p) {
    uint32_t a;
    asm("{ .reg .u64 t; cvta.to.shared.u64 t, %1; cvt.u32.u64 %0, t; }" : "=r"(a) : "l"(p));
    return a;
}

#define CP_ASYNC16(dst, src) \
    asm volatile("cp.async.cg.shared.global [%0], [%1], 16;" :: "r"(dst), "l"(src))
#define CP_COMMIT() asm volatile("cp.async.commit_group;")
#define CP_WAIT1()  asm volatile("cp.async.wait_group 1;")
#define CP_WAIT0()  asm volatile("cp.async.wait_group 0;")

__device__ __forceinline__ void mma16816(float* c, const uint32_t* a, const uint32_t* b) {
    asm volatile(
        "mma.sync.aligned.m16n8k16.row.col.f32.bf16.bf16.f32 "
        "{%0,%1,%2,%3}, {%4,%5,%6,%7}, {%8,%9}, {%0,%1,%2,%3};"
        : "+f"(c[0]), "+f"(c[1]), "+f"(c[2]), "+f"(c[3])
        : "r"(a[0]), "r"(a[1]), "r"(a[2]), "r"(a[3]), "r"(b[0]), "r"(b[1]));
}
__device__ __forceinline__ void mma16816h(float* c, const uint32_t* a, const uint32_t* b) {
    asm volatile(
        "mma.sync.aligned.m16n8k16.row.col.f32.f16.f16.f32 "
        "{%0,%1,%2,%3}, {%4,%5,%6,%7}, {%8,%9}, {%0,%1,%2,%3};"
        : "+f"(c[0]), "+f"(c[1]), "+f"(c[2]), "+f"(c[3])
        : "r"(a[0]), "r"(a[1]), "r"(a[2]), "r"(a[3]), "r"(b[0]), "r"(b[1]));
}

__device__ __forceinline__ void bsplit(float v, bf16& h, bf16& l) {
    h = __float2bfloat16(v);
    l = __float2bfloat16(v - __bfloat162float(h));
}
__device__ __forceinline__ void hsplit(float v, f16& h, f16& l) {
    h = __float2half(v);
    l = __float2half(v - __half2float(h));
}

__device__ __forceinline__ uint32_t pack_hi2(float a, float b) {
    __nv_bfloat162 r = __floats2bfloat162_rn(a, b);
    return *(uint32_t*)&r;
}
__device__ __forceinline__ uint32_t pack_lo2(float a, float b) {
    float ra = a - __bfloat162float(__float2bfloat16(a));
    float rb = b - __bfloat162float(__float2bfloat16(b));
    __nv_bfloat162 r = __floats2bfloat162_rn(ra, rb);
    return *(uint32_t*)&r;
}

// ===================== block reductions =====================
__device__ __forceinline__ float blk_sum(float v, float* sbuf) {
    int tid = threadIdx.x;
    #pragma unroll
    for (int o = 16; o > 0; o >>= 1) v += __shfl_down_sync(0xffffffffu, v, o);
    if ((tid & 31) == 0) sbuf[tid >> 5] = v;
    __syncthreads();
    if (tid < 32) {
        int nw = (blockDim.x + 31) >> 5;
        float x = (tid < nw) ? sbuf[tid] : 0.f;
        #pragma unroll
        for (int o = 16; o > 0; o >>= 1) x += __shfl_down_sync(0xffffffffu, x, o);
        if (tid == 0) sbuf[0] = x;
    }
    __syncthreads();
    float r = sbuf[0];
    __syncthreads();
    return r;
}

// ===================== bf16 3-pass GEMM (Wo path) =====================
template<int KC>
__global__ __launch_bounds__(256)
void mma_gemm(const bf16* __restrict__ Ah, const bf16* __restrict__ Al,
              const bf16* __restrict__ Bh, const bf16* __restrict__ Bl,
              const float* __restrict__ bias, float* __restrict__ C,
              int lda, int ldb, int ldc, int c0, int Nreal, int K,
              float alpha, float cadd)
{
    constexpr int ROWB = 2 * KC + 16;
    constexpr int STG_MAT = 128 * ROWB;
    constexpr int STG_SZ = 4 * STG_MAT;
    constexpr int CPR = KC / 8;
    constexpr int LPT = KC / 4;

    extern __shared__ char smem[];
    int tid = threadIdx.x, w = tid >> 5, lane = tid & 31;
    int m0 = blockIdx.y * 128, n0 = blockIdx.x * 128;
    const int NC = K / KC;

    auto load_stage = [&](int kofs, int s) {
        char* stg = smem + s * STG_SZ;
        #pragma unroll
        for (int i = 0; i < LPT; i++) {
            int idx = tid + i * 256;
            int mat = idx / (16 * KC);
            int cc  = idx % (16 * KC);
            int row = cc / CPR, kc = cc % CPR;
            uint32_t dst = smem_u32(stg + mat * STG_MAT + row * ROWB + kc * 16);
            const bf16* p = (mat == 0) ? Ah : (mat == 1) ? Al : (mat == 2) ? Bh : Bl;
            int b0 = (mat < 2) ? m0 : n0;
            int ld = (mat < 2) ? lda : ldb;
            CP_ASYNC16(dst, p + (size_t)(b0 + row) * ld + kofs + kc * 8);
        }
        CP_COMMIT();
    };

    load_stage(0, 0);
    if (NC > 1) load_stage(KC, 1);

    int g = lane >> 2, t = lane & 3;
    int wm = (w & 3) * 32, wn = (w >> 2) * 64;

    float acc[2][8][4];
    #pragma unroll
    for (int mt = 0; mt < 2; mt++)
        #pragma unroll
        for (int nt = 0; nt < 8; nt++)
            #pragma unroll
            for (int r = 0; r < 4; r++) acc[mt][nt][r] = 0.f;

    for (int kc = 0; kc < NC; kc++) {
        if (kc + 1 < NC) { CP_WAIT1(); } else { CP_WAIT0(); }
        __syncthreads();
        const char* stg = smem + (kc & 1) * STG_SZ;
        const char* pAh = stg;
        const char* pAl = stg + STG_MAT;
        const char* pBh = stg + 2 * STG_MAT;
        const char* pBl = stg + 3 * STG_MAT;

        #pragma unroll
        for (int ko = 0; ko < KC; ko += 16) {
            uint32_t aH[2][4], aL[2][4], b[8][2];
            #pragma unroll
            for (int mt = 0; mt < 2; mt++) {
                int r0 = (wm + mt * 16 + g) * ROWB + (ko + t * 2) * 2;
                aH[mt][0] = *(const uint32_t*)(pAh + r0);
                aH[mt][1] = *(const uint32_t*)(pAh + r0 + 8 * ROWB);
                aH[mt][2] = *(const uint32_t*)(pAh + r0 + 16);
                aH[mt][3] = *(const uint32_t*)(pAh + r0 + 8 * ROWB + 16);
                aL[mt][0] = *(const uint32_t*)(pAl + r0);
                aL[mt][1] = *(const uint32_t*)(pAl + r0 + 8 * ROWB);
                aL[mt][2] = *(const uint32_t*)(pAl + r0 + 16);
                aL[mt][3] = *(const uint32_t*)(pAl + r0 + 8 * ROWB + 16);
            }
            #pragma unroll
            for (int nt = 0; nt < 8; nt++) {
                int r0 = (wn + nt * 8 + g) * ROWB + (ko + t * 2) * 2;
                b[nt][0] = *(const uint32_t*)(pBh + r0);
                b[nt][1] = *(const uint32_t*)(pBh + r0 + 16);
            }
            #pragma unroll
            for (int mt = 0; mt < 2; mt++)
                #pragma unroll
                for (int nt = 0; nt < 8; nt++) {
                    mma16816(acc[mt][nt], aH[mt], b[nt]);
                    mma16816(acc[mt][nt], aL[mt], b[nt]);
                }
            #pragma unroll
            for (int nt = 0; nt < 8; nt++) {
                int r0 = (wn + nt * 8 + g) * ROWB + (ko + t * 2) * 2;
                b[nt][0] = *(const uint32_t*)(pBl + r0);
                b[nt][1] = *(const uint32_t*)(pBl + r0 + 16);
            }
            #pragma unroll
            for (int mt = 0; mt < 2; mt++)
                #pragma unroll
                for (int nt = 0; nt < 8; nt++)
                    mma16816(acc[mt][nt], aH[mt], b[nt]);
        }
        __syncthreads();
        if (kc + 2 < NC) load_stage((kc + 2) * KC, kc & 1);
    }

    #pragma unroll
    for (int mt = 0; mt < 2; mt++) {
        int r0 = m0 + wm + mt * 16 + g;
        float* c0p = C + (size_t)r0 * ldc + c0;
        float* c1p = C + (size_t)(r0 + 8) * ldc + c0;
        #pragma unroll
        for (int nt = 0; nt < 8; nt++) {
            int n = n0 + wn + nt * 8 + t * 2;
            if (n < Nreal) {
                float bv = bias ? bias[n] : 0.f;
                c0p[n] = alpha * acc[mt][nt][0] + cadd + bv;
                c1p[n] = alpha * acc[mt][nt][2] + cadd + bv;
            }
            if (n + 1 < Nreal) {
                float bv = bias ? bias[n + 1] : 0.f;
                c0p[n + 1] = alpha * acc[mt][nt][1] + cadd + bv;
                c1p[n + 1] = alpha * acc[mt][nt][3] + cadd + bv;
            }
        }
    }
}

#define SMEM_G64 (2 * 4 * 128 * 144)   // 147456

// ===================== fp16 2-pass GEMM (A exact, B fp16-rounded) =====================
// D = (Ah+Al) * Bh^T + bias : 3 smem matrices per stage.
template<int KC>
__global__ __launch_bounds__(256)
void gemm2p(const f16* __restrict__ Ah, const f16* __restrict__ Al,
            const f16* __restrict__ Bh,
            const float* __restrict__ bias, float* __restrict__ C,
            int lda, int ldb, int ldc, int Nreal, int K)
{
    constexpr int ROWB = 2 * KC + 16;
    constexpr int STG_MAT = 128 * ROWB;
    constexpr int STG_SZ = 3 * STG_MAT;
    constexpr int CPR = KC / 8;
    constexpr int LPT = 3 * KC / 16;

    extern __shared__ char smem[];
    int tid = threadIdx.x, w = tid >> 5, lane = tid & 31;
    int m0 = blockIdx.y * 128, n0 = blockIdx.x * 128;
    const int NC = K / KC;

    auto load_stage = [&](int kofs, int s) {
        char* stg = smem + s * STG_SZ;
        #pragma unroll
        for (int i = 0; i < LPT; i++) {
            int idx = tid + i * 256;
            int mat = idx / (16 * KC);            // 0:Ah 1:Al 2:Bh
            int cc  = idx % (16 * KC);
            int row = cc / CPR, kc = cc % CPR;
            uint32_t dst = smem_u32(stg + mat * STG_MAT + row * ROWB + kc * 16);
            const f16* p = (mat == 0) ? Ah : (mat == 1) ? Al : Bh;
            int b0 = (mat < 2) ? m0 : n0;
            int ld = (mat < 2) ? lda : ldb;
            CP_ASYNC16(dst, p + (size_t)(b0 + row) * ld + kofs + kc * 8);
        }
        CP_COMMIT();
    };

    load_stage(0, 0);
    if (NC > 1) load_stage(KC, 1);

    int g = lane >> 2, t = lane & 3;
    int wm = (w & 3) * 32, wn = (w >> 2) * 64;

    float acc[2][8][4];
    #pragma unroll
    for (int mt = 0; mt < 2; mt++)
        #pragma unroll
        for (int nt = 0; nt < 8; nt++)
            #pragma unroll
            for (int r = 0; r < 4; r++) acc[mt][nt][r] = 0.f;

    for (int kc = 0; kc < NC; kc++) {
        if (kc + 1 < NC) { CP_WAIT1(); } else { CP_WAIT0(); }
        __syncthreads();
        const char* stg = smem + (kc & 1) * STG_SZ;
        const char* pAh = stg;
        const char* pAl = stg + STG_MAT;
        const char* pBh = stg + 2 * STG_MAT;

        #pragma unroll
        for (int ko = 0; ko < KC; ko += 16) {
            uint32_t aH[2][4], aL[2][4], b[8][2];
            #pragma unroll
            for (int mt = 0; mt < 2; mt++) {
                int r0 = (wm + mt * 16 + g) * ROWB + (ko + t * 2) * 2;
                aH[mt][0] = *(const uint32_t*)(pAh + r0);
                aH[mt][1] = *(const uint32_t*)(pAh + r0 + 8 * ROWB);
                aH[mt][2] = *(const uint32_t*)(pAh + r0 + 16);
                aH[mt][3] = *(const uint32_t*)(pAh + r0 + 8 * ROWB + 16);
                aL[mt][0] = *(const uint32_t*)(pAl + r0);
                aL[mt][1] = *(const uint32_t*)(pAl + r0 + 8 * ROWB);
                aL[mt][2] = *(const uint32_t*)(pAl + r0 + 16);
                aL[mt][3] = *(const uint32_t*)(pAl + r0 + 8 * ROWB + 16);
            }
            #pragma unroll
            for (int nt = 0; nt < 8; nt++) {
                int r0 = (wn + nt * 8 + g) * ROWB + (ko + t * 2) * 2;
                b[nt][0] = *(const uint32_t*)(pBh + r0);
                b[nt][1] = *(const uint32_t*)(pBh + r0 + 16);
            }
            #pragma unroll
            for (int mt = 0; mt < 2; mt++)
                #pragma unroll
                for (int nt = 0; nt < 8; nt++) {
                    mma16816h(acc[mt][nt], aH[mt], b[nt]);
                    mma16816h(acc[mt][nt], aL[mt], b[nt]);
                }
        }
        __syncthreads();
        if (kc + 2 < NC) load_stage((kc + 2) * KC, kc & 1);
    }

    #pragma unroll
    for (int mt = 0; mt < 2; mt++) {
        int r0 = m0 + wm + mt * 16 + g;
        float* c0p = C + (size_t)r0 * ldc;
        float* c1p = C + (size_t)(r0 + 8) * ldc;
        #pragma unroll
        for (int nt = 0; nt < 8; nt++) {
            int n = n0 + wn + nt * 8 + t * 2;
            if (n < Nreal) {
                float bv = bias ? bias[n] : 0.f;
                c0p[n] = acc[mt][nt][0] + bv;
                c1p[n] = acc[mt][nt][2] + bv;
            }
            if (n + 1 < Nreal) {
                float bv = bias ? bias[n + 1] : 0.f;
                c0p[n + 1] = acc[mt][nt][1] + bv;
                c1p[n + 1] = acc[mt][nt][3] + bv;
            }
        }
    }
}

#define SMEM_2P64 (2 * 3 * 128 * 144)  // 110592

// ===================== fused flash attention (unchanged from R6) =====================
#define FQ_ROWB 176
#define FV_ROWB 144
#define FSM_QMAT (128*FQ_ROWB)
#define FSM_KMAT (64*FQ_ROWB)
#define FSM_VMAT (72*FV_ROWB)
#define FSM_KSTG (2*FSM_KMAT)
#define FSM_VSTG (2*FSM_VMAT)
#define FSM_K0   (2*FSM_QMAT)
#define FSM_V0   (FSM_K0 + 2*FSM_KSTG)
#define FSM_TOTAL (FSM_V0 + 2*FSM_VSTG)

__global__ __launch_bounds__(256)
void flash_attn(const bf16* __restrict__ qhh, const bf16* __restrict__ qhl,
                const bf16* __restrict__ khh, const bf16* __restrict__ khl,
                const bf16* __restrict__ vth, const bf16* __restrict__ vtl,
                bf16* __restrict__ cath, bf16* __restrict__ catl)
{
    extern __shared__ char smem[];
    int tid = threadIdx.x, w = tid >> 5, lane = tid & 31;
    int g = lane >> 2, t = lane & 3;
    int bh = blockIdx.y;
    int q0 = blockIdx.x * 128;

    {
        #pragma unroll
        for (int i = 0; i < 10; i++) {
            int idx = tid + i * 256;
            int mat = idx / 1280;
            int cc = idx % 1280;
            int row = cc / 10, ch = cc % 10;
            const bf16* src = (mat ? qhl : qhh) +
                ((size_t)bh * 1024 + q0 + row) * QKLD + ch * 8;
            uint32_t dst = smem_u32(smem + mat * FSM_QMAT + row * FQ_ROWB + ch * 16);
            CP_ASYNC16(dst, src);
        }
        CP_COMMIT();
    }

    auto load_kv = [&](int kt, int s) {
        char* kb = smem + FSM_K0 + s * FSM_KSTG;
        #pragma unroll
        for (int i = 0; i < 5; i++) {
            int idx = tid + i * 256;
            int mat = idx / 640;
            int cc = idx % 640;
            int row = cc / 10, ch = cc % 10;
            const bf16* src = (mat ? khl : khh) +
                ((size_t)bh * 1024 + kt * 64 + row) * QKLD + ch * 8;
            uint32_t dst = smem_u32(kb + mat * FSM_KMAT + row * FQ_ROWB + ch * 16);
            CP_ASYNC16(dst, src);
        }
        char* vb = smem + FSM_V0 + s * FSM_VSTG;
        #pragma unroll
        for (int i = 0; i < 5; i++) {
            int idx = tid + i * 256;
            if (idx < 1152) {
                int mat = idx / 576;
                int cc = idx % 576;
                int row = cc / 8, ch = cc % 8;
                const bf16* src = (mat ? vtl : vth) +
                    ((size_t)bh * 72 + row) * 1024 + kt * 64 + ch * 8;
                uint32_t dst = smem_u32(vb + mat * FSM_VMAT + row * FV_ROWB + ch * 16);
                CP_ASYNC16(dst, src);
            }
        }
        CP_COMMIT();
    };

    load_kv(0, 0);

    float O[9][4];
    #pragma unroll
    for (int nv = 0; nv < 9; nv++)
        #pragma unroll
        for (int r = 0; r < 4; r++) O[nv][r] = 0.f;
    float m0 = -INFINITY, m1 = -INFINITY, l0 = 0.f, l1 = 0.f;

    for (int kt = 0; kt < 16; kt++) {
        if (kt + 1 < 16) { load_kv(kt + 1, (kt + 1) & 1); CP_WAIT1(); }
        else { CP_WAIT0(); }
        __syncthreads();
        const char* kb = smem + FSM_K0 + (kt & 1) * FSM_KSTG;
        const char* vb = smem + FSM_V0 + (kt & 1) * FSM_VSTG;
        const char* pKh = kb;
        const char* pKl = kb + FSM_KMAT;
        const char* pVh = vb;
        const char* pVl = vb + FSM_VMAT;

        float S[8][4];
        #pragma unroll
        for (int nt = 0; nt < 8; nt++)
            #pragma unroll
            for (int r = 0; r < 4; r++) S[nt][r] = 0.f;

        #pragma unroll
        for (int kk = 0; kk < 5; kk++) {
            uint32_t aH[4], aL[4], b[2];
            int r0 = (w * 16 + g) * FQ_ROWB + (kk * 16 + t * 2) * 2;
            aH[0] = *(const uint32_t*)(smem + r0);
            aH[1] = *(const uint32_t*)(smem + r0 + 8 * FQ_ROWB);
            aH[2] = *(const uint32_t*)(smem + r0 + 16);
            aH[3] = *(const uint32_t*)(smem + r0 + 8 * FQ_ROWB + 16);
            aL[0] = *(const uint32_t*)(smem + FSM_QMAT + r0);
            aL[1] = *(const uint32_t*)(smem + FSM_QMAT + r0 + 8 * FQ_ROWB);
            aL[2] = *(const uint32_t*)(smem + FSM_QMAT + r0 + 16);
            aL[3] = *(const uint32_t*)(smem + FSM_QMAT + r0 + 8 * FQ_ROWB + 16);
            #pragma unroll
            for (int nt = 0; nt < 8; nt++) {
                int rb = (nt * 8 + g) * FQ_ROWB + (kk * 16 + t * 2) * 2;
                b[0] = *(const uint32_t*)(pKh + rb);
                b[1] = *(const uint32_t*)(pKh + rb + 16);
                mma16816(S[nt], aH, b);
                mma16816(S[nt], aL, b);
                b[0] = *(const uint32_t*)(pKl + rb);
                b[1] = *(const uint32_t*)(pKl + rb + 16);
                mma16816(S[nt], aH, b);
            }
        }

        #pragma unroll
        for (int nt = 0; nt < 8; nt++)
            #pragma unroll
            for (int r = 0; r < 4; r++) S[nt][r] *= 0.25f;

        float lm0 = -INFINITY, lm1 = -INFINITY;
        #pragma unroll
        for (int nt = 0; nt < 8; nt++) {
            lm0 = fmaxf(lm0, fmaxf(S[nt][0], S[nt][1]));
            lm1 = fmaxf(lm1, fmaxf(S[nt][2], S[nt][3]));
        }
        lm0 = fmaxf(lm0, __shfl_xor_sync(0xffffffffu, lm0, 1));
        lm0 = fmaxf(lm0, __shfl_xor_sync(0xffffffffu, lm0, 2));
        lm1 = fmaxf(lm1, __shfl_xor_sync(0xffffffffu, lm1, 1));
        lm1 = fmaxf(lm1, __shfl_xor_sync(0xffffffffu, lm1, 2));
        float mn0 = fmaxf(m0, lm0), mn1 = fmaxf(m1, lm1);
        float sc0 = __expf(m0 - mn0), sc1 = __expf(m1 - mn1);
        m0 = mn0; m1 = mn1;
        l0 *= sc0; l1 *= sc1;
        #pragma unroll
        for (int nv = 0; nv < 9; nv++) {
            O[nv][0] *= sc0; O[nv][1] *= sc0;
            O[nv][2] *= sc1; O[nv][3] *= sc1;
        }
        #pragma unroll
        for (int nt = 0; nt < 8; nt++) {
            S[nt][0] = __expf(S[nt][0] - mn0);
            S[nt][1] = __expf(S[nt][1] - mn0);
            S[nt][2] = __expf(S[nt][2] - mn1);
            S[nt][3] = __expf(S[nt][3] - mn1);
            l0 += S[nt][0] + S[nt][1];
            l1 += S[nt][2] + S[nt][3];
        }

        #pragma unroll
        for (int ks = 0; ks < 4; ks++) {
            uint32_t pH[4], pL[4], b[2];
            pH[0] = pack_hi2(S[2 * ks][0], S[2 * ks][1]);
            pH[1] = pack_hi2(S[2 * ks][2], S[2 * ks][3]);
            pH[2] = pack_hi2(S[2 * ks + 1][0], S[2 * ks + 1][1]);
            pH[3] = pack_hi2(S[2 * ks + 1][2], S[2 * ks + 1][3]);
            pL[0] = pack_lo2(S[2 * ks][0], S[2 * ks][1]);
            pL[1] = pack_lo2(S[2 * ks][2], S[2 * ks][3]);
            pL[2] = pack_lo2(S[2 * ks + 1][0], S[2 * ks + 1][1]);
            pL[3] = pack_lo2(S[2 * ks + 1][2], S[2 * ks + 1][3]);
            #pragma unroll
            for (int nv = 0; nv < 9; nv++) {
                int rb = (nv * 8 + g) * FV_ROWB + (ks * 16 + t * 2) * 2;
                b[0] = *(const uint32_t*)(pVh + rb);
                b[1] = *(const uint32_t*)(pVh + rb + 16);
                mma16816(O[nv], pH, b);
                mma16816(O[nv], pL, b);
                b[0] = *(const uint32_t*)(pVl + rb);
                b[1] = *(const uint32_t*)(pVl + rb + 16);
                mma16816(O[nv], pH, b);
            }
        }
        __syncthreads();
    }

    l0 += __shfl_xor_sync(0xffffffffu, l0, 1);
    l0 += __shfl_xor_sync(0xffffffffu, l0, 2);
    l1 += __shfl_xor_sync(0xffffffffu, l1, 1);
    l1 += __shfl_xor_sync(0xffffffffu, l1, 2);
    float r0 = 1.f / l0, r1 = 1.f / l1;
    #pragma unroll
    for (int nv = 0; nv < 9; nv++) {
        O[nv][0] *= r0; O[nv][1] *= r0;
        O[nv][2] *= r1; O[nv][3] *= r1;
    }
    float t0 = __shfl_sync(0xffffffffu, O[0][0], lane & ~3);
    float t1 = __shfl_sync(0xffffffffu, O[0][2], lane & ~3);
    float ss0 = 0.f, ss1 = 0.f;
    #pragma unroll
    for (int nv = 0; nv < 9; nv++) {
        int c = nv * 8 + 2 * t;
        if (c >= 1 && c < 65) { ss0 += O[nv][0] * O[nv][0]; ss1 += O[nv][2] * O[nv][2]; }
        if (c + 1 >= 1 && c + 1 < 65) { ss0 += O[nv][1] * O[nv][1]; ss1 += O[nv][3] * O[nv][3]; }
    }
    ss0 += __shfl_xor_sync(0xffffffffu, ss0, 1);
    ss0 += __shfl_xor_sync(0xffffffffu, ss0, 2);
    ss1 += __shfl_xor_sync(0xffffffffu, ss1, 1);
    ss1 += __shfl_xor_sync(0xffffffffu, ss1, 2);
    float inv0 = rsqrtf(fmaxf(t0 * t0 - ss0, 1e-8f));
    float inv1 = rsqrtf(fmaxf(t1 * t1 - ss1, 1e-8f));

    int b = bh >> 4, h = bh & 15;
    int tr0 = b * 1024 + q0 + w * 16 + g;
    size_t base0 = (size_t)tr0 * 1088 + h * 65;
    size_t base1 = (size_t)(tr0 + 8) * 1088 + h * 65;
    #pragma unroll
    for (int nv = 0; nv < 9; nv++) {
        int c = nv * 8 + 2 * t;
        if (c < 65) {
            bf16 hh, ll;
            bsplit(O[nv][0] * inv0, hh, ll); cath[base0 + c] = hh; catl[base0 + c] = ll;
            bsplit(O[nv][2] * inv1, hh, ll); cath[base1 + c] = hh; catl[base1 + c] = ll;
        }
        if (c + 1 < 65) {
            bf16 hh, ll;
            bsplit(O[nv][1] * inv0, hh, ll); cath[base0 + c + 1] = hh; catl[base0 + c + 1] = ll;
            bsplit(O[nv][3] * inv1, hh, ll); cath[base1 + c + 1] = hh; catl[base1 + c + 1] = ll;
        }
    }
}

// ===================== weight transposes =====================
__global__ void k_tsplit(const float* __restrict__ W, bf16* __restrict__ Th,
                         bf16* __restrict__ Tl, int K, int N, int Kpad)
{
    __shared__ float t[32][33];
    int nb = blockIdx.x * 32, kb = blockIdx.y * 32;
    int tx = threadIdx.x, ty = threadIdx.y;
    #pragma unroll
    for (int i = 0; i < 32; i += 8) {
        int k = kb + ty + i, n = nb + tx;
        t[ty + i][tx] = (k < K && n < N) ? W[(size_t)k * N + n] : 0.f;
    }
    __syncthreads();
    #pragma unroll
    for (int i = 0; i < 32; i += 8) {
        int n = nb + ty + i, k = kb + tx;
        if (n < N && k < K) {
            float v = t[tx][ty + i];
            bf16 h, l; bsplit(v, h, l);
            Th[(size_t)n * Kpad + k] = h;
            Tl[(size_t)n * Kpad + k] = l;
        }
    }
}

__global__ void k_tsplit_h(const float* __restrict__ W, f16* __restrict__ Th,
                           int K, int N, int Kpad)
{
    __shared__ float t[32][33];
    int nb = blockIdx.x * 32, kb = blockIdx.y * 32;
    int tx = threadIdx.x, ty = threadIdx.y;
    #pragma unroll
    for (int i = 0; i < 32; i += 8) {
        int k = kb + ty + i, n = nb + tx;
        t[ty + i][tx] = (k < K && n < N) ? W[(size_t)k * N + n] : 0.f;
    }
    __syncthreads();
    #pragma unroll
    for (int i = 0; i < 32; i += 8) {
        int n = nb + ty + i, k = kb + tx;
        if (n < N && k < K)
            Th[(size_t)n * Kpad + k] = __float2half(t[tx][ty + i]);
    }
}

// ===================== Lorentz layernorm -> fp16 hi/lo =====================
__global__ __launch_bounds__(256)
void k_ln(const float* __restrict__ x, const float* __restrict__ g,
          const float* __restrict__ b, f16* __restrict__ oh, f16* __restrict__ ol)
{
    __shared__ float sbuf[32];
    int t = blockIdx.x, tid = threadIdx.x;
    const float* xs = x + (size_t)t * 1024 + 1;
    float sv[4]; float s1 = 0.f, s2 = 0.f;
    #pragma unroll
    for (int j = 0; j < 4; j++) {
        int i = tid + j * 256;
        sv[j] = 0.f;
        if (i < 1023) { sv[j] = xs[i]; s1 += sv[j]; s2 += sv[j] * sv[j]; }
    }
    s1 = blk_sum(s1, sbuf);
    s2 = blk_sum(s2, sbuf);
    float mu = s1 * (1.f / 1023.f);
    float var = s2 * (1.f / 1023.f) - mu * mu;
    float rstd = rsqrtf(var + 1e-5f);
    float q = 0.f;
    float yv[4];
    #pragma unroll
    for (int j = 0; j < 4; j++) {
        int i = tid + j * 256;
        yv[j] = 0.f;
        if (i < 1023) {
            yv[j] = (sv[j] - mu) * rstd * g[i] + b[i];
            q += yv[j] * yv[j];
        }
    }
    q = blk_sum(q, sbuf);
    size_t base = (size_t)t * 1024;
    #pragma unroll
    for (int j = 0; j < 4; j++) {
        int i = tid + j * 256;
        if (i < 1023) {
            f16 h, l; hsplit(yv[j], h, l);
            oh[base + 1 + i] = h; ol[base + 1 + i] = l;
        }
    }
    if (tid == 0) {
        f16 h, l; hsplit(sqrtf(q + 1.f), h, l);
        oh[base] = h; ol[base] = l;
    }
}

// ===================== lift heads (q/k) =====================
__global__ __launch_bounds__(512)
void k_lift(const float* __restrict__ S, bf16* __restrict__ Oh, bf16* __restrict__ Ol, float sign)
{
    int t = blockIdx.x;
    int b = t >> 10, n = t & 1023;
    int w = threadIdx.x >> 5, lane = threadIdx.x & 31;
    const float* src = S + (size_t)t * 1024 + w * 64;
    float v0 = src[lane], v1 = src[lane + 32];
    float ss = v0 * v0 + v1 * v1;
    #pragma unroll
    for (int o = 16; o > 0; o >>= 1) ss += __shfl_down_sync(0xffffffffu, ss, o);
    ss = __shfl_sync(0xffffffffu, ss, 0);
    size_t base = ((size_t)(b * HH + w) * 1024 + n) * QKLD;
    bf16 h, l;
    bsplit(v0, h, l); Oh[base + 1 + lane] = h; Ol[base + 1 + lane] = l;
    bsplit(v1, h, l); Oh[base + 33 + lane] = h; Ol[base + 33 + lane] = l;
    if (lane == 0) {
        bsplit(sign * sqrtf(ss + 1.f), h, l);
        Oh[base] = h; Ol[base] = l;
    }
    for (int i = 65 + lane; i < QKLD; i += 32) {
        Oh[base + i] = __float2bfloat16(0.f);
        Ol[base + i] = __float2bfloat16(0.f);
    }
}

// ===================== lift+transpose v =====================
__global__ void k_liftT(const float* __restrict__ vs, bf16* __restrict__ Th, bf16* __restrict__ Tl)
{
    int blk = blockIdx.x;
    int bh = blk >> 5;
    int tg = blk & 31;
    int b = bh >> 4, h = bh & 15;
    __shared__ float sv[32][65];
    __shared__ float stime[32];
    int tx = threadIdx.x, ty = threadIdx.y;
    #pragma unroll
    for (int i = 0; i < 32; i += 8) {
        int tok = i + ty;
        const float* src = vs + (size_t)(b * 1024 + tg * 32 + tok) * 1024 + h * 64;
        sv[tok][1 + tx] = src[tx];
        sv[tok][33 + tx] = src[tx + 32];
    }
    __syncthreads();
    if (ty == 0) {
        float s = 0.f;
        #pragma unroll
        for (int d = 1; d <= 64; d++) { float x = sv[tx][d]; s += x * x; }
        stime[tx] = sqrtf(s + 1.f);
    }
    __syncthreads();
    size_t base = (size_t)bh * (72 * 1024) + (size_t)(tg * 32);
    for (int d = ty; d < 72; d += 8) {
        float v = (d == 0) ? stime[tx] : (d < 65 ? sv[tx][d] : 0.f);
        bf16 hh, ll; bsplit(v, hh, ll);
        Th[base + (size_t)d * 1024 + tx] = hh;
        Tl[base + (size_t)d * 1024 + tx] = ll;
    }
}

// ===================== gelu + lift -> fp16 hi/lo =====================
__global__ __launch_bounds__(256)
void k_gelu(const float* __restrict__ fcpre, f16* __restrict__ fh, f16* __restrict__ fl)
{
    __shared__ float sbuf[32];
    int t = blockIdx.x, tid = threadIdx.x;
    const float* rin = fcpre + (size_t)t * 4095;
    float gv[16];
    float q = 0.f;
    #pragma unroll
    for (int j = 0; j < 16; j++) {
        int i = tid + j * 256;
        gv[j] = 0.f;
        if (i < 4095) {
            float x = rin[i];
            gv[j] = 0.5f * x * (1.f + erff(x * 0.70710678118654752f));
            q += gv[j] * gv[j];
        }
    }
    q = blk_sum(q, sbuf);
    size_t base = (size_t)t * 4096;
    #pragma unroll
    for (int j = 0; j < 16; j++) {
        int i = tid + j * 256;
        if (i < 4095) {
            f16 h, l; hsplit(gv[j], h, l);
            fh[base + 1 + i] = h; fl[base + 1 + i] = l;
        }
    }
    if (tid == 0) {
        f16 h, l; hsplit(sqrtf(q + 1.f), h, l);
        fh[base] = h; fl[base] = l;
    }
}

// ===================== Lorentz residual =====================
__global__ __launch_bounds__(256)
void k_lresnet(const float* __restrict__ xin, const float* __restrict__ spart,
               const float* __restrict__ wp, float* __restrict__ out)
{
    __shared__ float sbuf[32];
    int t = blockIdx.x, tid = threadIdx.x;
    float w = wp[0];
    const float* xr = xin + (size_t)t * 1024;
    const float* ar = spart + (size_t)t * 1023;
    float xs[4], as[4];
    float sa = 0.f;
    #pragma unroll
    for (int j = 0; j < 4; j++) {
        int i = tid + j * 256;
        xs[j] = 0.f; as[j] = 0.f;
        if (i < 1023) { xs[j] = xr[1 + i]; as[j] = ar[i]; sa += as[j] * as[j]; }
    }
    sa = blk_sum(sa, sbuf);
    float axt = sqrtf(sa + 1.f);
    float zt = xr[0] + w * axt;
    float sz = 0.f;
    #pragma unroll
    for (int j = 0; j < 4; j++) {
        int i = tid + j * 256;
        if (i < 1023) { xs[j] = xs[j] + w * as[j]; sz += xs[j] * xs[j]; }
    }
    sz = blk_sum(sz, sbuf);
    float inv = rsqrtf(fmaxf(zt * zt - sz, 1e-8f));
    if (tid == 0) out[(size_t)t * 1024] = zt * inv;
    #pragma unroll
    for (int j = 0; j < 4; j++) {
        int i = tid + j * 256;
        if (i < 1023) out[(size_t)t * 1024 + 1 + i] = xs[j] * inv;
    }
}

// ===================== host =====================
extern "C" void kernel_launch(void* const* d_in, const int* in_sizes, int n_in,
                              void* d_out, int out_size)
{
    const float* x   = (const float*)d_in[0];
    const float* g1  = (const float*)d_in[1];
    const float* b1  = (const float*)d_in[2];
    const float* Wq  = (const float*)d_in[3];
    const float* bq  = (const float*)d_in[4];
    const float* Wk  = (const float*)d_in[5];
    const float* bk  = (const float*)d_in[6];
    const float* Wv  = (const float*)d_in[7];
    const float* bv  = (const float*)d_in[8];
    const float* Wo  = (const float*)d_in[9];
    const float* bo  = (const float*)d_in[10];
    const float* g2  = (const float*)d_in[11];
    const float* b2  = (const float*)d_in[12];
    const float* Wfc = (const float*)d_in[13];
    const float* bfc = (const float*)d_in[14];
    const float* Wpj = (const float*)d_in[15];
    const float* bpj = (const float*)d_in[16];
    const float* w1  = (const float*)d_in[17];
    const float* w2  = (const float*)d_in[18];
    float* out = (float*)d_out;

    cudaFuncSetAttribute(mma_gemm<64>, cudaFuncAttributeMaxDynamicSharedMemorySize, SMEM_G64);
    cudaFuncSetAttribute(gemm2p<64>, cudaFuncAttributeMaxDynamicSharedMemorySize, SMEM_2P64);
    cudaFuncSetAttribute(flash_attn, cudaFuncAttributeMaxDynamicSharedMemorySize, FSM_TOTAL);

    #define SYM(p, s) do { void* _t; cudaGetSymbolAddress(&_t, s); p = decltype(p)(_t); } while (0)
    f16 *lxh, *lxl, *WqTh, *WkTh, *WvTh, *WfcTh, *WpjTh, *h1h, *h1l, *fch, *fcl;
    bf16 *WoTh, *WoTl, *qhh, *qhl, *khh, *khl, *vTh, *vTl, *cath, *catl;
    float *qs, *ks, *vs, *axs, *x1, *fcpre, *pjs;
    SYM(lxh, g_lxh); SYM(lxl, g_lxl);
    SYM(WqTh, g_WqTh); SYM(WkTh, g_WkTh); SYM(WvTh, g_WvTh);
    SYM(WoTh, g_WoTh); SYM(WoTl, g_WoTl);
    SYM(WfcTh, g_WfcTh); SYM(WpjTh, g_WpjTh);
    SYM(qs, g_qs); SYM(ks, g_ks); SYM(vs, g_vs);
    SYM(qhh, g_qhh); SYM(qhl, g_qhl); SYM(khh, g_khh); SYM(khl, g_khl);
    SYM(vTh, g_vTh); SYM(vTl, g_vTl);
    SYM(cath, g_cath); SYM(catl, g_catl);
    SYM(axs, g_axs); SYM(x1, g_x1); SYM(h1h, g_h1h); SYM(h1l, g_h1l);
    SYM(fcpre, g_fcpre); SYM(fch, g_fch); SYM(fcl, g_fcl); SYM(pjs, g_pjs);

    dim3 tb(32, 8);
    // launches 1-5 (launch 6 = gemm2p for ncu)
    k_tsplit_h<<<dim3(32, 32), tb>>>(Wq, WqTh, 1024, 1024, 1024);
    k_tsplit_h<<<dim3(32, 32), tb>>>(Wk, WkTh, 1024, 1024, 1024);
    k_tsplit_h<<<dim3(32, 32), tb>>>(Wv, WvTh, 1024, 1024, 1024);
    k_tsplit<<<dim3(32, 33), tb>>>(Wo, WoTh, WoTl, 1040, 1023, 1088);
    k_ln<<<TT, 256>>>(x, g1, b1, lxh, lxl);

    // QKV: fp16 2-pass
    {
        dim3 grid(8, 32, 1);
        gemm2p<64><<<grid, 256, SMEM_2P64>>>(lxh, lxl, WqTh, bq, qs, 1024, 1024, 1024, 1024, 1024);
        gemm2p<64><<<grid, 256, SMEM_2P64>>>(lxh, lxl, WkTh, bk, ks, 1024, 1024, 1024, 1024, 1024);
        gemm2p<64><<<grid, 256, SMEM_2P64>>>(lxh, lxl, WvTh, bv, vs, 1024, 1024, 1024, 1024, 1024);
    }

    // remaining weight transposes
    k_tsplit_h<<<dim3(128, 32), tb>>>(Wfc, WfcTh, 1024, 4095, 1024);
    k_tsplit_h<<<dim3(32, 128), tb>>>(Wpj, WpjTh, 4096, 1023, 4096);

    // lifts
    k_lift<<<TT, 512>>>(qs, qhh, qhl, -1.f);
    k_lift<<<TT, 512>>>(ks, khh, khl, 1.f);
    k_liftT<<<BHN * 32, tb>>>(vs, vTh, vTl);

    // fused flash attention -> cat
    flash_attn<<<dim3(8, BHN), 256, FSM_TOTAL>>>(qhh, qhl, khh, khl, vTh, vTl, cath, catl);

    // Wo: bf16 3-pass
    mma_gemm<64><<<dim3(8, 32, 1), 256, SMEM_G64>>>(cath, catl, WoTh, WoTl, bo, axs,
        1088, 1088, 1023, 0, 1023, 1088, 1.f, 0.f);

    // residual 1
    k_lresnet<<<TT, 256>>>(x, axs, w1, x1);

    // LN2
    k_ln<<<TT, 256>>>(x1, g2, b2, h1h, h1l);

    // Wfc: fp16 2-pass
    gemm2p<64><<<dim3(32, 32, 1), 256, SMEM_2P64>>>(h1h, h1l, WfcTh, bfc, fcpre,
        1024, 1024, 4095, 4095, 1024);

    // gelu + lift
    k_gelu<<<TT, 256>>>(fcpre, fch, fcl);

    // Wpj: fp16 2-pass
    gemm2p<64><<<dim3(8, 32, 1), 256, SMEM_2P64>>>(fch, fcl, WpjTh, bpj, pjs,
        4096, 4096, 1023, 1023, 4096);

    // residual 2
    k_lresnet<<<TT, 256>>>(x1, pjs, w2, out);
}

// round 8
// speedup vs baseline: 2.5931x; 1.1526x over previous
#include <cuda_runtime.h>
#include <cuda_bf16.h>
#include <cuda_fp16.h>
#include <math.h>
#include <stdint.h>

// Problem constants
#define BB 4
#define NNTOK 1024
#define DDIM 1024
#define HH 16
#define TT (BB*NNTOK)     // 4096 tokens
#define BHN (BB*HH)       // 64
#define QKLD 80           // padded lifted q/k leading dim (65 -> 80)

typedef __half f16;

// ===================== scratch (device globals) =====================
__device__ __align__(128) f16   g_lxh [TT*1024];
__device__ __align__(128) f16   g_lxl [TT*1024];
__device__ __align__(128) f16   g_WqTh[1024*1024];
__device__ __align__(128) f16   g_WkTh[1024*1024];
__device__ __align__(128) f16   g_WvTh[1024*1024];
__device__ __align__(128) f16   g_WoTh[1024*1088];
__device__ __align__(128) f16   g_WfcTh[4096*1024];
__device__ __align__(128) f16   g_WpjTh[1024*4096];
__device__ __align__(128) float g_qs  [TT*1024];
__device__ __align__(128) float g_ks  [TT*1024];
__device__ __align__(128) float g_vs  [TT*1024];
__device__ __align__(128) f16   g_qhh [(size_t)BHN*1024*QKLD];
__device__ __align__(128) f16   g_qhl [(size_t)BHN*1024*QKLD];
__device__ __align__(128) f16   g_khh [(size_t)BHN*1024*QKLD];
__device__ __align__(128) f16   g_vTh [(size_t)BHN*72*1024];
__device__ __align__(128) f16   g_cath[TT*1088];
__device__ __align__(128) f16   g_catl[TT*1088];
__device__ __align__(128) float g_axs [TT*1023];
__device__ __align__(128) float g_x1  [TT*1024];
__device__ __align__(128) f16   g_h1h [TT*1024];
__device__ __align__(128) f16   g_h1l [TT*1024];
__device__ __align__(128) float g_fcpre[(size_t)TT*4095];
__device__ __align__(128) f16   g_fch [(size_t)TT*4096];
__device__ __align__(128) f16   g_fcl [(size_t)TT*4096];
__device__ __align__(128) float g_pjs [TT*1023];

// ===================== PTX helpers =====================
__device__ __forceinline__ uint32_t smem_u32(const void* p) {
    uint32_t a;
    asm("{ .reg .u64 t; cvta.to.shared.u64 t, %1; cvt.u32.u64 %0, t; }" : "=r"(a) : "l"(p));
    return a;
}

#define CP_ASYNC16(dst, src) \
    asm volatile("cp.async.cg.shared.global [%0], [%1], 16;" :: "r"(dst), "l"(src))
#define CP_COMMIT() asm volatile("cp.async.commit_group;")
#define CP_WAIT1()  asm volatile("cp.async.wait_group 1;")
#define CP_WAIT0()  asm volatile("cp.async.wait_group 0;")

__device__ __forceinline__ void mma16816h(float* c, const uint32_t* a, const uint32_t* b) {
    asm volatile(
        "mma.sync.aligned.m16n8k16.row.col.f32.f16.f16.f32 "
        "{%0,%1,%2,%3}, {%4,%5,%6,%7}, {%8,%9}, {%0,%1,%2,%3};"
        : "+f"(c[0]), "+f"(c[1]), "+f"(c[2]), "+f"(c[3])
        : "r"(a[0]), "r"(a[1]), "r"(a[2]), "r"(a[3]), "r"(b[0]), "r"(b[1]));
}

__device__ __forceinline__ void hsplit(float v, f16& h, f16& l) {
    h = __float2half(v);
    l = __float2half(v - __half2float(h));
}

__device__ __forceinline__ uint32_t pack_hi2h(float a, float b) {
    __half2 r = __floats2half2_rn(a, b);
    return *(uint32_t*)&r;
}
__device__ __forceinline__ uint32_t pack_lo2h(float a, float b) {
    float ra = a - __half2float(__float2half(a));
    float rb = b - __half2float(__float2half(b));
    __half2 r = __floats2half2_rn(ra, rb);
    return *(uint32_t*)&r;
}

// ===================== block reductions =====================
__device__ __forceinline__ float blk_sum(float v, float* sbuf) {
    int tid = threadIdx.x;
    #pragma unroll
    for (int o = 16; o > 0; o >>= 1) v += __shfl_down_sync(0xffffffffu, v, o);
    if ((tid & 31) == 0) sbuf[tid >> 5] = v;
    __syncthreads();
    if (tid < 32) {
        int nw = (blockDim.x + 31) >> 5;
        float x = (tid < nw) ? sbuf[tid] : 0.f;
        #pragma unroll
        for (int o = 16; o > 0; o >>= 1) x += __shfl_down_sync(0xffffffffu, x, o);
        if (tid == 0) sbuf[0] = x;
    }
    __syncthreads();
    float r = sbuf[0];
    __syncthreads();
    return r;
}

// ===================== fp16 2-pass GEMM (A exact via hi/lo, B fp16-rounded) =====================
template<int KC>
__global__ __launch_bounds__(256)
void gemm2p(const f16* __restrict__ Ah, const f16* __restrict__ Al,
            const f16* __restrict__ Bh,
            const float* __restrict__ bias, float* __restrict__ C,
            int lda, int ldb, int ldc, int Nreal, int K)
{
    constexpr int ROWB = 2 * KC + 16;
    constexpr int STG_MAT = 128 * ROWB;
    constexpr int STG_SZ = 3 * STG_MAT;
    constexpr int CPR = KC / 8;
    constexpr int LPT = 3 * KC / 16;

    extern __shared__ char smem[];
    int tid = threadIdx.x, w = tid >> 5, lane = tid & 31;
    int m0 = blockIdx.y * 128, n0 = blockIdx.x * 128;
    const int NC = K / KC;

    auto load_stage = [&](int kofs, int s) {
        char* stg = smem + s * STG_SZ;
        #pragma unroll
        for (int i = 0; i < LPT; i++) {
            int idx = tid + i * 256;
            int mat = idx / (16 * KC);            // 0:Ah 1:Al 2:Bh
            int cc  = idx % (16 * KC);
            int row = cc / CPR, kc = cc % CPR;
            uint32_t dst = smem_u32(stg + mat * STG_MAT + row * ROWB + kc * 16);
            const f16* p = (mat == 0) ? Ah : (mat == 1) ? Al : Bh;
            int b0 = (mat < 2) ? m0 : n0;
            int ld = (mat < 2) ? lda : ldb;
            CP_ASYNC16(dst, p + (size_t)(b0 + row) * ld + kofs + kc * 8);
        }
        CP_COMMIT();
    };

    load_stage(0, 0);
    if (NC > 1) load_stage(KC, 1);

    int g = lane >> 2, t = lane & 3;
    int wm = (w & 3) * 32, wn = (w >> 2) * 64;

    float acc[2][8][4];
    #pragma unroll
    for (int mt = 0; mt < 2; mt++)
        #pragma unroll
        for (int nt = 0; nt < 8; nt++)
            #pragma unroll
            for (int r = 0; r < 4; r++) acc[mt][nt][r] = 0.f;

    for (int kc = 0; kc < NC; kc++) {
        if (kc + 1 < NC) { CP_WAIT1(); } else { CP_WAIT0(); }
        __syncthreads();
        const char* stg = smem + (kc & 1) * STG_SZ;
        const char* pAh = stg;
        const char* pAl = stg + STG_MAT;
        const char* pBh = stg + 2 * STG_MAT;

        #pragma unroll
        for (int ko = 0; ko < KC; ko += 16) {
            uint32_t aH[2][4], aL[2][4], b[8][2];
            #pragma unroll
            for (int mt = 0; mt < 2; mt++) {
                int r0 = (wm + mt * 16 + g) * ROWB + (ko + t * 2) * 2;
                aH[mt][0] = *(const uint32_t*)(pAh + r0);
                aH[mt][1] = *(const uint32_t*)(pAh + r0 + 8 * ROWB);
                aH[mt][2] = *(const uint32_t*)(pAh + r0 + 16);
                aH[mt][3] = *(const uint32_t*)(pAh + r0 + 8 * ROWB + 16);
                aL[mt][0] = *(const uint32_t*)(pAl + r0);
                aL[mt][1] = *(const uint32_t*)(pAl + r0 + 8 * ROWB);
                aL[mt][2] = *(const uint32_t*)(pAl + r0 + 16);
                aL[mt][3] = *(const uint32_t*)(pAl + r0 + 8 * ROWB + 16);
            }
            #pragma unroll
            for (int nt = 0; nt < 8; nt++) {
                int r0 = (wn + nt * 8 + g) * ROWB + (ko + t * 2) * 2;
                b[nt][0] = *(const uint32_t*)(pBh + r0);
                b[nt][1] = *(const uint32_t*)(pBh + r0 + 16);
            }
            #pragma unroll
            for (int mt = 0; mt < 2; mt++)
                #pragma unroll
                for (int nt = 0; nt < 8; nt++) {
                    mma16816h(acc[mt][nt], aH[mt], b[nt]);
                    mma16816h(acc[mt][nt], aL[mt], b[nt]);
                }
        }
        __syncthreads();
        if (kc + 2 < NC) load_stage((kc + 2) * KC, kc & 1);
    }

    #pragma unroll
    for (int mt = 0; mt < 2; mt++) {
        int r0 = m0 + wm + mt * 16 + g;
        float* c0p = C + (size_t)r0 * ldc;
        float* c1p = C + (size_t)(r0 + 8) * ldc;
        #pragma unroll
        for (int nt = 0; nt < 8; nt++) {
            int n = n0 + wn + nt * 8 + t * 2;
            if (n < Nreal) {
                float bv = bias ? bias[n] : 0.f;
                c0p[n] = acc[mt][nt][0] + bv;
                c1p[n] = acc[mt][nt][2] + bv;
            }
            if (n + 1 < Nreal) {
                float bv = bias ? bias[n + 1] : 0.f;
                c0p[n + 1] = acc[mt][nt][1] + bv;
                c1p[n + 1] = acc[mt][nt][3] + bv;
            }
        }
    }
}

#define SMEM_2P64 (2 * 3 * 128 * 144)  // 110592

// ===================== fused flash attention (fp16 2-pass) =====================
// Q exact (hi/lo fp16), K/V fp16-rounded (single matrix each), P exact (hi/lo).
#define FQ_ROWB 176
#define FV_ROWB 144
#define FSM_QMAT (128*FQ_ROWB)                 // 22528
#define FSM_K0   (2*FSM_QMAT)                  // 45056
#define FSM_KSTG (64*FQ_ROWB)                  // 11264
#define FSM_V0   (FSM_K0 + 2*FSM_KSTG)         // 67584
#define FSM_VSTG (72*FV_ROWB)                  // 10368
#define FSM_TOTAL (FSM_V0 + 2*FSM_VSTG)        // 88320

__global__ __launch_bounds__(256)
void flash_attn(const f16* __restrict__ qhh, const f16* __restrict__ qhl,
                const f16* __restrict__ khh,
                const f16* __restrict__ vth,
                f16* __restrict__ cath, f16* __restrict__ catl)
{
    extern __shared__ char smem[];
    int tid = threadIdx.x, w = tid >> 5, lane = tid & 31;
    int g = lane >> 2, t = lane & 3;
    int bh = blockIdx.y;
    int q0 = blockIdx.x * 128;

    // load Q tile (hi+lo)
    {
        #pragma unroll
        for (int i = 0; i < 10; i++) {
            int idx = tid + i * 256;           // 0..2559
            int mat = idx / 1280;
            int cc = idx % 1280;
            int row = cc / 10, ch = cc % 10;
            const f16* src = (mat ? qhl : qhh) +
                ((size_t)bh * 1024 + q0 + row) * QKLD + ch * 8;
            uint32_t dst = smem_u32(smem + mat * FSM_QMAT + row * FQ_ROWB + ch * 16);
            CP_ASYNC16(dst, src);
        }
        CP_COMMIT();
    }

    auto load_kv = [&](int kt, int s) {
        char* kb = smem + FSM_K0 + s * FSM_KSTG;
        char* vb = smem + FSM_V0 + s * FSM_VSTG;
        #pragma unroll
        for (int i = 0; i < 5; i++) {
            int idx = tid + i * 256;           // K: 0..639, V: 640..1215
            if (idx < 640) {
                int row = idx / 10, ch = idx % 10;
                const f16* src = khh + ((size_t)bh * 1024 + kt * 64 + row) * QKLD + ch * 8;
                uint32_t dst = smem_u32(kb + row * FQ_ROWB + ch * 16);
                CP_ASYNC16(dst, src);
            } else if (idx < 1216) {
                int cc = idx - 640;
                int row = cc / 8, ch = cc % 8;
                const f16* src = vth + ((size_t)bh * 72 + row) * 1024 + kt * 64 + ch * 8;
                uint32_t dst = smem_u32(vb + row * FV_ROWB + ch * 16);
                CP_ASYNC16(dst, src);
            }
        }
        CP_COMMIT();
    };

    load_kv(0, 0);

    float O[9][4];
    #pragma unroll
    for (int nv = 0; nv < 9; nv++)
        #pragma unroll
        for (int r = 0; r < 4; r++) O[nv][r] = 0.f;
    float m0 = -INFINITY, m1 = -INFINITY, l0 = 0.f, l1 = 0.f;

    for (int kt = 0; kt < 16; kt++) {
        if (kt + 1 < 16) { load_kv(kt + 1, (kt + 1) & 1); CP_WAIT1(); }
        else { CP_WAIT0(); }
        __syncthreads();
        const char* pK = smem + FSM_K0 + (kt & 1) * FSM_KSTG;
        const char* pV = smem + FSM_V0 + (kt & 1) * FSM_VSTG;

        // S = Q K^T (2-pass: Qh*K + Ql*K)
        float S[8][4];
        #pragma unroll
        for (int nt = 0; nt < 8; nt++)
            #pragma unroll
            for (int r = 0; r < 4; r++) S[nt][r] = 0.f;

        #pragma unroll
        for (int kk = 0; kk < 5; kk++) {
            uint32_t aH[4], aL[4], b[2];
            int r0 = (w * 16 + g) * FQ_ROWB + (kk * 16 + t * 2) * 2;
            aH[0] = *(const uint32_t*)(smem + r0);
            aH[1] = *(const uint32_t*)(smem + r0 + 8 * FQ_ROWB);
            aH[2] = *(const uint32_t*)(smem + r0 + 16);
            aH[3] = *(const uint32_t*)(smem + r0 + 8 * FQ_ROWB + 16);
            aL[0] = *(const uint32_t*)(smem + FSM_QMAT + r0);
            aL[1] = *(const uint32_t*)(smem + FSM_QMAT + r0 + 8 * FQ_ROWB);
            aL[2] = *(const uint32_t*)(smem + FSM_QMAT + r0 + 16);
            aL[3] = *(const uint32_t*)(smem + FSM_QMAT + r0 + 8 * FQ_ROWB + 16);
            #pragma unroll
            for (int nt = 0; nt < 8; nt++) {
                int rb = (nt * 8 + g) * FQ_ROWB + (kk * 16 + t * 2) * 2;
                b[0] = *(const uint32_t*)(pK + rb);
                b[1] = *(const uint32_t*)(pK + rb + 16);
                mma16816h(S[nt], aH, b);
                mma16816h(S[nt], aL, b);
            }
        }

        #pragma unroll
        for (int nt = 0; nt < 8; nt++)
            #pragma unroll
            for (int r = 0; r < 4; r++) S[nt][r] *= 0.25f;

        float lm0 = -INFINITY, lm1 = -INFINITY;
        #pragma unroll
        for (int nt = 0; nt < 8; nt++) {
            lm0 = fmaxf(lm0, fmaxf(S[nt][0], S[nt][1]));
            lm1 = fmaxf(lm1, fmaxf(S[nt][2], S[nt][3]));
        }
        lm0 = fmaxf(lm0, __shfl_xor_sync(0xffffffffu, lm0, 1));
        lm0 = fmaxf(lm0, __shfl_xor_sync(0xffffffffu, lm0, 2));
        lm1 = fmaxf(lm1, __shfl_xor_sync(0xffffffffu, lm1, 1));
        lm1 = fmaxf(lm1, __shfl_xor_sync(0xffffffffu, lm1, 2));
        float mn0 = fmaxf(m0, lm0), mn1 = fmaxf(m1, lm1);
        float sc0 = __expf(m0 - mn0), sc1 = __expf(m1 - mn1);
        m0 = mn0; m1 = mn1;
        l0 *= sc0; l1 *= sc1;
        #pragma unroll
        for (int nv = 0; nv < 9; nv++) {
            O[nv][0] *= sc0; O[nv][1] *= sc0;
            O[nv][2] *= sc1; O[nv][3] *= sc1;
        }
        #pragma unroll
        for (int nt = 0; nt < 8; nt++) {
            S[nt][0] = __expf(S[nt][0] - mn0);
            S[nt][1] = __expf(S[nt][1] - mn0);
            S[nt][2] = __expf(S[nt][2] - mn1);
            S[nt][3] = __expf(S[nt][3] - mn1);
            l0 += S[nt][0] + S[nt][1];
            l1 += S[nt][2] + S[nt][3];
        }

        // PV: O += P V (2-pass: Ph*V + Pl*V)
        #pragma unroll
        for (int ks = 0; ks < 4; ks++) {
            uint32_t pH[4], pL[4], b[2];
            pH[0] = pack_hi2h(S[2 * ks][0], S[2 * ks][1]);
            pH[1] = pack_hi2h(S[2 * ks][2], S[2 * ks][3]);
            pH[2] = pack_hi2h(S[2 * ks + 1][0], S[2 * ks + 1][1]);
            pH[3] = pack_hi2h(S[2 * ks + 1][2], S[2 * ks + 1][3]);
            pL[0] = pack_lo2h(S[2 * ks][0], S[2 * ks][1]);
            pL[1] = pack_lo2h(S[2 * ks][2], S[2 * ks][3]);
            pL[2] = pack_lo2h(S[2 * ks + 1][0], S[2 * ks + 1][1]);
            pL[3] = pack_lo2h(S[2 * ks + 1][2], S[2 * ks + 1][3]);
            #pragma unroll
            for (int nv = 0; nv < 9; nv++) {
                int rb = (nv * 8 + g) * FV_ROWB + (ks * 16 + t * 2) * 2;
                b[0] = *(const uint32_t*)(pV + rb);
                b[1] = *(const uint32_t*)(pV + rb + 16);
                mma16816h(O[nv], pH, b);
                mma16816h(O[nv], pL, b);
            }
        }
        __syncthreads();
    }

    // epilogue: normalize + Lorentz + write cat
    l0 += __shfl_xor_sync(0xffffffffu, l0, 1);
    l0 += __shfl_xor_sync(0xffffffffu, l0, 2);
    l1 += __shfl_xor_sync(0xffffffffu, l1, 1);
    l1 += __shfl_xor_sync(0xffffffffu, l1, 2);
    float r0 = 1.f / l0, r1 = 1.f / l1;
    #pragma unroll
    for (int nv = 0; nv < 9; nv++) {
        O[nv][0] *= r0; O[nv][1] *= r0;
        O[nv][2] *= r1; O[nv][3] *= r1;
    }
    float t0 = __shfl_sync(0xffffffffu, O[0][0], lane & ~3);
    float t1 = __shfl_sync(0xffffffffu, O[0][2], lane & ~3);
    float ss0 = 0.f, ss1 = 0.f;
    #pragma unroll
    for (int nv = 0; nv < 9; nv++) {
        int c = nv * 8 + 2 * t;
        if (c >= 1 && c < 65) { ss0 += O[nv][0] * O[nv][0]; ss1 += O[nv][2] * O[nv][2]; }
        if (c + 1 >= 1 && c + 1 < 65) { ss0 += O[nv][1] * O[nv][1]; ss1 += O[nv][3] * O[nv][3]; }
    }
    ss0 += __shfl_xor_sync(0xffffffffu, ss0, 1);
    ss0 += __shfl_xor_sync(0xffffffffu, ss0, 2);
    ss1 += __shfl_xor_sync(0xffffffffu, ss1, 1);
    ss1 += __shfl_xor_sync(0xffffffffu, ss1, 2);
    float inv0 = rsqrtf(fmaxf(t0 * t0 - ss0, 1e-8f));
    float inv1 = rsqrtf(fmaxf(t1 * t1 - ss1, 1e-8f));

    int b = bh >> 4, h = bh & 15;
    int tr0 = b * 1024 + q0 + w * 16 + g;
    size_t base0 = (size_t)tr0 * 1088 + h * 65;
    size_t base1 = (size_t)(tr0 + 8) * 1088 + h * 65;
    #pragma unroll
    for (int nv = 0; nv < 9; nv++) {
        int c = nv * 8 + 2 * t;
        if (c < 65) {
            f16 hh, ll;
            hsplit(O[nv][0] * inv0, hh, ll); cath[base0 + c] = hh; catl[base0 + c] = ll;
            hsplit(O[nv][2] * inv1, hh, ll); cath[base1 + c] = hh; catl[base1 + c] = ll;
        }
        if (c + 1 < 65) {
            f16 hh, ll;
            hsplit(O[nv][1] * inv0, hh, ll); cath[base0 + c + 1] = hh; catl[base0 + c + 1] = ll;
            hsplit(O[nv][3] * inv1, hh, ll); cath[base1 + c + 1] = hh; catl[base1 + c + 1] = ll;
        }
    }
}

// ===================== weight transpose -> fp16 =====================
__global__ void k_tsplit_h(const float* __restrict__ W, f16* __restrict__ Th,
                           int K, int N, int Kpad)
{
    __shared__ float t[32][33];
    int nb = blockIdx.x * 32, kb = blockIdx.y * 32;
    int tx = threadIdx.x, ty = threadIdx.y;
    #pragma unroll
    for (int i = 0; i < 32; i += 8) {
        int k = kb + ty + i, n = nb + tx;
        t[ty + i][tx] = (k < K && n < N) ? W[(size_t)k * N + n] : 0.f;
    }
    __syncthreads();
    #pragma unroll
    for (int i = 0; i < 32; i += 8) {
        int n = nb + ty + i, k = kb + tx;
        if (n < N && k < K)
            Th[(size_t)n * Kpad + k] = __float2half(t[tx][ty + i]);
    }
}

// ===================== Lorentz layernorm -> fp16 hi/lo =====================
__global__ __launch_bounds__(256)
void k_ln(const float* __restrict__ x, const float* __restrict__ g,
          const float* __restrict__ b, f16* __restrict__ oh, f16* __restrict__ ol)
{
    __shared__ float sbuf[32];
    int t = blockIdx.x, tid = threadIdx.x;
    const float* xs = x + (size_t)t * 1024 + 1;
    float sv[4]; float s1 = 0.f, s2 = 0.f;
    #pragma unroll
    for (int j = 0; j < 4; j++) {
        int i = tid + j * 256;
        sv[j] = 0.f;
        if (i < 1023) { sv[j] = xs[i]; s1 += sv[j]; s2 += sv[j] * sv[j]; }
    }
    s1 = blk_sum(s1, sbuf);
    s2 = blk_sum(s2, sbuf);
    float mu = s1 * (1.f / 1023.f);
    float var = s2 * (1.f / 1023.f) - mu * mu;
    float rstd = rsqrtf(var + 1e-5f);
    float q = 0.f;
    float yv[4];
    #pragma unroll
    for (int j = 0; j < 4; j++) {
        int i = tid + j * 256;
        yv[j] = 0.f;
        if (i < 1023) {
            yv[j] = (sv[j] - mu) * rstd * g[i] + b[i];
            q += yv[j] * yv[j];
        }
    }
    q = blk_sum(q, sbuf);
    size_t base = (size_t)t * 1024;
    #pragma unroll
    for (int j = 0; j < 4; j++) {
        int i = tid + j * 256;
        if (i < 1023) {
            f16 h, l; hsplit(yv[j], h, l);
            oh[base + 1 + i] = h; ol[base + 1 + i] = l;
        }
    }
    if (tid == 0) {
        f16 h, l; hsplit(sqrtf(q + 1.f), h, l);
        oh[base] = h; ol[base] = l;
    }
}

// ===================== lift heads: Q (hi/lo, sign -1) or K (hi only, sign +1) =====================
__global__ __launch_bounds__(512)
void k_lift(const float* __restrict__ S, f16* __restrict__ Oh, f16* __restrict__ Ol, float sign)
{
    int t = blockIdx.x;
    int b = t >> 10, n = t & 1023;
    int w = threadIdx.x >> 5, lane = threadIdx.x & 31;
    const float* src = S + (size_t)t * 1024 + w * 64;
    float v0 = src[lane], v1 = src[lane + 32];
    float ss = v0 * v0 + v1 * v1;
    #pragma unroll
    for (int o = 16; o > 0; o >>= 1) ss += __shfl_down_sync(0xffffffffu, ss, o);
    ss = __shfl_sync(0xffffffffu, ss, 0);
    size_t base = ((size_t)(b * HH + w) * 1024 + n) * QKLD;
    f16 h, l;
    hsplit(v0, h, l); Oh[base + 1 + lane] = h; if (Ol) Ol[base + 1 + lane] = l;
    hsplit(v1, h, l); Oh[base + 33 + lane] = h; if (Ol) Ol[base + 33 + lane] = l;
    if (lane == 0) {
        hsplit(sign * sqrtf(ss + 1.f), h, l);
        Oh[base] = h; if (Ol) Ol[base] = l;
    }
    for (int i = 65 + lane; i < QKLD; i += 32) {
        Oh[base + i] = __float2half(0.f);
        if (Ol) Ol[base + i] = __float2half(0.f);
    }
}

// ===================== lift+transpose v -> fp16 (BH,72,1024) =====================
__global__ void k_liftT(const float* __restrict__ vs, f16* __restrict__ Th)
{
    int blk = blockIdx.x;
    int bh = blk >> 5;
    int tg = blk & 31;
    int b = bh >> 4, h = bh & 15;
    __shared__ float sv[32][65];
    __shared__ float stime[32];
    int tx = threadIdx.x, ty = threadIdx.y;
    #pragma unroll
    for (int i = 0; i < 32; i += 8) {
        int tok = i + ty;
        const float* src = vs + (size_t)(b * 1024 + tg * 32 + tok) * 1024 + h * 64;
        sv[tok][1 + tx] = src[tx];
        sv[tok][33 + tx] = src[tx + 32];
    }
    __syncthreads();
    if (ty == 0) {
        float s = 0.f;
        #pragma unroll
        for (int d = 1; d <= 64; d++) { float x = sv[tx][d]; s += x * x; }
        stime[tx] = sqrtf(s + 1.f);
    }
    __syncthreads();
    size_t base = (size_t)bh * (72 * 1024) + (size_t)(tg * 32);
    for (int d = ty; d < 72; d += 8) {
        float v = (d == 0) ? stime[tx] : (d < 65 ? sv[tx][d] : 0.f);
        Th[base + (size_t)d * 1024 + tx] = __float2half(v);
    }
}

// ===================== gelu + lift -> fp16 hi/lo =====================
__global__ __launch_bounds__(256)
void k_gelu(const float* __restrict__ fcpre, f16* __restrict__ fh, f16* __restrict__ fl)
{
    __shared__ float sbuf[32];
    int t = blockIdx.x, tid = threadIdx.x;
    const float* rin = fcpre + (size_t)t * 4095;
    float gv[16];
    float q = 0.f;
    #pragma unroll
    for (int j = 0; j < 16; j++) {
        int i = tid + j * 256;
        gv[j] = 0.f;
        if (i < 4095) {
            float x = rin[i];
            gv[j] = 0.5f * x * (1.f + erff(x * 0.70710678118654752f));
            q += gv[j] * gv[j];
        }
    }
    q = blk_sum(q, sbuf);
    size_t base = (size_t)t * 4096;
    #pragma unroll
    for (int j = 0; j < 16; j++) {
        int i = tid + j * 256;
        if (i < 4095) {
            f16 h, l; hsplit(gv[j], h, l);
            fh[base + 1 + i] = h; fl[base + 1 + i] = l;
        }
    }
    if (tid == 0) {
        f16 h, l; hsplit(sqrtf(q + 1.f), h, l);
        fh[base] = h; fl[base] = l;
    }
}

// ===================== Lorentz residual =====================
__global__ __launch_bounds__(256)
void k_lresnet(const float* __restrict__ xin, const float* __restrict__ spart,
               const float* __restrict__ wp, float* __restrict__ out)
{
    __shared__ float sbuf[32];
    int t = blockIdx.x, tid = threadIdx.x;
    float w = wp[0];
    const float* xr = xin + (size_t)t * 1024;
    const float* ar = spart + (size_t)t * 1023;
    float xs[4], as[4];
    float sa = 0.f;
    #pragma unroll
    for (int j = 0; j < 4; j++) {
        int i = tid + j * 256;
        xs[j] = 0.f; as[j] = 0.f;
        if (i < 1023) { xs[j] = xr[1 + i]; as[j] = ar[i]; sa += as[j] * as[j]; }
    }
    sa = blk_sum(sa, sbuf);
    float axt = sqrtf(sa + 1.f);
    float zt = xr[0] + w * axt;
    float sz = 0.f;
    #pragma unroll
    for (int j = 0; j < 4; j++) {
        int i = tid + j * 256;
        if (i < 1023) { xs[j] = xs[j] + w * as[j]; sz += xs[j] * xs[j]; }
    }
    sz = blk_sum(sz, sbuf);
    float inv = rsqrtf(fmaxf(zt * zt - sz, 1e-8f));
    if (tid == 0) out[(size_t)t * 1024] = zt * inv;
    #pragma unroll
    for (int j = 0; j < 4; j++) {
        int i = tid + j * 256;
        if (i < 1023) out[(size_t)t * 1024 + 1 + i] = xs[j] * inv;
    }
}

// ===================== host =====================
extern "C" void kernel_launch(void* const* d_in, const int* in_sizes, int n_in,
                              void* d_out, int out_size)
{
    const float* x   = (const float*)d_in[0];
    const float* g1  = (const float*)d_in[1];
    const float* b1  = (const float*)d_in[2];
    const float* Wq  = (const float*)d_in[3];
    const float* bq  = (const float*)d_in[4];
    const float* Wk  = (const float*)d_in[5];
    const float* bk  = (const float*)d_in[6];
    const float* Wv  = (const float*)d_in[7];
    const float* bv  = (const float*)d_in[8];
    const float* Wo  = (const float*)d_in[9];
    const float* bo  = (const float*)d_in[10];
    const float* g2  = (const float*)d_in[11];
    const float* b2  = (const float*)d_in[12];
    const float* Wfc = (const float*)d_in[13];
    const float* bfc = (const float*)d_in[14];
    const float* Wpj = (const float*)d_in[15];
    const float* bpj = (const float*)d_in[16];
    const float* w1  = (const float*)d_in[17];
    const float* w2  = (const float*)d_in[18];
    float* out = (float*)d_out;

    cudaFuncSetAttribute(gemm2p<64>, cudaFuncAttributeMaxDynamicSharedMemorySize, SMEM_2P64);
    cudaFuncSetAttribute(flash_attn, cudaFuncAttributeMaxDynamicSharedMemorySize, FSM_TOTAL);

    #define SYM(p, s) do { void* _t; cudaGetSymbolAddress(&_t, s); p = decltype(p)(_t); } while (0)
    f16 *lxh, *lxl, *WqTh, *WkTh, *WvTh, *WoTh, *WfcTh, *WpjTh;
    f16 *qhh, *qhl, *khh, *vTh, *cath, *catl, *h1h, *h1l, *fch, *fcl;
    float *qs, *ks, *vs, *axs, *x1, *fcpre, *pjs;
    SYM(lxh, g_lxh); SYM(lxl, g_lxl);
    SYM(WqTh, g_WqTh); SYM(WkTh, g_WkTh); SYM(WvTh, g_WvTh);
    SYM(WoTh, g_WoTh);
    SYM(WfcTh, g_WfcTh); SYM(WpjTh, g_WpjTh);
    SYM(qs, g_qs); SYM(ks, g_ks); SYM(vs, g_vs);
    SYM(qhh, g_qhh); SYM(qhl, g_qhl); SYM(khh, g_khh);
    SYM(vTh, g_vTh);
    SYM(cath, g_cath); SYM(catl, g_catl);
    SYM(axs, g_axs); SYM(x1, g_x1); SYM(h1h, g_h1h); SYM(h1l, g_h1l);
    SYM(fcpre, g_fcpre); SYM(fch, g_fch); SYM(fcl, g_fcl); SYM(pjs, g_pjs);

    dim3 tb(32, 8);
    k_tsplit_h<<<dim3(32, 32), tb>>>(Wq, WqTh, 1024, 1024, 1024);
    k_tsplit_h<<<dim3(32, 32), tb>>>(Wk, WkTh, 1024, 1024, 1024);
    k_tsplit_h<<<dim3(32, 32), tb>>>(Wv, WvTh, 1024, 1024, 1024);
    k_tsplit_h<<<dim3(32, 33), tb>>>(Wo, WoTh, 1040, 1023, 1088);
    k_ln<<<TT, 256>>>(x, g1, b1, lxh, lxl);

    // QKV: fp16 2-pass
    {
        dim3 grid(8, 32, 1);
        gemm2p<64><<<grid, 256, SMEM_2P64>>>(lxh, lxl, WqTh, bq, qs, 1024, 1024, 1024, 1024, 1024);
        gemm2p<64><<<grid, 256, SMEM_2P64>>>(lxh, lxl, WkTh, bk, ks, 1024, 1024, 1024, 1024, 1024);
        gemm2p<64><<<grid, 256, SMEM_2P64>>>(lxh, lxl, WvTh, bv, vs, 1024, 1024, 1024, 1024, 1024);
    }

    // remaining weight transposes
    k_tsplit_h<<<dim3(128, 32), tb>>>(Wfc, WfcTh, 1024, 4095, 1024);
    k_tsplit_h<<<dim3(32, 128), tb>>>(Wpj, WpjTh, 4096, 1023, 4096);

    // lifts
    k_lift<<<TT, 512>>>(qs, qhh, qhl, -1.f);
    k_lift<<<TT, 512>>>(ks, khh, nullptr, 1.f);
    k_liftT<<<BHN * 32, tb>>>(vs, vTh);

    // fused flash attention -> cat
    flash_attn<<<dim3(8, BHN), 256, FSM_TOTAL>>>(qhh, qhl, khh, vTh, cath, catl);

    // Wo: fp16 2-pass
    gemm2p<64><<<dim3(8, 32, 1), 256, SMEM_2P64>>>(cath, catl, WoTh, bo, axs,
        1088, 1088, 1023, 1023, 1088);

    // residual 1
    k_lresnet<<<TT, 256>>>(x, axs, w1, x1);

    // LN2
    k_ln<<<TT, 256>>>(x1, g2, b2, h1h, h1l);

    // Wfc: fp16 2-pass
    gemm2p<64><<<dim3(32, 32, 1), 256, SMEM_2P64>>>(h1h, h1l, WfcTh, bfc, fcpre,
        1024, 1024, 4095, 4095, 1024);

    // gelu + lift
    k_gelu<<<TT, 256>>>(fcpre, fch, fcl);

    // Wpj: fp16 2-pass
    gemm2p<64><<<dim3(8, 32, 1), 256, SMEM_2P64>>>(fch, fcl, WpjTh, bpj, pjs,
        4096, 4096, 1023, 1023, 4096);

    // residual 2
    k_lresnet<<<TT, 256>>>(x1, pjs, w2, out);
}

// round 10
// speedup vs baseline: 3.8989x; 1.5036x over previous
#include <cuda_runtime.h>
#include <cuda_bf16.h>
#include <cuda_fp16.h>
#include <math.h>
#include <stdint.h>

// Problem constants
#define BB 4
#define NNTOK 1024
#define DDIM 1024
#define HH 16
#define TT (BB*NNTOK)     // 4096 tokens
#define BHN (BB*HH)       // 64
#define QKLD 80           // padded lifted q/k leading dim (65 -> 80)

typedef __half f16;

// ===================== scratch (device globals) =====================
__device__ __align__(128) f16   g_lxh [TT*1024];
__device__ __align__(128) f16   g_WqTh[1024*1024];
__device__ __align__(128) f16   g_WkTh[1024*1024];
__device__ __align__(128) f16   g_WvTh[1024*1024];
__device__ __align__(128) f16   g_WoTh[1024*1088];
__device__ __align__(128) f16   g_WfcTh[4096*1024];
__device__ __align__(128) f16   g_WpjTh[1024*4096];
__device__ __align__(128) float g_qs  [TT*1024];
__device__ __align__(128) float g_ks  [TT*1024];
__device__ __align__(128) float g_vs  [TT*1024];
__device__ __align__(128) f16   g_qhh [(size_t)BHN*1024*QKLD];
__device__ __align__(128) f16   g_qhl [(size_t)BHN*1024*QKLD];
__device__ __align__(128) f16   g_khh [(size_t)BHN*1024*QKLD];
__device__ __align__(128) f16   g_vTh [(size_t)BHN*72*1024];
__device__ __align__(128) f16   g_cath[TT*1088];
__device__ __align__(128) float g_axs [TT*1023];
__device__ __align__(128) float g_x1  [TT*1024];
__device__ __align__(128) f16   g_h1h [TT*1024];
__device__ __align__(128) float g_fcpre[(size_t)TT*4095];
__device__ __align__(128) f16   g_fch [(size_t)TT*4096];
__device__ __align__(128) float g_pjs [TT*1023];

// ===================== PTX helpers =====================
__device__ __forceinline__ uint32_t smem_u32(const void* p) {
    uint32_t a;
    asm("{ .reg .u64 t; cvta.to.shared.u64 t, %1; cvt.u32.u64 %0, t; }" : "=r"(a) : "l"(p));
    return a;
}

#define CP_ASYNC16(dst, src) \
    asm volatile("cp.async.cg.shared.global [%0], [%1], 16;" :: "r"(dst), "l"(src))
#define CP_COMMIT() asm volatile("cp.async.commit_group;")
#define CP_WAIT1()  asm volatile("cp.async.wait_group 1;")
#define CP_WAIT0()  asm volatile("cp.async.wait_group 0;")

__device__ __forceinline__ void mma16816h(float* c, const uint32_t* a, const uint32_t* b) {
    asm volatile(
        "mma.sync.aligned.m16n8k16.row.col.f32.f16.f16.f32 "
        "{%0,%1,%2,%3}, {%4,%5,%6,%7}, {%8,%9}, {%0,%1,%2,%3};"
        : "+f"(c[0]), "+f"(c[1]), "+f"(c[2]), "+f"(c[3])
        : "r"(a[0]), "r"(a[1]), "r"(a[2]), "r"(a[3]), "r"(b[0]), "r"(b[1]));
}

__device__ __forceinline__ void hsplit(float v, f16& h, f16& l) {
    h = __float2half(v);
    l = __float2half(v - __half2float(h));
}

__device__ __forceinline__ uint32_t pack_hi2h(float a, float b) {
    __half2 r = __floats2half2_rn(a, b);
    return *(uint32_t*)&r;
}
__device__ __forceinline__ uint32_t pack_lo2h(float a, float b) {
    float ra = a - __half2float(__float2half(a));
    float rb = b - __half2float(__float2half(b));
    __half2 r = __floats2half2_rn(ra, rb);
    return *(uint32_t*)&r;
}

// ===================== block reductions =====================
__device__ __forceinline__ float blk_sum(float v, float* sbuf) {
    int tid = threadIdx.x;
    #pragma unroll
    for (int o = 16; o > 0; o >>= 1) v += __shfl_down_sync(0xffffffffu, v, o);
    if ((tid & 31) == 0) sbuf[tid >> 5] = v;
    __syncthreads();
    if (tid < 32) {
        int nw = (blockDim.x + 31) >> 5;
        float x = (tid < nw) ? sbuf[tid] : 0.f;
        #pragma unroll
        for (int o = 16; o > 0; o >>= 1) x += __shfl_down_sync(0xffffffffu, x, o);
        if (tid == 0) sbuf[0] = x;
    }
    __syncthreads();
    float r = sbuf[0];
    __syncthreads();
    return r;
}

// ===================== fp16 1-pass GEMM (A and B fp16-rounded) =====================
template<int KC>
__global__ __launch_bounds__(256)
void gemm1p(const f16* __restrict__ Ah, const f16* __restrict__ Bh,
            const float* __restrict__ bias, float* __restrict__ C,
            int lda, int ldb, int ldc, int Nreal, int K)
{
    constexpr int ROWB = 2 * KC + 16;
    constexpr int STG_MAT = 128 * ROWB;
    constexpr int STG_SZ = 2 * STG_MAT;
    constexpr int CPR = KC / 8;
    constexpr int LPT = KC / 8;            // 2 matrices * 128 rows * CPR / 256

    extern __shared__ char smem[];
    int tid = threadIdx.x, w = tid >> 5, lane = tid & 31;
    int m0 = blockIdx.y * 128, n0 = blockIdx.x * 128;
    const int NC = K / KC;

    auto load_stage = [&](int kofs, int s) {
        char* stg = smem + s * STG_SZ;
        #pragma unroll
        for (int i = 0; i < LPT; i++) {
            int idx = tid + i * 256;
            int mat = idx / (16 * KC);            // 0:Ah 1:Bh
            int cc  = idx % (16 * KC);
            int row = cc / CPR, kc = cc % CPR;
            uint32_t dst = smem_u32(stg + mat * STG_MAT + row * ROWB + kc * 16);
            const f16* p = (mat == 0) ? Ah : Bh;
            int b0 = (mat == 0) ? m0 : n0;
            int ld = (mat == 0) ? lda : ldb;
            CP_ASYNC16(dst, p + (size_t)(b0 + row) * ld + kofs + kc * 8);
        }
        CP_COMMIT();
    };

    load_stage(0, 0);
    if (NC > 1) load_stage(KC, 1);

    int g = lane >> 2, t = lane & 3;
    int wm = (w & 3) * 32, wn = (w >> 2) * 64;

    float acc[2][8][4];
    #pragma unroll
    for (int mt = 0; mt < 2; mt++)
        #pragma unroll
        for (int nt = 0; nt < 8; nt++)
            #pragma unroll
            for (int r = 0; r < 4; r++) acc[mt][nt][r] = 0.f;

    for (int kc = 0; kc < NC; kc++) {
        if (kc + 1 < NC) { CP_WAIT1(); } else { CP_WAIT0(); }
        __syncthreads();
        const char* stg = smem + (kc & 1) * STG_SZ;
        const char* pAh = stg;
        const char* pBh = stg + STG_MAT;

        #pragma unroll
        for (int ko = 0; ko < KC; ko += 16) {
            uint32_t aH[2][4], b[8][2];
            #pragma unroll
            for (int mt = 0; mt < 2; mt++) {
                int r0 = (wm + mt * 16 + g) * ROWB + (ko + t * 2) * 2;
                aH[mt][0] = *(const uint32_t*)(pAh + r0);
                aH[mt][1] = *(const uint32_t*)(pAh + r0 + 8 * ROWB);
                aH[mt][2] = *(const uint32_t*)(pAh + r0 + 16);
                aH[mt][3] = *(const uint32_t*)(pAh + r0 + 8 * ROWB + 16);
            }
            #pragma unroll
            for (int nt = 0; nt < 8; nt++) {
                int r0 = (wn + nt * 8 + g) * ROWB + (ko + t * 2) * 2;
                b[nt][0] = *(const uint32_t*)(pBh + r0);
                b[nt][1] = *(const uint32_t*)(pBh + r0 + 16);
            }
            #pragma unroll
            for (int mt = 0; mt < 2; mt++)
                #pragma unroll
                for (int nt = 0; nt < 8; nt++)
                    mma16816h(acc[mt][nt], aH[mt], b[nt]);
        }
        __syncthreads();
        if (kc + 2 < NC) load_stage((kc + 2) * KC, kc & 1);
    }

    #pragma unroll
    for (int mt = 0; mt < 2; mt++) {
        int r0 = m0 + wm + mt * 16 + g;
        float* c0p = C + (size_t)r0 * ldc;
        float* c1p = C + (size_t)(r0 + 8) * ldc;
        #pragma unroll
        for (int nt = 0; nt < 8; nt++) {
            int n = n0 + wn + nt * 8 + t * 2;
            if (n < Nreal) {
                float bv = bias ? bias[n] : 0.f;
                c0p[n] = acc[mt][nt][0] + bv;
                c1p[n] = acc[mt][nt][2] + bv;
            }
            if (n + 1 < Nreal) {
                float bv = bias ? bias[n + 1] : 0.f;
                c0p[n + 1] = acc[mt][nt][1] + bv;
                c1p[n + 1] = acc[mt][nt][3] + bv;
            }
        }
    }
}

#define SMEM_1P64 (2 * 2 * 128 * 144)  // 73728

// ===================== fused flash attention (fp16 2-pass, exact q/P) =====================
#define FQ_ROWB 176
#define FV_ROWB 144
#define FSM_QMAT (128*FQ_ROWB)
#define FSM_K0   (2*FSM_QMAT)
#define FSM_KSTG (64*FQ_ROWB)
#define FSM_V0   (FSM_K0 + 2*FSM_KSTG)
#define FSM_VSTG (72*FV_ROWB)
#define FSM_TOTAL (FSM_V0 + 2*FSM_VSTG)   // 88320

__global__ __launch_bounds__(256)
void flash_attn(const f16* __restrict__ qhh, const f16* __restrict__ qhl,
                const f16* __restrict__ khh,
                const f16* __restrict__ vth,
                f16* __restrict__ cath)
{
    extern __shared__ char smem[];
    int tid = threadIdx.x, w = tid >> 5, lane = tid & 31;
    int g = lane >> 2, t = lane & 3;
    int bh = blockIdx.y;
    int q0 = blockIdx.x * 128;

    {
        #pragma unroll
        for (int i = 0; i < 10; i++) {
            int idx = tid + i * 256;
            int mat = idx / 1280;
            int cc = idx % 1280;
            int row = cc / 10, ch = cc % 10;
            const f16* src = (mat ? qhl : qhh) +
                ((size_t)bh * 1024 + q0 + row) * QKLD + ch * 8;
            uint32_t dst = smem_u32(smem + mat * FSM_QMAT + row * FQ_ROWB + ch * 16);
            CP_ASYNC16(dst, src);
        }
        CP_COMMIT();
    }

    auto load_kv = [&](int kt, int s) {
        char* kb = smem + FSM_K0 + s * FSM_KSTG;
        char* vb = smem + FSM_V0 + s * FSM_VSTG;
        #pragma unroll
        for (int i = 0; i < 5; i++) {
            int idx = tid + i * 256;
            if (idx < 640) {
                int row = idx / 10, ch = idx % 10;
                const f16* src = khh + ((size_t)bh * 1024 + kt * 64 + row) * QKLD + ch * 8;
                uint32_t dst = smem_u32(kb + row * FQ_ROWB + ch * 16);
                CP_ASYNC16(dst, src);
            } else if (idx < 1216) {
                int cc = idx - 640;
                int row = cc / 8, ch = cc % 8;
                const f16* src = vth + ((size_t)bh * 72 + row) * 1024 + kt * 64 + ch * 8;
                uint32_t dst = smem_u32(vb + row * FV_ROWB + ch * 16);
                CP_ASYNC16(dst, src);
            }
        }
        CP_COMMIT();
    };

    load_kv(0, 0);

    float O[9][4];
    #pragma unroll
    for (int nv = 0; nv < 9; nv++)
        #pragma unroll
        for (int r = 0; r < 4; r++) O[nv][r] = 0.f;
    float m0 = -INFINITY, m1 = -INFINITY, l0 = 0.f, l1 = 0.f;

    for (int kt = 0; kt < 16; kt++) {
        if (kt + 1 < 16) { load_kv(kt + 1, (kt + 1) & 1); CP_WAIT1(); }
        else { CP_WAIT0(); }
        __syncthreads();
        const char* pK = smem + FSM_K0 + (kt & 1) * FSM_KSTG;
        const char* pV = smem + FSM_V0 + (kt & 1) * FSM_VSTG;

        float S[8][4];
        #pragma unroll
        for (int nt = 0; nt < 8; nt++)
            #pragma unroll
            for (int r = 0; r < 4; r++) S[nt][r] = 0.f;

        #pragma unroll
        for (int kk = 0; kk < 5; kk++) {
            uint32_t aH[4], aL[4], b[2];
            int r0 = (w * 16 + g) * FQ_ROWB + (kk * 16 + t * 2) * 2;
            aH[0] = *(const uint32_t*)(smem + r0);
            aH[1] = *(const uint32_t*)(smem + r0 + 8 * FQ_ROWB);
            aH[2] = *(const uint32_t*)(smem + r0 + 16);
            aH[3] = *(const uint32_t*)(smem + r0 + 8 * FQ_ROWB + 16);
            aL[0] = *(const uint32_t*)(smem + FSM_QMAT + r0);
            aL[1] = *(const uint32_t*)(smem + FSM_QMAT + r0 + 8 * FQ_ROWB);
            aL[2] = *(const uint32_t*)(smem + FSM_QMAT + r0 + 16);
            aL[3] = *(const uint32_t*)(smem + FSM_QMAT + r0 + 8 * FQ_ROWB + 16);
            #pragma unroll
            for (int nt = 0; nt < 8; nt++) {
                int rb = (nt * 8 + g) * FQ_ROWB + (kk * 16 + t * 2) * 2;
                b[0] = *(const uint32_t*)(pK + rb);
                b[1] = *(const uint32_t*)(pK + rb + 16);
                mma16816h(S[nt], aH, b);
                mma16816h(S[nt], aL, b);
            }
        }

        #pragma unroll
        for (int nt = 0; nt < 8; nt++)
            #pragma unroll
            for (int r = 0; r < 4; r++) S[nt][r] *= 0.25f;

        float lm0 = -INFINITY, lm1 = -INFINITY;
        #pragma unroll
        for (int nt = 0; nt < 8; nt++) {
            lm0 = fmaxf(lm0, fmaxf(S[nt][0], S[nt][1]));
            lm1 = fmaxf(lm1, fmaxf(S[nt][2], S[nt][3]));
        }
        lm0 = fmaxf(lm0, __shfl_xor_sync(0xffffffffu, lm0, 1));
        lm0 = fmaxf(lm0, __shfl_xor_sync(0xffffffffu, lm0, 2));
        lm1 = fmaxf(lm1, __shfl_xor_sync(0xffffffffu, lm1, 1));
        lm1 = fmaxf(lm1, __shfl_xor_sync(0xffffffffu, lm1, 2));
        float mn0 = fmaxf(m0, lm0), mn1 = fmaxf(m1, lm1);
        float sc0 = __expf(m0 - mn0), sc1 = __expf(m1 - mn1);
        m0 = mn0; m1 = mn1;
        l0 *= sc0; l1 *= sc1;
        #pragma unroll
        for (int nv = 0; nv < 9; nv++) {
            O[nv][0] *= sc0; O[nv][1] *= sc0;
            O[nv][2] *= sc1; O[nv][3] *= sc1;
        }
        #pragma unroll
        for (int nt = 0; nt < 8; nt++) {
            S[nt][0] = __expf(S[nt][0] - mn0);
            S[nt][1] = __expf(S[nt][1] - mn0);
            S[nt][2] = __expf(S[nt][2] - mn1);
            S[nt][3] = __expf(S[nt][3] - mn1);
            l0 += S[nt][0] + S[nt][1];
            l1 += S[nt][2] + S[nt][3];
        }

        #pragma unroll
        for (int ks = 0; ks < 4; ks++) {
            uint32_t pH[4], pL[4], b[2];
            pH[0] = pack_hi2h(S[2 * ks][0], S[2 * ks][1]);
            pH[1] = pack_hi2h(S[2 * ks][2], S[2 * ks][3]);
            pH[2] = pack_hi2h(S[2 * ks + 1][0], S[2 * ks + 1][1]);
            pH[3] = pack_hi2h(S[2 * ks + 1][2], S[2 * ks + 1][3]);
            pL[0] = pack_lo2h(S[2 * ks][0], S[2 * ks][1]);
            pL[1] = pack_lo2h(S[2 * ks][2], S[2 * ks][3]);
            pL[2] = pack_lo2h(S[2 * ks + 1][0], S[2 * ks + 1][1]);
            pL[3] = pack_lo2h(S[2 * ks + 1][2], S[2 * ks + 1][3]);
            #pragma unroll
            for (int nv = 0; nv < 9; nv++) {
                int rb = (nv * 8 + g) * FV_ROWB + (ks * 16 + t * 2) * 2;
                b[0] = *(const uint32_t*)(pV + rb);
                b[1] = *(const uint32_t*)(pV + rb + 16);
                mma16816h(O[nv], pH, b);
                mma16816h(O[nv], pL, b);
            }
        }
        __syncthreads();
    }

    l0 += __shfl_xor_sync(0xffffffffu, l0, 1);
    l0 += __shfl_xor_sync(0xffffffffu, l0, 2);
    l1 += __shfl_xor_sync(0xffffffffu, l1, 1);
    l1 += __shfl_xor_sync(0xffffffffu, l1, 2);
    float r0 = 1.f / l0, r1 = 1.f / l1;
    #pragma unroll
    for (int nv = 0; nv < 9; nv++) {
        O[nv][0] *= r0; O[nv][1] *= r0;
        O[nv][2] *= r1; O[nv][3] *= r1;
    }
    float t0 = __shfl_sync(0xffffffffu, O[0][0], lane & ~3);
    float t1 = __shfl_sync(0xffffffffu, O[0][2], lane & ~3);
    float ss0 = 0.f, ss1 = 0.f;
    #pragma unroll
    for (int nv = 0; nv < 9; nv++) {
        int c = nv * 8 + 2 * t;
        if (c >= 1 && c < 65) { ss0 += O[nv][0] * O[nv][0]; ss1 += O[nv][2] * O[nv][2]; }
        if (c + 1 >= 1 && c + 1 < 65) { ss0 += O[nv][1] * O[nv][1]; ss1 += O[nv][3] * O[nv][3]; }
    }
    ss0 += __shfl_xor_sync(0xffffffffu, ss0, 1);
    ss0 += __shfl_xor_sync(0xffffffffu, ss0, 2);
    ss1 += __shfl_xor_sync(0xffffffffu, ss1, 1);
    ss1 += __shfl_xor_sync(0xffffffffu, ss1, 2);
    float inv0 = rsqrtf(fmaxf(t0 * t0 - ss0, 1e-8f));
    float inv1 = rsqrtf(fmaxf(t1 * t1 - ss1, 1e-8f));

    int b = bh >> 4, h = bh & 15;
    int tr0 = b * 1024 + q0 + w * 16 + g;
    size_t base0 = (size_t)tr0 * 1088 + h * 65;
    size_t base1 = (size_t)(tr0 + 8) * 1088 + h * 65;
    #pragma unroll
    for (int nv = 0; nv < 9; nv++) {
        int c = nv * 8 + 2 * t;
        if (c < 65) {
            cath[base0 + c] = __float2half(O[nv][0] * inv0);
            cath[base1 + c] = __float2half(O[nv][2] * inv1);
        }
        if (c + 1 < 65) {
            cath[base0 + c + 1] = __float2half(O[nv][1] * inv0);
            cath[base1 + c + 1] = __float2half(O[nv][3] * inv1);
        }
    }
}

// ===================== weight transpose -> fp16 =====================
__global__ void k_tsplit_h(const float* __restrict__ W, f16* __restrict__ Th,
                           int K, int N, int Kpad)
{
    __shared__ float t[32][33];
    int nb = blockIdx.x * 32, kb = blockIdx.y * 32;
    int tx = threadIdx.x, ty = threadIdx.y;
    #pragma unroll
    for (int i = 0; i < 32; i += 8) {
        int k = kb + ty + i, n = nb + tx;
        t[ty + i][tx] = (k < K && n < N) ? W[(size_t)k * N + n] : 0.f;
    }
    __syncthreads();
    #pragma unroll
    for (int i = 0; i < 32; i += 8) {
        int n = nb + ty + i, k = kb + tx;
        if (n < N && k < K)
            Th[(size_t)n * Kpad + k] = __float2half(t[tx][ty + i]);
    }
}

// ===================== Lorentz layernorm -> fp16 (hi only) =====================
__global__ __launch_bounds__(256)
void k_ln(const float* __restrict__ x, const float* __restrict__ g,
          const float* __restrict__ b, f16* __restrict__ oh)
{
    __shared__ float sbuf[32];
    int t = blockIdx.x, tid = threadIdx.x;
    const float* xs = x + (size_t)t * 1024 + 1;
    float sv[4]; float s1 = 0.f, s2 = 0.f;
    #pragma unroll
    for (int j = 0; j < 4; j++) {
        int i = tid + j * 256;
        sv[j] = 0.f;
        if (i < 1023) { sv[j] = xs[i]; s1 += sv[j]; s2 += sv[j] * sv[j]; }
    }
    s1 = blk_sum(s1, sbuf);
    s2 = blk_sum(s2, sbuf);
    float mu = s1 * (1.f / 1023.f);
    float var = s2 * (1.f / 1023.f) - mu * mu;
    float rstd = rsqrtf(var + 1e-5f);
    float q = 0.f;
    float yv[4];
    #pragma unroll
    for (int j = 0; j < 4; j++) {
        int i = tid + j * 256;
        yv[j] = 0.f;
        if (i < 1023) {
            yv[j] = (sv[j] - mu) * rstd * g[i] + b[i];
            q += yv[j] * yv[j];
        }
    }
    q = blk_sum(q, sbuf);
    size_t base = (size_t)t * 1024;
    #pragma unroll
    for (int j = 0; j < 4; j++) {
        int i = tid + j * 256;
        if (i < 1023) oh[base + 1 + i] = __float2half(yv[j]);
    }
    if (tid == 0) oh[base] = __float2half(sqrtf(q + 1.f));
}

// ===================== lift heads: Q (hi/lo, sign -1) or K (hi only, sign +1) =====================
__global__ __launch_bounds__(512)
void k_lift(const float* __restrict__ S, f16* __restrict__ Oh, f16* __restrict__ Ol, float sign)
{
    int t = blockIdx.x;
    int b = t >> 10, n = t & 1023;
    int w = threadIdx.x >> 5, lane = threadIdx.x & 31;
    const float* src = S + (size_t)t * 1024 + w * 64;
    float v0 = src[lane], v1 = src[lane + 32];
    float ss = v0 * v0 + v1 * v1;
    #pragma unroll
    for (int o = 16; o > 0; o >>= 1) ss += __shfl_down_sync(0xffffffffu, ss, o);
    ss = __shfl_sync(0xffffffffu, ss, 0);
    size_t base = ((size_t)(b * HH + w) * 1024 + n) * QKLD;
    f16 h, l;
    hsplit(v0, h, l); Oh[base + 1 + lane] = h; if (Ol) Ol[base + 1 + lane] = l;
    hsplit(v1, h, l); Oh[base + 33 + lane] = h; if (Ol) Ol[base + 33 + lane] = l;
    if (lane == 0) {
        hsplit(sign * sqrtf(ss + 1.f), h, l);
        Oh[base] = h; if (Ol) Ol[base] = l;
    }
    for (int i = 65 + lane; i < QKLD; i += 32) {
        Oh[base + i] = __float2half(0.f);
        if (Ol) Ol[base + i] = __float2half(0.f);
    }
}

// ===================== lift+transpose v -> fp16 (BH,72,1024) =====================
__global__ void k_liftT(const float* __restrict__ vs, f16* __restrict__ Th)
{
    int blk = blockIdx.x;
    int bh = blk >> 5;
    int tg = blk & 31;
    int b = bh >> 4, h = bh & 15;
    __shared__ float sv[32][65];
    __shared__ float stime[32];
    int tx = threadIdx.x, ty = threadIdx.y;
    #pragma unroll
    for (int i = 0; i < 32; i += 8) {
        int tok = i + ty;
        const float* src = vs + (size_t)(b * 1024 + tg * 32 + tok) * 1024 + h * 64;
        sv[tok][1 + tx] = src[tx];
        sv[tok][33 + tx] = src[tx + 32];
    }
    __syncthreads();
    if (ty == 0) {
        float s = 0.f;
        #pragma unroll
        for (int d = 1; d <= 64; d++) { float x = sv[tx][d]; s += x * x; }
        stime[tx] = sqrtf(s + 1.f);
    }
    __syncthreads();
    size_t base = (size_t)bh * (72 * 1024) + (size_t)(tg * 32);
    for (int d = ty; d < 72; d += 8) {
        float v = (d == 0) ? stime[tx] : (d < 65 ? sv[tx][d] : 0.f);
        Th[base + (size_t)d * 1024 + tx] = __float2half(v);
    }
}

// ===================== gelu + lift -> fp16 (hi only) =====================
__global__ __launch_bounds__(256)
void k_gelu(const float* __restrict__ fcpre, f16* __restrict__ fh)
{
    __shared__ float sbuf[32];
    int t = blockIdx.x, tid = threadIdx.x;
    const float* rin = fcpre + (size_t)t * 4095;
    float gv[16];
    float q = 0.f;
    #pragma unroll
    for (int j = 0; j < 16; j++) {
        int i = tid + j * 256;
        gv[j] = 0.f;
        if (i < 4095) {
            float x = rin[i];
            gv[j] = 0.5f * x * (1.f + erff(x * 0.70710678118654752f));
            q += gv[j] * gv[j];
        }
    }
    q = blk_sum(q, sbuf);
    size_t base = (size_t)t * 4096;
    #pragma unroll
    for (int j = 0; j < 16; j++) {
        int i = tid + j * 256;
        if (i < 4095) fh[base + 1 + i] = __float2half(gv[j]);
    }
    if (tid == 0) fh[base] = __float2half(sqrtf(q + 1.f));
}

// ===================== Lorentz residual =====================
__global__ __launch_bounds__(256)
void k_lresnet(const float* __restrict__ xin, const float* __restrict__ spart,
               const float* __restrict__ wp, float* __restrict__ out)
{
    __shared__ float sbuf[32];
    int t = blockIdx.x, tid = threadIdx.x;
    float w = wp[0];
    const float* xr = xin + (size_t)t * 1024;
    const float* ar = spart + (size_t)t * 1023;
    float xs[4], as[4];
    float sa = 0.f;
    #pragma unroll
    for (int j = 0; j < 4; j++) {
        int i = tid + j * 256;
        xs[j] = 0.f; as[j] = 0.f;
        if (i < 1023) { xs[j] = xr[1 + i]; as[j] = ar[i]; sa += as[j] * as[j]; }
    }
    sa = blk_sum(sa, sbuf);
    float axt = sqrtf(sa + 1.f);
    float zt = xr[0] + w * axt;
    float sz = 0.f;
    #pragma unroll
    for (int j = 0; j < 4; j++) {
        int i = tid + j * 256;
        if (i < 1023) { xs[j] = xs[j] + w * as[j]; sz += xs[j] * xs[j]; }
    }
    sz = blk_sum(sz, sbuf);
    float inv = rsqrtf(fmaxf(zt * zt - sz, 1e-8f));
    if (tid == 0) out[(size_t)t * 1024] = zt * inv;
    #pragma unroll
    for (int j = 0; j < 4; j++) {
        int i = tid + j * 256;
        if (i < 1023) out[(size_t)t * 1024 + 1 + i] = xs[j] * inv;
    }
}

// ===================== host =====================
extern "C" void kernel_launch(void* const* d_in, const int* in_sizes, int n_in,
                              void* d_out, int out_size)
{
    const float* x   = (const float*)d_in[0];
    const float* g1  = (const float*)d_in[1];
    const float* b1  = (const float*)d_in[2];
    const float* Wq  = (const float*)d_in[3];
    const float* bq  = (const float*)d_in[4];
    const float* Wk  = (const float*)d_in[5];
    const float* bk  = (const float*)d_in[6];
    const float* Wv  = (const float*)d_in[7];
    const float* bv  = (const float*)d_in[8];
    const float* Wo  = (const float*)d_in[9];
    const float* bo  = (const float*)d_in[10];
    const float* g2  = (const float*)d_in[11];
    const float* b2  = (const float*)d_in[12];
    const float* Wfc = (const float*)d_in[13];
    const float* bfc = (const float*)d_in[14];
    const float* Wpj = (const float*)d_in[15];
    const float* bpj = (const float*)d_in[16];
    const float* w1  = (const float*)d_in[17];
    const float* w2  = (const float*)d_in[18];
    float* out = (float*)d_out;

    cudaFuncSetAttribute(gemm1p<64>, cudaFuncAttributeMaxDynamicSharedMemorySize, SMEM_1P64);
    cudaFuncSetAttribute(flash_attn, cudaFuncAttributeMaxDynamicSharedMemorySize, FSM_TOTAL);

    #define SYM(p, s) do { void* _t; cudaGetSymbolAddress(&_t, s); p = decltype(p)(_t); } while (0)
    f16 *lxh, *WqTh, *WkTh, *WvTh, *WoTh, *WfcTh, *WpjTh;
    f16 *qhh, *qhl, *khh, *vTh, *cath, *h1h, *fch;
    float *qs, *ks, *vs, *axs, *x1, *fcpre, *pjs;
    SYM(lxh, g_lxh);
    SYM(WqTh, g_WqTh); SYM(WkTh, g_WkTh); SYM(WvTh, g_WvTh);
    SYM(WoTh, g_WoTh);
    SYM(WfcTh, g_WfcTh); SYM(WpjTh, g_WpjTh);
    SYM(qs, g_qs); SYM(ks, g_ks); SYM(vs, g_vs);
    SYM(qhh, g_qhh); SYM(qhl, g_qhl); SYM(khh, g_khh);
    SYM(vTh, g_vTh);
    SYM(cath, g_cath);
    SYM(axs, g_axs); SYM(x1, g_x1); SYM(h1h, g_h1h);
    SYM(fcpre, g_fcpre); SYM(fch, g_fch); SYM(pjs, g_pjs);

    dim3 tb(32, 8);
    k_tsplit_h<<<dim3(32, 32), tb>>>(Wq, WqTh, 1024, 1024, 1024);
    k_tsplit_h<<<dim3(32, 32), tb>>>(Wk, WkTh, 1024, 1024, 1024);
    k_tsplit_h<<<dim3(32, 32), tb>>>(Wv, WvTh, 1024, 1024, 1024);
    k_tsplit_h<<<dim3(32, 33), tb>>>(Wo, WoTh, 1040, 1023, 1088);
    k_ln<<<TT, 256>>>(x, g1, b1, lxh);

    // QKV: fp16 1-pass
    {
        dim3 grid(8, 32, 1);
        gemm1p<64><<<grid, 256, SMEM_1P64>>>(lxh, WqTh, bq, qs, 1024, 1024, 1024, 1024, 1024);
        gemm1p<64><<<grid, 256, SMEM_1P64>>>(lxh, WkTh, bk, ks, 1024, 1024, 1024, 1024, 1024);
        gemm1p<64><<<grid, 256, SMEM_1P64>>>(lxh, WvTh, bv, vs, 1024, 1024, 1024, 1024, 1024);
    }

    // remaining weight transposes
    k_tsplit_h<<<dim3(128, 32), tb>>>(Wfc, WfcTh, 1024, 4095, 1024);
    k_tsplit_h<<<dim3(32, 128), tb>>>(Wpj, WpjTh, 4096, 1023, 4096);

    // lifts
    k_lift<<<TT, 512>>>(qs, qhh, qhl, -1.f);
    k_lift<<<TT, 512>>>(ks, khh, nullptr, 1.f);
    k_liftT<<<BHN * 32, tb>>>(vs, vTh);

    // fused flash attention -> cat (hi only)
    flash_attn<<<dim3(8, BHN), 256, FSM_TOTAL>>>(qhh, qhl, khh, vTh, cath);

    // Wo: fp16 1-pass
    gemm1p<64><<<dim3(8, 32, 1), 256, SMEM_1P64>>>(cath, WoTh, bo, axs,
        1088, 1088, 1023, 1023, 1088);

    // residual 1
    k_lresnet<<<TT, 256>>>(x, axs, w1, x1);

    // LN2
    k_ln<<<TT, 256>>>(x1, g2, b2, h1h);

    // Wfc: fp16 1-pass
    gemm1p<64><<<dim3(32, 32, 1), 256, SMEM_1P64>>>(h1h, WfcTh, bfc, fcpre,
        1024, 1024, 4095, 4095, 1024);

    // gelu + lift
    k_gelu<<<TT, 256>>>(fcpre, fch);

    // Wpj: fp16 1-pass
    gemm1p<64><<<dim3(8, 32, 1), 256, SMEM_1P64>>>(fch, WpjTh, bpj, pjs,
        4096, 4096, 1023, 1023, 4096);

    // residual 2
    k_lresnet<<<TT, 256>>>(x1, pjs, w2, out);
}

// round 12
// speedup vs baseline: 4.1628x; 1.0677x over previous
#include <cuda_runtime.h>
#include <cuda_bf16.h>
#include <cuda_fp16.h>
#include <math.h>
#include <stdint.h>

// Problem constants
#define BB 4
#define NNTOK 1024
#define DDIM 1024
#define HH 16
#define TT (BB*NNTOK)     // 4096 tokens
#define BHN (BB*HH)       // 64
#define QKLD 80           // padded lifted q/k leading dim (65 -> 80)

typedef __half f16;

// ===================== scratch (device globals) =====================
__device__ __align__(128) f16   g_lxh [TT*1024];
__device__ __align__(128) f16   g_WqTh[1024*1024];
__device__ __align__(128) f16   g_WkTh[1024*1024];
__device__ __align__(128) f16   g_WvTh[1024*1024];
__device__ __align__(128) f16   g_WoTh[1024*1088];
__device__ __align__(128) f16   g_WfcTh[4096*1024];
__device__ __align__(128) f16   g_WpjTh[1024*4096];
__device__ __align__(128) float g_qs  [TT*1024];
__device__ __align__(128) float g_ks  [TT*1024];
__device__ __align__(128) float g_vs  [TT*1024];
__device__ __align__(128) f16   g_qhh [(size_t)BHN*1024*QKLD];
__device__ __align__(128) f16   g_khh [(size_t)BHN*1024*QKLD];
__device__ __align__(128) f16   g_vTh [(size_t)BHN*72*1024];
__device__ __align__(128) f16   g_cath[TT*1088];
__device__ __align__(128) float g_axs [TT*1023];
__device__ __align__(128) float g_x1  [TT*1024];
__device__ __align__(128) f16   g_h1h [TT*1024];
__device__ __align__(128) f16   g_fch [(size_t)TT*4096];
__device__ __align__(128) float g_qsum[TT];
__device__ __align__(128) float g_pjs [TT*1023];

// ===================== PTX helpers =====================
__device__ __forceinline__ uint32_t smem_u32(const void* p) {
    uint32_t a;
    asm("{ .reg .u64 t; cvta.to.shared.u64 t, %1; cvt.u32.u64 %0, t; }" : "=r"(a) : "l"(p));
    return a;
}

#define CP_ASYNC16(dst, src) \
    asm volatile("cp.async.cg.shared.global [%0], [%1], 16;" :: "r"(dst), "l"(src))
#define CP_COMMIT() asm volatile("cp.async.commit_group;")
#define CP_WAIT1()  asm volatile("cp.async.wait_group 1;")
#define CP_WAIT0()  asm volatile("cp.async.wait_group 0;")

__device__ __forceinline__ void mma16816h(float* c, const uint32_t* a, const uint32_t* b) {
    asm volatile(
        "mma.sync.aligned.m16n8k16.row.col.f32.f16.f16.f32 "
        "{%0,%1,%2,%3}, {%4,%5,%6,%7}, {%8,%9}, {%0,%1,%2,%3};"
        : "+f"(c[0]), "+f"(c[1]), "+f"(c[2]), "+f"(c[3])
        : "r"(a[0]), "r"(a[1]), "r"(a[2]), "r"(a[3]), "r"(b[0]), "r"(b[1]));
}

__device__ __forceinline__ uint32_t pack_hi2h(float a, float b) {
    __half2 r = __floats2half2_rn(a, b);
    return *(uint32_t*)&r;
}

// ===================== block reductions =====================
__device__ __forceinline__ float blk_sum(float v, float* sbuf) {
    int tid = threadIdx.x;
    #pragma unroll
    for (int o = 16; o > 0; o >>= 1) v += __shfl_down_sync(0xffffffffu, v, o);
    if ((tid & 31) == 0) sbuf[tid >> 5] = v;
    __syncthreads();
    if (tid < 32) {
        int nw = (blockDim.x + 31) >> 5;
        float x = (tid < nw) ? sbuf[tid] : 0.f;
        #pragma unroll
        for (int o = 16; o > 0; o >>= 1) x += __shfl_down_sync(0xffffffffu, x, o);
        if (tid == 0) sbuf[0] = x;
    }
    __syncthreads();
    float r = sbuf[0];
    __syncthreads();
    return r;
}

// ===================== fp16 1-pass GEMM =====================
template<int KC>
__global__ __launch_bounds__(256)
void gemm1p(const f16* __restrict__ Ah, const f16* __restrict__ Bh,
            const float* __restrict__ bias, float* __restrict__ C,
            int lda, int ldb, int ldc, int Nreal, int K)
{
    constexpr int ROWB = 2 * KC + 16;
    constexpr int STG_MAT = 128 * ROWB;
    constexpr int STG_SZ = 2 * STG_MAT;
    constexpr int CPR = KC / 8;
    constexpr int LPT = KC / 8;

    extern __shared__ char smem[];
    int tid = threadIdx.x, w = tid >> 5, lane = tid & 31;
    int m0 = blockIdx.y * 128, n0 = blockIdx.x * 128;
    const int NC = K / KC;

    auto load_stage = [&](int kofs, int s) {
        char* stg = smem + s * STG_SZ;
        #pragma unroll
        for (int i = 0; i < LPT; i++) {
            int idx = tid + i * 256;
            int mat = idx / (16 * KC);
            int cc  = idx % (16 * KC);
            int row = cc / CPR, kc = cc % CPR;
            uint32_t dst = smem_u32(stg + mat * STG_MAT + row * ROWB + kc * 16);
            const f16* p = (mat == 0) ? Ah : Bh;
            int b0 = (mat == 0) ? m0 : n0;
            int ld = (mat == 0) ? lda : ldb;
            CP_ASYNC16(dst, p + (size_t)(b0 + row) * ld + kofs + kc * 8);
        }
        CP_COMMIT();
    };

    load_stage(0, 0);
    if (NC > 1) load_stage(KC, 1);

    int g = lane >> 2, t = lane & 3;
    int wm = (w & 3) * 32, wn = (w >> 2) * 64;

    float acc[2][8][4];
    #pragma unroll
    for (int mt = 0; mt < 2; mt++)
        #pragma unroll
        for (int nt = 0; nt < 8; nt++)
            #pragma unroll
            for (int r = 0; r < 4; r++) acc[mt][nt][r] = 0.f;

    for (int kc = 0; kc < NC; kc++) {
        if (kc + 1 < NC) { CP_WAIT1(); } else { CP_WAIT0(); }
        __syncthreads();
        const char* stg = smem + (kc & 1) * STG_SZ;
        const char* pAh = stg;
        const char* pBh = stg + STG_MAT;

        #pragma unroll
        for (int ko = 0; ko < KC; ko += 16) {
            uint32_t aH[2][4], b[8][2];
            #pragma unroll
            for (int mt = 0; mt < 2; mt++) {
                int r0 = (wm + mt * 16 + g) * ROWB + (ko + t * 2) * 2;
                aH[mt][0] = *(const uint32_t*)(pAh + r0);
                aH[mt][1] = *(const uint32_t*)(pAh + r0 + 8 * ROWB);
                aH[mt][2] = *(const uint32_t*)(pAh + r0 + 16);
                aH[mt][3] = *(const uint32_t*)(pAh + r0 + 8 * ROWB + 16);
            }
            #pragma unroll
            for (int nt = 0; nt < 8; nt++) {
                int r0 = (wn + nt * 8 + g) * ROWB + (ko + t * 2) * 2;
                b[nt][0] = *(const uint32_t*)(pBh + r0);
                b[nt][1] = *(const uint32_t*)(pBh + r0 + 16);
            }
            #pragma unroll
            for (int mt = 0; mt < 2; mt++)
                #pragma unroll
                for (int nt = 0; nt < 8; nt++)
                    mma16816h(acc[mt][nt], aH[mt], b[nt]);
        }
        __syncthreads();
        if (kc + 2 < NC) load_stage((kc + 2) * KC, kc & 1);
    }

    #pragma unroll
    for (int mt = 0; mt < 2; mt++) {
        int r0 = m0 + wm + mt * 16 + g;
        float* c0p = C + (size_t)r0 * ldc;
        float* c1p = C + (size_t)(r0 + 8) * ldc;
        #pragma unroll
        for (int nt = 0; nt < 8; nt++) {
            int n = n0 + wn + nt * 8 + t * 2;
            if (n < Nreal) {
                float bv = bias ? bias[n] : 0.f;
                c0p[n] = acc[mt][nt][0] + bv;
                c1p[n] = acc[mt][nt][2] + bv;
            }
            if (n + 1 < Nreal) {
                float bv = bias ? bias[n + 1] : 0.f;
                c0p[n + 1] = acc[mt][nt][1] + bv;
                c1p[n + 1] = acc[mt][nt][3] + bv;
            }
        }
    }
}

#define SMEM_1P64 (2 * 2 * 128 * 144)  // 73728

// ===================== fp16 1-pass GEMM with fused GELU + row sum-of-squares =====================
// Writes fch[row*4096 + 1 + n] = fp16(gelu(acc+bias)); atomicAdd qsum[row] += sum(g^2).
__global__ __launch_bounds__(256)
void gemm1p_gelu(const f16* __restrict__ Ah, const f16* __restrict__ Bh,
                 const float* __restrict__ bias, f16* __restrict__ Cf,
                 float* __restrict__ qsum,
                 int lda, int ldb, int Nreal, int K)
{
    constexpr int KC = 64;
    constexpr int ROWB = 2 * KC + 16;
    constexpr int STG_MAT = 128 * ROWB;
    constexpr int STG_SZ = 2 * STG_MAT;
    constexpr int CPR = KC / 8;
    constexpr int LPT = KC / 8;

    extern __shared__ char smem[];
    int tid = threadIdx.x, w = tid >> 5, lane = tid & 31;
    int m0 = blockIdx.y * 128, n0 = blockIdx.x * 128;
    const int NC = K / KC;

    auto load_stage = [&](int kofs, int s) {
        char* stg = smem + s * STG_SZ;
        #pragma unroll
        for (int i = 0; i < LPT; i++) {
            int idx = tid + i * 256;
            int mat = idx / (16 * KC);
            int cc  = idx % (16 * KC);
            int row = cc / CPR, kc = cc % CPR;
            uint32_t dst = smem_u32(stg + mat * STG_MAT + row * ROWB + kc * 16);
            const f16* p = (mat == 0) ? Ah : Bh;
            int b0 = (mat == 0) ? m0 : n0;
            int ld = (mat == 0) ? lda : ldb;
            CP_ASYNC16(dst, p + (size_t)(b0 + row) * ld + kofs + kc * 8);
        }
        CP_COMMIT();
    };

    load_stage(0, 0);
    if (NC > 1) load_stage(KC, 1);

    int g = lane >> 2, t = lane & 3;
    int wm = (w & 3) * 32, wn = (w >> 2) * 64;

    float acc[2][8][4];
    #pragma unroll
    for (int mt = 0; mt < 2; mt++)
        #pragma unroll
        for (int nt = 0; nt < 8; nt++)
            #pragma unroll
            for (int r = 0; r < 4; r++) acc[mt][nt][r] = 0.f;

    for (int kc = 0; kc < NC; kc++) {
        if (kc + 1 < NC) { CP_WAIT1(); } else { CP_WAIT0(); }
        __syncthreads();
        const char* stg = smem + (kc & 1) * STG_SZ;
        const char* pAh = stg;
        const char* pBh = stg + STG_MAT;

        #pragma unroll
        for (int ko = 0; ko < KC; ko += 16) {
            uint32_t aH[2][4], b[8][2];
            #pragma unroll
            for (int mt = 0; mt < 2; mt++) {
                int r0 = (wm + mt * 16 + g) * ROWB + (ko + t * 2) * 2;
                aH[mt][0] = *(const uint32_t*)(pAh + r0);
                aH[mt][1] = *(const uint32_t*)(pAh + r0 + 8 * ROWB);
                aH[mt][2] = *(const uint32_t*)(pAh + r0 + 16);
                aH[mt][3] = *(const uint32_t*)(pAh + r0 + 8 * ROWB + 16);
            }
            #pragma unroll
            for (int nt = 0; nt < 8; nt++) {
                int r0 = (wn + nt * 8 + g) * ROWB + (ko + t * 2) * 2;
                b[nt][0] = *(const uint32_t*)(pBh + r0);
                b[nt][1] = *(const uint32_t*)(pBh + r0 + 16);
            }
            #pragma unroll
            for (int mt = 0; mt < 2; mt++)
                #pragma unroll
                for (int nt = 0; nt < 8; nt++)
                    mma16816h(acc[mt][nt], aH[mt], b[nt]);
        }
        __syncthreads();
        if (kc + 2 < NC) load_stage((kc + 2) * KC, kc & 1);
    }

    // fused GELU epilogue
    #pragma unroll
    for (int mt = 0; mt < 2; mt++) {
        int r0 = m0 + wm + mt * 16 + g;
        f16* c0p = Cf + (size_t)r0 * 4096 + 1;
        f16* c1p = Cf + (size_t)(r0 + 8) * 4096 + 1;
        float s0 = 0.f, s1 = 0.f;
        #pragma unroll
        for (int nt = 0; nt < 8; nt++) {
            int n = n0 + wn + nt * 8 + t * 2;
            if (n < Nreal) {
                float bv = bias[n];
                float v0 = acc[mt][nt][0] + bv;
                float v2 = acc[mt][nt][2] + bv;
                float g0 = 0.5f * v0 * (1.f + erff(v0 * 0.70710678118654752f));
                float g2 = 0.5f * v2 * (1.f + erff(v2 * 0.70710678118654752f));
                c0p[n] = __float2half(g0); s0 += g0 * g0;
                c1p[n] = __float2half(g2); s1 += g2 * g2;
            }
            if (n + 1 < Nreal) {
                float bv = bias[n + 1];
                float v1 = acc[mt][nt][1] + bv;
                float v3 = acc[mt][nt][3] + bv;
                float g1 = 0.5f * v1 * (1.f + erff(v1 * 0.70710678118654752f));
                float g3 = 0.5f * v3 * (1.f + erff(v3 * 0.70710678118654752f));
                c0p[n + 1] = __float2half(g1); s0 += g1 * g1;
                c1p[n + 1] = __float2half(g3); s1 += g3 * g3;
            }
        }
        // reduce across quad (t = 0..3 share the same rows)
        s0 += __shfl_xor_sync(0xffffffffu, s0, 1);
        s0 += __shfl_xor_sync(0xffffffffu, s0, 2);
        s1 += __shfl_xor_sync(0xffffffffu, s1, 1);
        s1 += __shfl_xor_sync(0xffffffffu, s1, 2);
        if (t == 0) {
            atomicAdd(&qsum[r0], s0);
            atomicAdd(&qsum[r0 + 8], s1);
        }
    }
}

// zero qsum
__global__ void k_zero(float* __restrict__ p, int n) {
    int i = blockIdx.x * 256 + threadIdx.x;
    if (i < n) p[i] = 0.f;
}
// fill time column of fch from qsum
__global__ void k_time(const float* __restrict__ qsum, f16* __restrict__ fch) {
    int i = blockIdx.x * 256 + threadIdx.x;
    if (i < TT) fch[(size_t)i * 4096] = __float2half(sqrtf(qsum[i] + 1.f));
}

// ===================== fused flash attention (fp16 1-pass) =====================
#define FQ_ROWB 176
#define FV_ROWB 144
#define FSM_QMAT (128*FQ_ROWB)                 // 22528
#define FSM_K0   FSM_QMAT
#define FSM_KSTG (64*FQ_ROWB)                  // 11264
#define FSM_V0   (FSM_K0 + 2*FSM_KSTG)         // 45056
#define FSM_VSTG (72*FV_ROWB)                  // 10368
#define FSM_TOTAL (FSM_V0 + 2*FSM_VSTG)        // 65792

__global__ __launch_bounds__(256)
void flash_attn(const f16* __restrict__ qhh,
                const f16* __restrict__ khh,
                const f16* __restrict__ vth,
                f16* __restrict__ cath)
{
    extern __shared__ char smem[];
    int tid = threadIdx.x, w = tid >> 5, lane = tid & 31;
    int g = lane >> 2, t = lane & 3;
    int bh = blockIdx.y;
    int q0 = blockIdx.x * 128;

    // load Q tile (hi only)
    {
        #pragma unroll
        for (int i = 0; i < 5; i++) {
            int idx = tid + i * 256;           // 0..1279
            int row = idx / 10, ch = idx % 10;
            const f16* src = qhh + ((size_t)bh * 1024 + q0 + row) * QKLD + ch * 8;
            uint32_t dst = smem_u32(smem + row * FQ_ROWB + ch * 16);
            CP_ASYNC16(dst, src);
        }
        CP_COMMIT();
    }

    auto load_kv = [&](int kt, int s) {
        char* kb = smem + FSM_K0 + s * FSM_KSTG;
        char* vb = smem + FSM_V0 + s * FSM_VSTG;
        #pragma unroll
        for (int i = 0; i < 5; i++) {
            int idx = tid + i * 256;
            if (idx < 640) {
                int row = idx / 10, ch = idx % 10;
                const f16* src = khh + ((size_t)bh * 1024 + kt * 64 + row) * QKLD + ch * 8;
                uint32_t dst = smem_u32(kb + row * FQ_ROWB + ch * 16);
                CP_ASYNC16(dst, src);
            } else if (idx < 1216) {
                int cc = idx - 640;
                int row = cc / 8, ch = cc % 8;
                const f16* src = vth + ((size_t)bh * 72 + row) * 1024 + kt * 64 + ch * 8;
                uint32_t dst = smem_u32(vb + row * FV_ROWB + ch * 16);
                CP_ASYNC16(dst, src);
            }
        }
        CP_COMMIT();
    };

    load_kv(0, 0);

    float O[9][4];
    #pragma unroll
    for (int nv = 0; nv < 9; nv++)
        #pragma unroll
        for (int r = 0; r < 4; r++) O[nv][r] = 0.f;
    float m0 = -INFINITY, m1 = -INFINITY, l0 = 0.f, l1 = 0.f;

    for (int kt = 0; kt < 16; kt++) {
        if (kt + 1 < 16) { load_kv(kt + 1, (kt + 1) & 1); CP_WAIT1(); }
        else { CP_WAIT0(); }
        __syncthreads();
        const char* pK = smem + FSM_K0 + (kt & 1) * FSM_KSTG;
        const char* pV = smem + FSM_V0 + (kt & 1) * FSM_VSTG;

        float S[8][4];
        #pragma unroll
        for (int nt = 0; nt < 8; nt++)
            #pragma unroll
            for (int r = 0; r < 4; r++) S[nt][r] = 0.f;

        #pragma unroll
        for (int kk = 0; kk < 5; kk++) {
            uint32_t aH[4], b[2];
            int r0 = (w * 16 + g) * FQ_ROWB + (kk * 16 + t * 2) * 2;
            aH[0] = *(const uint32_t*)(smem + r0);
            aH[1] = *(const uint32_t*)(smem + r0 + 8 * FQ_ROWB);
            aH[2] = *(const uint32_t*)(smem + r0 + 16);
            aH[3] = *(const uint32_t*)(smem + r0 + 8 * FQ_ROWB + 16);
            #pragma unroll
            for (int nt = 0; nt < 8; nt++) {
                int rb = (nt * 8 + g) * FQ_ROWB + (kk * 16 + t * 2) * 2;
                b[0] = *(const uint32_t*)(pK + rb);
                b[1] = *(const uint32_t*)(pK + rb + 16);
                mma16816h(S[nt], aH, b);
            }
        }

        #pragma unroll
        for (int nt = 0; nt < 8; nt++)
            #pragma unroll
            for (int r = 0; r < 4; r++) S[nt][r] *= 0.25f;

        float lm0 = -INFINITY, lm1 = -INFINITY;
        #pragma unroll
        for (int nt = 0; nt < 8; nt++) {
            lm0 = fmaxf(lm0, fmaxf(S[nt][0], S[nt][1]));
            lm1 = fmaxf(lm1, fmaxf(S[nt][2], S[nt][3]));
        }
        lm0 = fmaxf(lm0, __shfl_xor_sync(0xffffffffu, lm0, 1));
        lm0 = fmaxf(lm0, __shfl_xor_sync(0xffffffffu, lm0, 2));
        lm1 = fmaxf(lm1, __shfl_xor_sync(0xffffffffu, lm1, 1));
        lm1 = fmaxf(lm1, __shfl_xor_sync(0xffffffffu, lm1, 2));
        float mn0 = fmaxf(m0, lm0), mn1 = fmaxf(m1, lm1);
        float sc0 = __expf(m0 - mn0), sc1 = __expf(m1 - mn1);
        m0 = mn0; m1 = mn1;
        l0 *= sc0; l1 *= sc1;
        #pragma unroll
        for (int nv = 0; nv < 9; nv++) {
            O[nv][0] *= sc0; O[nv][1] *= sc0;
            O[nv][2] *= sc1; O[nv][3] *= sc1;
        }
        #pragma unroll
        for (int nt = 0; nt < 8; nt++) {
            S[nt][0] = __expf(S[nt][0] - mn0);
            S[nt][1] = __expf(S[nt][1] - mn0);
            S[nt][2] = __expf(S[nt][2] - mn1);
            S[nt][3] = __expf(S[nt][3] - mn1);
            l0 += S[nt][0] + S[nt][1];
            l1 += S[nt][2] + S[nt][3];
        }

        // PV (1-pass, P fp16-rounded)
        #pragma unroll
        for (int ks = 0; ks < 4; ks++) {
            uint32_t pH[4], b[2];
            pH[0] = pack_hi2h(S[2 * ks][0], S[2 * ks][1]);
            pH[1] = pack_hi2h(S[2 * ks][2], S[2 * ks][3]);
            pH[2] = pack_hi2h(S[2 * ks + 1][0], S[2 * ks + 1][1]);
            pH[3] = pack_hi2h(S[2 * ks + 1][2], S[2 * ks + 1][3]);
            #pragma unroll
            for (int nv = 0; nv < 9; nv++) {
                int rb = (nv * 8 + g) * FV_ROWB + (ks * 16 + t * 2) * 2;
                b[0] = *(const uint32_t*)(pV + rb);
                b[1] = *(const uint32_t*)(pV + rb + 16);
                mma16816h(O[nv], pH, b);
            }
        }
        __syncthreads();
    }

    l0 += __shfl_xor_sync(0xffffffffu, l0, 1);
    l0 += __shfl_xor_sync(0xffffffffu, l0, 2);
    l1 += __shfl_xor_sync(0xffffffffu, l1, 1);
    l1 += __shfl_xor_sync(0xffffffffu, l1, 2);
    float r0 = 1.f / l0, r1 = 1.f / l1;
    #pragma unroll
    for (int nv = 0; nv < 9; nv++) {
        O[nv][0] *= r0; O[nv][1] *= r0;
        O[nv][2] *= r1; O[nv][3] *= r1;
    }
    float t0 = __shfl_sync(0xffffffffu, O[0][0], lane & ~3);
    float t1 = __shfl_sync(0xffffffffu, O[0][2], lane & ~3);
    float ss0 = 0.f, ss1 = 0.f;
    #pragma unroll
    for (int nv = 0; nv < 9; nv++) {
        int c = nv * 8 + 2 * t;
        if (c >= 1 && c < 65) { ss0 += O[nv][0] * O[nv][0]; ss1 += O[nv][2] * O[nv][2]; }
        if (c + 1 >= 1 && c + 1 < 65) { ss0 += O[nv][1] * O[nv][1]; ss1 += O[nv][3] * O[nv][3]; }
    }
    ss0 += __shfl_xor_sync(0xffffffffu, ss0, 1);
    ss0 += __shfl_xor_sync(0xffffffffu, ss0, 2);
    ss1 += __shfl_xor_sync(0xffffffffu, ss1, 1);
    ss1 += __shfl_xor_sync(0xffffffffu, ss1, 2);
    float inv0 = rsqrtf(fmaxf(t0 * t0 - ss0, 1e-8f));
    float inv1 = rsqrtf(fmaxf(t1 * t1 - ss1, 1e-8f));

    int b = bh >> 4, h = bh & 15;
    int tr0 = b * 1024 + q0 + w * 16 + g;
    size_t base0 = (size_t)tr0 * 1088 + h * 65;
    size_t base1 = (size_t)(tr0 + 8) * 1088 + h * 65;
    #pragma unroll
    for (int nv = 0; nv < 9; nv++) {
        int c = nv * 8 + 2 * t;
        if (c < 65) {
            cath[base0 + c] = __float2half(O[nv][0] * inv0);
            cath[base1 + c] = __float2half(O[nv][2] * inv1);
        }
        if (c + 1 < 65) {
            cath[base0 + c + 1] = __float2half(O[nv][1] * inv0);
            cath[base1 + c + 1] = __float2half(O[nv][3] * inv1);
        }
    }
}

// ===================== weight transpose -> fp16 =====================
__global__ void k_tsplit_h(const float* __restrict__ W, f16* __restrict__ Th,
                           int K, int N, int Kpad)
{
    __shared__ float t[32][33];
    int nb = blockIdx.x * 32, kb = blockIdx.y * 32;
    int tx = threadIdx.x, ty = threadIdx.y;
    #pragma unroll
    for (int i = 0; i < 32; i += 8) {
        int k = kb + ty + i, n = nb + tx;
        t[ty + i][tx] = (k < K && n < N) ? W[(size_t)k * N + n] : 0.f;
    }
    __syncthreads();
    #pragma unroll
    for (int i = 0; i < 32; i += 8) {
        int n = nb + ty + i, k = kb + tx;
        if (n < N && k < K)
            Th[(size_t)n * Kpad + k] = __float2half(t[tx][ty + i]);
    }
}

// ===================== Lorentz layernorm -> fp16 (hi only) =====================
__global__ __launch_bounds__(256)
void k_ln(const float* __restrict__ x, const float* __restrict__ g,
          const float* __restrict__ b, f16* __restrict__ oh)
{
    __shared__ float sbuf[32];
    int t = blockIdx.x, tid = threadIdx.x;
    const float* xs = x + (size_t)t * 1024 + 1;
    float sv[4]; float s1 = 0.f, s2 = 0.f;
    #pragma unroll
    for (int j = 0; j < 4; j++) {
        int i = tid + j * 256;
        sv[j] = 0.f;
        if (i < 1023) { sv[j] = xs[i]; s1 += sv[j]; s2 += sv[j] * sv[j]; }
    }
    s1 = blk_sum(s1, sbuf);
    s2 = blk_sum(s2, sbuf);
    float mu = s1 * (1.f / 1023.f);
    float var = s2 * (1.f / 1023.f) - mu * mu;
    float rstd = rsqrtf(var + 1e-5f);
    float q = 0.f;
    float yv[4];
    #pragma unroll
    for (int j = 0; j < 4; j++) {
        int i = tid + j * 256;
        yv[j] = 0.f;
        if (i < 1023) {
            yv[j] = (sv[j] - mu) * rstd * g[i] + b[i];
            q += yv[j] * yv[j];
        }
    }
    q = blk_sum(q, sbuf);
    size_t base = (size_t)t * 1024;
    #pragma unroll
    for (int j = 0; j < 4; j++) {
        int i = tid + j * 256;
        if (i < 1023) oh[base + 1 + i] = __float2half(yv[j]);
    }
    if (tid == 0) oh[base] = __float2half(sqrtf(q + 1.f));
}

// ===================== lift heads (hi only) =====================
__global__ __launch_bounds__(512)
void k_lift(const float* __restrict__ S, f16* __restrict__ Oh, float sign)
{
    int t = blockIdx.x;
    int b = t >> 10, n = t & 1023;
    int w = threadIdx.x >> 5, lane = threadIdx.x & 31;
    const float* src = S + (size_t)t * 1024 + w * 64;
    float v0 = src[lane], v1 = src[lane + 32];
    float ss = v0 * v0 + v1 * v1;
    #pragma unroll
    for (int o = 16; o > 0; o >>= 1) ss += __shfl_down_sync(0xffffffffu, ss, o);
    ss = __shfl_sync(0xffffffffu, ss, 0);
    size_t base = ((size_t)(b * HH + w) * 1024 + n) * QKLD;
    Oh[base + 1 + lane] = __float2half(v0);
    Oh[base + 33 + lane] = __float2half(v1);
    if (lane == 0) Oh[base] = __float2half(sign * sqrtf(ss + 1.f));
    for (int i = 65 + lane; i < QKLD; i += 32) Oh[base + i] = __float2half(0.f);
}

// ===================== lift+transpose v -> fp16 (BH,72,1024) =====================
__global__ void k_liftT(const float* __restrict__ vs, f16* __restrict__ Th)
{
    int blk = blockIdx.x;
    int bh = blk >> 5;
    int tg = blk & 31;
    int b = bh >> 4, h = bh & 15;
    __shared__ float sv[32][65];
    __shared__ float stime[32];
    int tx = threadIdx.x, ty = threadIdx.y;
    #pragma unroll
    for (int i = 0; i < 32; i += 8) {
        int tok = i + ty;
        const float* src = vs + (size_t)(b * 1024 + tg * 32 + tok) * 1024 + h * 64;
        sv[tok][1 + tx] = src[tx];
        sv[tok][33 + tx] = src[tx + 32];
    }
    __syncthreads();
    if (ty == 0) {
        float s = 0.f;
        #pragma unroll
        for (int d = 1; d <= 64; d++) { float x = sv[tx][d]; s += x * x; }
        stime[tx] = sqrtf(s + 1.f);
    }
    __syncthreads();
    size_t base = (size_t)bh * (72 * 1024) + (size_t)(tg * 32);
    for (int d = ty; d < 72; d += 8) {
        float v = (d == 0) ? stime[tx] : (d < 65 ? sv[tx][d] : 0.f);
        Th[base + (size_t)d * 1024 + tx] = __float2half(v);
    }
}

// ===================== Lorentz residual =====================
__global__ __launch_bounds__(256)
void k_lresnet(const float* __restrict__ xin, const float* __restrict__ spart,
               const float* __restrict__ wp, float* __restrict__ out)
{
    __shared__ float sbuf[32];
    int t = blockIdx.x, tid = threadIdx.x;
    float w = wp[0];
    const float* xr = xin + (size_t)t * 1024;
    const float* ar = spart + (size_t)t * 1023;
    float xs[4], as[4];
    float sa = 0.f;
    #pragma unroll
    for (int j = 0; j < 4; j++) {
        int i = tid + j * 256;
        xs[j] = 0.f; as[j] = 0.f;
        if (i < 1023) { xs[j] = xr[1 + i]; as[j] = ar[i]; sa += as[j] * as[j]; }
    }
    sa = blk_sum(sa, sbuf);
    float axt = sqrtf(sa + 1.f);
    float zt = xr[0] + w * axt;
    float sz = 0.f;
    #pragma unroll
    for (int j = 0; j < 4; j++) {
        int i = tid + j * 256;
        if (i < 1023) { xs[j] = xs[j] + w * as[j]; sz += xs[j] * xs[j]; }
    }
    sz = blk_sum(sz, sbuf);
    float inv = rsqrtf(fmaxf(zt * zt - sz, 1e-8f));
    if (tid == 0) out[(size_t)t * 1024] = zt * inv;
    #pragma unroll
    for (int j = 0; j < 4; j++) {
        int i = tid + j * 256;
        if (i < 1023) out[(size_t)t * 1024 + 1 + i] = xs[j] * inv;
    }
}

// ===================== host =====================
extern "C" void kernel_launch(void* const* d_in, const int* in_sizes, int n_in,
                              void* d_out, int out_size)
{
    const float* x   = (const float*)d_in[0];
    const float* g1  = (const float*)d_in[1];
    const float* b1  = (const float*)d_in[2];
    const float* Wq  = (const float*)d_in[3];
    const float* bq  = (const float*)d_in[4];
    const float* Wk  = (const float*)d_in[5];
    const float* bk  = (const float*)d_in[6];
    const float* Wv  = (const float*)d_in[7];
    const float* bv  = (const float*)d_in[8];
    const float* Wo  = (const float*)d_in[9];
    const float* bo  = (const float*)d_in[10];
    const float* g2  = (const float*)d_in[11];
    const float* b2  = (const float*)d_in[12];
    const float* Wfc = (const float*)d_in[13];
    const float* bfc = (const float*)d_in[14];
    const float* Wpj = (const float*)d_in[15];
    const float* bpj = (const float*)d_in[16];
    const float* w1  = (const float*)d_in[17];
    const float* w2  = (const float*)d_in[18];
    float* out = (float*)d_out;

    cudaFuncSetAttribute(gemm1p<64>, cudaFuncAttributeMaxDynamicSharedMemorySize, SMEM_1P64);
    cudaFuncSetAttribute(gemm1p_gelu, cudaFuncAttributeMaxDynamicSharedMemorySize, SMEM_1P64);
    cudaFuncSetAttribute(flash_attn, cudaFuncAttributeMaxDynamicSharedMemorySize, FSM_TOTAL);

    #define SYM(p, s) do { void* _t; cudaGetSymbolAddress(&_t, s); p = decltype(p)(_t); } while (0)
    f16 *lxh, *WqTh, *WkTh, *WvTh, *WoTh, *WfcTh, *WpjTh;
    f16 *qhh, *khh, *vTh, *cath, *h1h, *fch;
    float *qs, *ks, *vs, *axs, *x1, *qsum, *pjs;
    SYM(lxh, g_lxh);
    SYM(WqTh, g_WqTh); SYM(WkTh, g_WkTh); SYM(WvTh, g_WvTh);
    SYM(WoTh, g_WoTh);
    SYM(WfcTh, g_WfcTh); SYM(WpjTh, g_WpjTh);
    SYM(qs, g_qs); SYM(ks, g_ks); SYM(vs, g_vs);
    SYM(qhh, g_qhh); SYM(khh, g_khh);
    SYM(vTh, g_vTh);
    SYM(cath, g_cath);
    SYM(axs, g_axs); SYM(x1, g_x1); SYM(h1h, g_h1h);
    SYM(fch, g_fch); SYM(qsum, g_qsum); SYM(pjs, g_pjs);

    dim3 tb(32, 8);
    k_tsplit_h<<<dim3(32, 32), tb>>>(Wq, WqTh, 1024, 1024, 1024);
    k_tsplit_h<<<dim3(32, 32), tb>>>(Wk, WkTh, 1024, 1024, 1024);
    k_tsplit_h<<<dim3(32, 32), tb>>>(Wv, WvTh, 1024, 1024, 1024);
    k_tsplit_h<<<dim3(32, 33), tb>>>(Wo, WoTh, 1040, 1023, 1088);
    k_ln<<<TT, 256>>>(x, g1, b1, lxh);

    // QKV: fp16 1-pass
    {
        dim3 grid(8, 32, 1);
        gemm1p<64><<<grid, 256, SMEM_1P64>>>(lxh, WqTh, bq, qs, 1024, 1024, 1024, 1024, 1024);
        gemm1p<64><<<grid, 256, SMEM_1P64>>>(lxh, WkTh, bk, ks, 1024, 1024, 1024, 1024, 1024);
        gemm1p<64><<<grid, 256, SMEM_1P64>>>(lxh, WvTh, bv, vs, 1024, 1024, 1024, 1024, 1024);
    }

    // remaining weight transposes + qsum zero
    k_tsplit_h<<<dim3(128, 32), tb>>>(Wfc, WfcTh, 1024, 4095, 1024);
    k_tsplit_h<<<dim3(32, 128), tb>>>(Wpj, WpjTh, 4096, 1023, 4096);
    k_zero<<<TT / 256, 256>>>(qsum, TT);

    // lifts
    k_lift<<<TT, 512>>>(qs, qhh, -1.f);
    k_lift<<<TT, 512>>>(ks, khh, 1.f);
    k_liftT<<<BHN * 32, tb>>>(vs, vTh);

    // fused flash attention -> cat
    flash_attn<<<dim3(8, BHN), 256, FSM_TOTAL>>>(qhh, khh, vTh, cath);

    // Wo: fp16 1-pass
    gemm1p<64><<<dim3(8, 32, 1), 256, SMEM_1P64>>>(cath, WoTh, bo, axs,
        1088, 1088, 1023, 1023, 1088);

    // residual 1
    k_lresnet<<<TT, 256>>>(x, axs, w1, x1);

    // LN2
    k_ln<<<TT, 256>>>(x1, g2, b2, h1h);

    // Wfc with fused GELU -> fch (+ row sums), then time column
    gemm1p_gelu<<<dim3(32, 32, 1), 256, SMEM_1P64>>>(h1h, WfcTh, bfc, fch, qsum,
        1024, 1024, 4095, 1024);
    k_time<<<TT / 256, 256>>>(qsum, fch);

    // Wpj: fp16 1-pass
    gemm1p<64><<<dim3(8, 32, 1), 256, SMEM_1P64>>>(fch, WpjTh, bpj, pjs,
        4096, 4096, 1023, 1023, 4096);

    // residual 2
    k_lresnet<<<TT, 256>>>(x1, pjs, w2, out);
}

// round 13
// speedup vs baseline: 4.4004x; 1.0571x over previous
#include <cuda_runtime.h>
#include <cuda_bf16.h>
#include <cuda_fp16.h>
#include <math.h>
#include <stdint.h>

// Problem constants
#define BB 4
#define NNTOK 1024
#define DDIM 1024
#define HH 16
#define TT (BB*NNTOK)     // 4096 tokens
#define BHN (BB*HH)       // 64
#define QKLD 80           // padded lifted q/k leading dim (65 -> 80)

typedef __half f16;

// ===================== scratch (device globals; zero-initialized at load) =====================
__device__ __align__(128) f16   g_lxh [TT*1024];
__device__ __align__(128) f16   g_WqTh[1024*1024];
__device__ __align__(128) f16   g_WkTh[1024*1024];
__device__ __align__(128) f16   g_WvTh[1024*1024];
__device__ __align__(128) f16   g_WoTh[1024*1088];
__device__ __align__(128) f16   g_WfcTh[4096*1024];
__device__ __align__(128) f16   g_WpjTh[1024*4096];
__device__ __align__(128) f16   g_vs16[TT*1024];
__device__ __align__(128) f16   g_qhh [(size_t)BHN*1024*QKLD];  // pads 65..79 stay zero
__device__ __align__(128) f16   g_khh [(size_t)BHN*1024*QKLD];
__device__ __align__(128) f16   g_vTh [(size_t)BHN*72*1024];
__device__ __align__(128) f16   g_cath[TT*1088];
__device__ __align__(128) float g_axs [TT*1023];
__device__ __align__(128) float g_x1  [TT*1024];
__device__ __align__(128) f16   g_h1h [TT*1024];
__device__ __align__(128) f16   g_fch [(size_t)TT*4096];
__device__ __align__(128) float g_qsum[TT];
__device__ __align__(128) float g_pjs [TT*1023];

// ===================== PTX helpers =====================
__device__ __forceinline__ uint32_t smem_u32(const void* p) {
    uint32_t a;
    asm("{ .reg .u64 t; cvta.to.shared.u64 t, %1; cvt.u32.u64 %0, t; }" : "=r"(a) : "l"(p));
    return a;
}

#define CP_ASYNC16(dst, src) \
    asm volatile("cp.async.cg.shared.global [%0], [%1], 16;" :: "r"(dst), "l"(src))
#define CP_COMMIT() asm volatile("cp.async.commit_group;")
#define CP_WAIT1()  asm volatile("cp.async.wait_group 1;")
#define CP_WAIT0()  asm volatile("cp.async.wait_group 0;")

__device__ __forceinline__ void mma16816h(float* c, const uint32_t* a, const uint32_t* b) {
    asm volatile(
        "mma.sync.aligned.m16n8k16.row.col.f32.f16.f16.f32 "
        "{%0,%1,%2,%3}, {%4,%5,%6,%7}, {%8,%9}, {%0,%1,%2,%3};"
        : "+f"(c[0]), "+f"(c[1]), "+f"(c[2]), "+f"(c[3])
        : "r"(a[0]), "r"(a[1]), "r"(a[2]), "r"(a[3]), "r"(b[0]), "r"(b[1]));
}

__device__ __forceinline__ uint32_t pack_hi2h(float a, float b) {
    __half2 r = __floats2half2_rn(a, b);
    return *(uint32_t*)&r;
}

// ===================== block reductions =====================
__device__ __forceinline__ float blk_sum(float v, float* sbuf) {
    int tid = threadIdx.x;
    #pragma unroll
    for (int o = 16; o > 0; o >>= 1) v += __shfl_down_sync(0xffffffffu, v, o);
    if ((tid & 31) == 0) sbuf[tid >> 5] = v;
    __syncthreads();
    if (tid < 32) {
        int nw = (blockDim.x + 31) >> 5;
        float x = (tid < nw) ? sbuf[tid] : 0.f;
        #pragma unroll
        for (int o = 16; o > 0; o >>= 1) x += __shfl_down_sync(0xffffffffu, x, o);
        if (tid == 0) sbuf[0] = x;
    }
    __syncthreads();
    float r = sbuf[0];
    __syncthreads();
    return r;
}

// ===================== shared GEMM mainloop pieces =====================
#define GEMM_KC 64
#define GEMM_ROWB 144
#define GEMM_STGMAT (128*GEMM_ROWB)
#define GEMM_STGSZ (2*GEMM_STGMAT)
#define SMEM_1P64 (2*GEMM_STGSZ)   // 73728

// Mainloop macro body shared across the three epilogue variants.
// Produces acc[2][8][4] for warp tile (wm rows x wn+64 cols).
#define GEMM_MAINLOOP(Ah, Bh, lda, ldb, K)                                          \
    constexpr int KC = GEMM_KC;                                                     \
    constexpr int ROWB = GEMM_ROWB;                                                 \
    constexpr int STG_MAT = GEMM_STGMAT;                                            \
    constexpr int STG_SZ = GEMM_STGSZ;                                              \
    constexpr int CPR = KC / 8;                                                     \
    constexpr int LPT = KC / 8;                                                     \
    extern __shared__ char smem[];                                                  \
    int tid = threadIdx.x, w = tid >> 5, lane = tid & 31;                           \
    int m0 = blockIdx.y * 128, n0 = blockIdx.x * 128;                               \
    const int NC = (K) / KC;                                                        \
    auto load_stage = [&](int kofs, int s) {                                        \
        char* stg = smem + s * STG_SZ;                                              \
        _Pragma("unroll")                                                           \
        for (int i = 0; i < LPT; i++) {                                             \
            int idx = tid + i * 256;                                                \
            int mat = idx / (16 * KC);                                              \
            int cc  = idx % (16 * KC);                                              \
            int row = cc / CPR, kc = cc % CPR;                                      \
            uint32_t dst = smem_u32(stg + mat * STG_MAT + row * ROWB + kc * 16);    \
            const f16* p = (mat == 0) ? (Ah) : (Bh);                                \
            int b0 = (mat == 0) ? m0 : n0;                                          \
            int ld = (mat == 0) ? (lda) : (ldb);                                    \
            CP_ASYNC16(dst, p + (size_t)(b0 + row) * ld + kofs + kc * 8);           \
        }                                                                           \
        CP_COMMIT();                                                                \
    };                                                                              \
    load_stage(0, 0);                                                               \
    if (NC > 1) load_stage(KC, 1);                                                  \
    int g = lane >> 2, t = lane & 3;                                                \
    int wm = (w & 3) * 32, wn = (w >> 2) * 64;                                      \
    float acc[2][8][4];                                                             \
    _Pragma("unroll")                                                               \
    for (int mt = 0; mt < 2; mt++)                                                  \
        _Pragma("unroll")                                                           \
        for (int nt = 0; nt < 8; nt++)                                              \
            _Pragma("unroll")                                                       \
            for (int r = 0; r < 4; r++) acc[mt][nt][r] = 0.f;                       \
    for (int kc = 0; kc < NC; kc++) {                                               \
        if (kc + 1 < NC) { CP_WAIT1(); } else { CP_WAIT0(); }                       \
        __syncthreads();                                                            \
        const char* stg = smem + (kc & 1) * STG_SZ;                                 \
        const char* pAh = stg;                                                      \
        const char* pBh = stg + STG_MAT;                                            \
        _Pragma("unroll")                                                           \
        for (int ko = 0; ko < KC; ko += 16) {                                       \
            uint32_t aH[2][4], b[8][2];                                             \
            _Pragma("unroll")                                                       \
            for (int mt = 0; mt < 2; mt++) {                                        \
                int r0 = (wm + mt * 16 + g) * ROWB + (ko + t * 2) * 2;              \
                aH[mt][0] = *(const uint32_t*)(pAh + r0);                           \
                aH[mt][1] = *(const uint32_t*)(pAh + r0 + 8 * ROWB);                \
                aH[mt][2] = *(const uint32_t*)(pAh + r0 + 16);                      \
                aH[mt][3] = *(const uint32_t*)(pAh + r0 + 8 * ROWB + 16);           \
            }                                                                       \
            _Pragma("unroll")                                                       \
            for (int nt = 0; nt < 8; nt++) {                                        \
                int r0 = (wn + nt * 8 + g) * ROWB + (ko + t * 2) * 2;               \
                b[nt][0] = *(const uint32_t*)(pBh + r0);                            \
                b[nt][1] = *(const uint32_t*)(pBh + r0 + 16);                       \
            }                                                                       \
            _Pragma("unroll")                                                       \
            for (int mt = 0; mt < 2; mt++)                                          \
                _Pragma("unroll")                                                   \
                for (int nt = 0; nt < 8; nt++)                                      \
                    mma16816h(acc[mt][nt], aH[mt], b[nt]);                          \
        }                                                                           \
        __syncthreads();                                                            \
        if (kc + 2 < NC) load_stage((kc + 2) * KC, kc & 1);                         \
    }

// ===================== fp16 1-pass GEMM, templated output type =====================
template<typename OutT>
__global__ __launch_bounds__(256)
void gemm1p(const f16* __restrict__ Ah, const f16* __restrict__ Bh,
            const float* __restrict__ bias, OutT* __restrict__ C,
            int lda, int ldb, int ldc, int Nreal, int K)
{
    GEMM_MAINLOOP(Ah, Bh, lda, ldb, K)

    #pragma unroll
    for (int mt = 0; mt < 2; mt++) {
        int r0 = m0 + wm + mt * 16 + g;
        OutT* c0p = C + (size_t)r0 * ldc;
        OutT* c1p = C + (size_t)(r0 + 8) * ldc;
        #pragma unroll
        for (int nt = 0; nt < 8; nt++) {
            int n = n0 + wn + nt * 8 + t * 2;
            if (n < Nreal) {
                float bv = bias ? bias[n] : 0.f;
                c0p[n] = (OutT)(acc[mt][nt][0] + bv);
                c1p[n] = (OutT)(acc[mt][nt][2] + bv);
            }
            if (n + 1 < Nreal) {
                float bv = bias ? bias[n + 1] : 0.f;
                c0p[n + 1] = (OutT)(acc[mt][nt][1] + bv);
                c1p[n + 1] = (OutT)(acc[mt][nt][3] + bv);
            }
        }
    }
}

// ===================== QKV GEMM with fused head-lift epilogue =====================
// Out layout: ((b*HH + h)*1024 + tok)*QKLD ; h = n/64, d = n%64 -> offset 1+d; time at 0.
__global__ __launch_bounds__(256)
void gemm1p_lift(const f16* __restrict__ Ah, const f16* __restrict__ Bh,
                 const float* __restrict__ bias, f16* __restrict__ Out,
                 float sign)
{
    GEMM_MAINLOOP(Ah, Bh, 1024, 1024, 1024)

    int h = (n0 + wn) >> 6;
    #pragma unroll
    for (int mt = 0; mt < 2; mt++) {
        int row = m0 + wm + mt * 16 + g;         // rows: row, row+8
        float v[2][16];
        float s0 = 0.f, s1 = 0.f;
        #pragma unroll
        for (int nt = 0; nt < 8; nt++) {
            int n = n0 + wn + nt * 8 + t * 2;
            float b0v = bias ? bias[n] : 0.f;
            float b1v = bias ? bias[n + 1] : 0.f;
            v[0][2 * nt]     = acc[mt][nt][0] + b0v;
            v[0][2 * nt + 1] = acc[mt][nt][1] + b1v;
            v[1][2 * nt]     = acc[mt][nt][2] + b0v;
            v[1][2 * nt + 1] = acc[mt][nt][3] + b1v;
            s0 += v[0][2 * nt] * v[0][2 * nt] + v[0][2 * nt + 1] * v[0][2 * nt + 1];
            s1 += v[1][2 * nt] * v[1][2 * nt] + v[1][2 * nt + 1] * v[1][2 * nt + 1];
        }
        s0 += __shfl_xor_sync(0xffffffffu, s0, 1);
        s0 += __shfl_xor_sync(0xffffffffu, s0, 2);
        s1 += __shfl_xor_sync(0xffffffffu, s1, 1);
        s1 += __shfl_xor_sync(0xffffffffu, s1, 2);
        #pragma unroll
        for (int rr = 0; rr < 2; rr++) {
            int r = row + rr * 8;
            int b = r >> 10, tok = r & 1023;
            size_t base = ((size_t)(b * HH + h) * 1024 + tok) * QKLD;
            #pragma unroll
            for (int nt = 0; nt < 8; nt++) {
                int d = nt * 8 + t * 2;
                Out[base + 1 + d] = __float2half(v[rr][2 * nt]);
                Out[base + 2 + d] = __float2half(v[rr][2 * nt + 1]);
            }
            if (t == 0)
                Out[base] = __float2half(sign * sqrtf((rr ? s1 : s0) + 1.f));
        }
    }
}

// ===================== Wfc GEMM with fused GELU + row sum-of-squares =====================
__global__ __launch_bounds__(256)
void gemm1p_gelu(const f16* __restrict__ Ah, const f16* __restrict__ Bh,
                 const float* __restrict__ bias, f16* __restrict__ Cf,
                 float* __restrict__ qsum, int Nreal)
{
    GEMM_MAINLOOP(Ah, Bh, 1024, 1024, 1024)

    #pragma unroll
    for (int mt = 0; mt < 2; mt++) {
        int r0 = m0 + wm + mt * 16 + g;
        f16* c0p = Cf + (size_t)r0 * 4096 + 1;
        f16* c1p = Cf + (size_t)(r0 + 8) * 4096 + 1;
        float s0 = 0.f, s1 = 0.f;
        #pragma unroll
        for (int nt = 0; nt < 8; nt++) {
            int n = n0 + wn + nt * 8 + t * 2;
            if (n < Nreal) {
                float bv = bias[n];
                float v0 = acc[mt][nt][0] + bv;
                float v2 = acc[mt][nt][2] + bv;
                float g0 = 0.5f * v0 * (1.f + erff(v0 * 0.70710678118654752f));
                float g2 = 0.5f * v2 * (1.f + erff(v2 * 0.70710678118654752f));
                c0p[n] = __float2half(g0); s0 += g0 * g0;
                c1p[n] = __float2half(g2); s1 += g2 * g2;
            }
            if (n + 1 < Nreal) {
                float bv = bias[n + 1];
                float v1 = acc[mt][nt][1] + bv;
                float v3 = acc[mt][nt][3] + bv;
                float g1 = 0.5f * v1 * (1.f + erff(v1 * 0.70710678118654752f));
                float g3 = 0.5f * v3 * (1.f + erff(v3 * 0.70710678118654752f));
                c0p[n + 1] = __float2half(g1); s0 += g1 * g1;
                c1p[n + 1] = __float2half(g3); s1 += g3 * g3;
            }
        }
        s0 += __shfl_xor_sync(0xffffffffu, s0, 1);
        s0 += __shfl_xor_sync(0xffffffffu, s0, 2);
        s1 += __shfl_xor_sync(0xffffffffu, s1, 1);
        s1 += __shfl_xor_sync(0xffffffffu, s1, 2);
        if (t == 0) {
            atomicAdd(&qsum[r0], s0);
            atomicAdd(&qsum[r0 + 8], s1);
        }
    }
}

__global__ void k_zero(float* __restrict__ p, int n) {
    int i = blockIdx.x * 256 + threadIdx.x;
    if (i < n) p[i] = 0.f;
}
__global__ void k_time(const float* __restrict__ qsum, f16* __restrict__ fch) {
    int i = blockIdx.x * 256 + threadIdx.x;
    if (i < TT) fch[(size_t)i * 4096] = __float2half(sqrtf(qsum[i] + 1.f));
}

// ===================== fused flash attention (fp16 1-pass) =====================
#define FQ_ROWB 176
#define FV_ROWB 144
#define FSM_QMAT (128*FQ_ROWB)
#define FSM_K0   FSM_QMAT
#define FSM_KSTG (64*FQ_ROWB)
#define FSM_V0   (FSM_K0 + 2*FSM_KSTG)
#define FSM_VSTG (72*FV_ROWB)
#define FSM_TOTAL (FSM_V0 + 2*FSM_VSTG)   // 65792

__global__ __launch_bounds__(256)
void flash_attn(const f16* __restrict__ qhh,
                const f16* __restrict__ khh,
                const f16* __restrict__ vth,
                f16* __restrict__ cath)
{
    extern __shared__ char smem[];
    int tid = threadIdx.x, w = tid >> 5, lane = tid & 31;
    int g = lane >> 2, t = lane & 3;
    int bh = blockIdx.y;
    int q0 = blockIdx.x * 128;

    {
        #pragma unroll
        for (int i = 0; i < 5; i++) {
            int idx = tid + i * 256;
            int row = idx / 10, ch = idx % 10;
            const f16* src = qhh + ((size_t)bh * 1024 + q0 + row) * QKLD + ch * 8;
            uint32_t dst = smem_u32(smem + row * FQ_ROWB + ch * 16);
            CP_ASYNC16(dst, src);
        }
        CP_COMMIT();
    }

    auto load_kv = [&](int kt, int s) {
        char* kb = smem + FSM_K0 + s * FSM_KSTG;
        char* vb = smem + FSM_V0 + s * FSM_VSTG;
        #pragma unroll
        for (int i = 0; i < 5; i++) {
            int idx = tid + i * 256;
            if (idx < 640) {
                int row = idx / 10, ch = idx % 10;
                const f16* src = khh + ((size_t)bh * 1024 + kt * 64 + row) * QKLD + ch * 8;
                uint32_t dst = smem_u32(kb + row * FQ_ROWB + ch * 16);
                CP_ASYNC16(dst, src);
            } else if (idx < 1216) {
                int cc = idx - 640;
                int row = cc / 8, ch = cc % 8;
                const f16* src = vth + ((size_t)bh * 72 + row) * 1024 + kt * 64 + ch * 8;
                uint32_t dst = smem_u32(vb + row * FV_ROWB + ch * 16);
                CP_ASYNC16(dst, src);
            }
        }
        CP_COMMIT();
    };

    load_kv(0, 0);

    float O[9][4];
    #pragma unroll
    for (int nv = 0; nv < 9; nv++)
        #pragma unroll
        for (int r = 0; r < 4; r++) O[nv][r] = 0.f;
    float m0 = -INFINITY, m1 = -INFINITY, l0 = 0.f, l1 = 0.f;

    for (int kt = 0; kt < 16; kt++) {
        if (kt + 1 < 16) { load_kv(kt + 1, (kt + 1) & 1); CP_WAIT1(); }
        else { CP_WAIT0(); }
        __syncthreads();
        const char* pK = smem + FSM_K0 + (kt & 1) * FSM_KSTG;
        const char* pV = smem + FSM_V0 + (kt & 1) * FSM_VSTG;

        float S[8][4];
        #pragma unroll
        for (int nt = 0; nt < 8; nt++)
            #pragma unroll
            for (int r = 0; r < 4; r++) S[nt][r] = 0.f;

        #pragma unroll
        for (int kk = 0; kk < 5; kk++) {
            uint32_t aH[4], b[2];
            int r0 = (w * 16 + g) * FQ_ROWB + (kk * 16 + t * 2) * 2;
            aH[0] = *(const uint32_t*)(smem + r0);
            aH[1] = *(const uint32_t*)(smem + r0 + 8 * FQ_ROWB);
            aH[2] = *(const uint32_t*)(smem + r0 + 16);
            aH[3] = *(const uint32_t*)(smem + r0 + 8 * FQ_ROWB + 16);
            #pragma unroll
            for (int nt = 0; nt < 8; nt++) {
                int rb = (nt * 8 + g) * FQ_ROWB + (kk * 16 + t * 2) * 2;
                b[0] = *(const uint32_t*)(pK + rb);
                b[1] = *(const uint32_t*)(pK + rb + 16);
                mma16816h(S[nt], aH, b);
            }
        }

        #pragma unroll
        for (int nt = 0; nt < 8; nt++)
            #pragma unroll
            for (int r = 0; r < 4; r++) S[nt][r] *= 0.25f;

        float lm0 = -INFINITY, lm1 = -INFINITY;
        #pragma unroll
        for (int nt = 0; nt < 8; nt++) {
            lm0 = fmaxf(lm0, fmaxf(S[nt][0], S[nt][1]));
            lm1 = fmaxf(lm1, fmaxf(S[nt][2], S[nt][3]));
        }
        lm0 = fmaxf(lm0, __shfl_xor_sync(0xffffffffu, lm0, 1));
        lm0 = fmaxf(lm0, __shfl_xor_sync(0xffffffffu, lm0, 2));
        lm1 = fmaxf(lm1, __shfl_xor_sync(0xffffffffu, lm1, 1));
        lm1 = fmaxf(lm1, __shfl_xor_sync(0xffffffffu, lm1, 2));
        float mn0 = fmaxf(m0, lm0), mn1 = fmaxf(m1, lm1);
        float sc0 = __expf(m0 - mn0), sc1 = __expf(m1 - mn1);
        m0 = mn0; m1 = mn1;
        l0 *= sc0; l1 *= sc1;
        #pragma unroll
        for (int nv = 0; nv < 9; nv++) {
            O[nv][0] *= sc0; O[nv][1] *= sc0;
            O[nv][2] *= sc1; O[nv][3] *= sc1;
        }
        #pragma unroll
        for (int nt = 0; nt < 8; nt++) {
            S[nt][0] = __expf(S[nt][0] - mn0);
            S[nt][1] = __expf(S[nt][1] - mn0);
            S[nt][2] = __expf(S[nt][2] - mn1);
            S[nt][3] = __expf(S[nt][3] - mn1);
            l0 += S[nt][0] + S[nt][1];
            l1 += S[nt][2] + S[nt][3];
        }

        #pragma unroll
        for (int ks = 0; ks < 4; ks++) {
            uint32_t pH[4], b[2];
            pH[0] = pack_hi2h(S[2 * ks][0], S[2 * ks][1]);
            pH[1] = pack_hi2h(S[2 * ks][2], S[2 * ks][3]);
            pH[2] = pack_hi2h(S[2 * ks + 1][0], S[2 * ks + 1][1]);
            pH[3] = pack_hi2h(S[2 * ks + 1][2], S[2 * ks + 1][3]);
            #pragma unroll
            for (int nv = 0; nv < 9; nv++) {
                int rb = (nv * 8 + g) * FV_ROWB + (ks * 16 + t * 2) * 2;
                b[0] = *(const uint32_t*)(pV + rb);
                b[1] = *(const uint32_t*)(pV + rb + 16);
                mma16816h(O[nv], pH, b);
            }
        }
        __syncthreads();
    }

    l0 += __shfl_xor_sync(0xffffffffu, l0, 1);
    l0 += __shfl_xor_sync(0xffffffffu, l0, 2);
    l1 += __shfl_xor_sync(0xffffffffu, l1, 1);
    l1 += __shfl_xor_sync(0xffffffffu, l1, 2);
    float r0 = 1.f / l0, r1 = 1.f / l1;
    #pragma unroll
    for (int nv = 0; nv < 9; nv++) {
        O[nv][0] *= r0; O[nv][1] *= r0;
        O[nv][2] *= r1; O[nv][3] *= r1;
    }
    float t0 = __shfl_sync(0xffffffffu, O[0][0], lane & ~3);
    float t1 = __shfl_sync(0xffffffffu, O[0][2], lane & ~3);
    float ss0 = 0.f, ss1 = 0.f;
    #pragma unroll
    for (int nv = 0; nv < 9; nv++) {
        int c = nv * 8 + 2 * t;
        if (c >= 1 && c < 65) { ss0 += O[nv][0] * O[nv][0]; ss1 += O[nv][2] * O[nv][2]; }
        if (c + 1 >= 1 && c + 1 < 65) { ss0 += O[nv][1] * O[nv][1]; ss1 += O[nv][3] * O[nv][3]; }
    }
    ss0 += __shfl_xor_sync(0xffffffffu, ss0, 1);
    ss0 += __shfl_xor_sync(0xffffffffu, ss0, 2);
    ss1 += __shfl_xor_sync(0xffffffffu, ss1, 1);
    ss1 += __shfl_xor_sync(0xffffffffu, ss1, 2);
    float inv0 = rsqrtf(fmaxf(t0 * t0 - ss0, 1e-8f));
    float inv1 = rsqrtf(fmaxf(t1 * t1 - ss1, 1e-8f));

    int b = bh >> 4, h = bh & 15;
    int tr0 = b * 1024 + q0 + w * 16 + g;
    size_t base0 = (size_t)tr0 * 1088 + h * 65;
    size_t base1 = (size_t)(tr0 + 8) * 1088 + h * 65;
    #pragma unroll
    for (int nv = 0; nv < 9; nv++) {
        int c = nv * 8 + 2 * t;
        if (c < 65) {
            cath[base0 + c] = __float2half(O[nv][0] * inv0);
            cath[base1 + c] = __float2half(O[nv][2] * inv1);
        }
        if (c + 1 < 65) {
            cath[base0 + c + 1] = __float2half(O[nv][1] * inv0);
            cath[base1 + c + 1] = __float2half(O[nv][3] * inv1);
        }
    }
}

// ===================== weight transpose -> fp16 =====================
__global__ void k_tsplit_h(const float* __restrict__ W, f16* __restrict__ Th,
                           int K, int N, int Kpad)
{
    __shared__ float t[32][33];
    int nb = blockIdx.x * 32, kb = blockIdx.y * 32;
    int tx = threadIdx.x, ty = threadIdx.y;
    #pragma unroll
    for (int i = 0; i < 32; i += 8) {
        int k = kb + ty + i, n = nb + tx;
        t[ty + i][tx] = (k < K && n < N) ? W[(size_t)k * N + n] : 0.f;
    }
    __syncthreads();
    #pragma unroll
    for (int i = 0; i < 32; i += 8) {
        int n = nb + ty + i, k = kb + tx;
        if (n < N && k < K)
            Th[(size_t)n * Kpad + k] = __float2half(t[tx][ty + i]);
    }
}

// ===================== Lorentz layernorm -> fp16 (hi only) =====================
__global__ __launch_bounds__(256)
void k_ln(const float* __restrict__ x, const float* __restrict__ g,
          const float* __restrict__ b, f16* __restrict__ oh)
{
    __shared__ float sbuf[32];
    int t = blockIdx.x, tid = threadIdx.x;
    const float* xs = x + (size_t)t * 1024 + 1;
    float sv[4]; float s1 = 0.f, s2 = 0.f;
    #pragma unroll
    for (int j = 0; j < 4; j++) {
        int i = tid + j * 256;
        sv[j] = 0.f;
        if (i < 1023) { sv[j] = xs[i]; s1 += sv[j]; s2 += sv[j] * sv[j]; }
    }
    s1 = blk_sum(s1, sbuf);
    s2 = blk_sum(s2, sbuf);
    float mu = s1 * (1.f / 1023.f);
    float var = s2 * (1.f / 1023.f) - mu * mu;
    float rstd = rsqrtf(var + 1e-5f);
    float q = 0.f;
    float yv[4];
    #pragma unroll
    for (int j = 0; j < 4; j++) {
        int i = tid + j * 256;
        yv[j] = 0.f;
        if (i < 1023) {
            yv[j] = (sv[j] - mu) * rstd * g[i] + b[i];
            q += yv[j] * yv[j];
        }
    }
    q = blk_sum(q, sbuf);
    size_t base = (size_t)t * 1024;
    #pragma unroll
    for (int j = 0; j < 4; j++) {
        int i = tid + j * 256;
        if (i < 1023) oh[base + 1 + i] = __float2half(yv[j]);
    }
    if (tid == 0) oh[base] = __float2half(sqrtf(q + 1.f));
}

// ===================== lift+transpose v (fp16 in) -> (BH,72,1024) =====================
__global__ void k_liftT(const f16* __restrict__ vs, f16* __restrict__ Th)
{
    int blk = blockIdx.x;
    int bh = blk >> 5;
    int tg = blk & 31;
    int b = bh >> 4, h = bh & 15;
    __shared__ float sv[32][65];
    __shared__ float stime[32];
    int tx = threadIdx.x, ty = threadIdx.y;
    #pragma unroll
    for (int i = 0; i < 32; i += 8) {
        int tok = i + ty;
        const f16* src = vs + (size_t)(b * 1024 + tg * 32 + tok) * 1024 + h * 64;
        sv[tok][1 + tx] = __half2float(src[tx]);
        sv[tok][33 + tx] = __half2float(src[tx + 32]);
    }
    __syncthreads();
    if (ty == 0) {
        float s = 0.f;
        #pragma unroll
        for (int d = 1; d <= 64; d++) { float x = sv[tx][d]; s += x * x; }
        stime[tx] = sqrtf(s + 1.f);
    }
    __syncthreads();
    size_t base = (size_t)bh * (72 * 1024) + (size_t)(tg * 32);
    for (int d = ty; d < 72; d += 8) {
        float v = (d == 0) ? stime[tx] : (d < 65 ? sv[tx][d] : 0.f);
        Th[base + (size_t)d * 1024 + tx] = __float2half(v);
    }
}

// ===================== Lorentz residual (fp32 out) =====================
__global__ __launch_bounds__(256)
void k_lresnet(const float* __restrict__ xin, const float* __restrict__ spart,
               const float* __restrict__ wp, float* __restrict__ out)
{
    __shared__ float sbuf[32];
    int t = blockIdx.x, tid = threadIdx.x;
    float w = wp[0];
    const float* xr = xin + (size_t)t * 1024;
    const float* ar = spart + (size_t)t * 1023;
    float xs[4], as[4];
    float sa = 0.f;
    #pragma unroll
    for (int j = 0; j < 4; j++) {
        int i = tid + j * 256;
        xs[j] = 0.f; as[j] = 0.f;
        if (i < 1023) { xs[j] = xr[1 + i]; as[j] = ar[i]; sa += as[j] * as[j]; }
    }
    sa = blk_sum(sa, sbuf);
    float axt = sqrtf(sa + 1.f);
    float zt = xr[0] + w * axt;
    float sz = 0.f;
    #pragma unroll
    for (int j = 0; j < 4; j++) {
        int i = tid + j * 256;
        if (i < 1023) { xs[j] = xs[j] + w * as[j]; sz += xs[j] * xs[j]; }
    }
    sz = blk_sum(sz, sbuf);
    float inv = rsqrtf(fmaxf(zt * zt - sz, 1e-8f));
    if (tid == 0) out[(size_t)t * 1024] = zt * inv;
    #pragma unroll
    for (int j = 0; j < 4; j++) {
        int i = tid + j * 256;
        if (i < 1023) out[(size_t)t * 1024 + 1 + i] = xs[j] * inv;
    }
}

// ===================== fused lresnet1 + LN2: writes x1 (fp32) and h1h (fp16) =====================
__global__ __launch_bounds__(256)
void k_lresnet_ln(const float* __restrict__ xin, const float* __restrict__ spart,
                  const float* __restrict__ wp,
                  const float* __restrict__ g2, const float* __restrict__ b2,
                  float* __restrict__ x1, f16* __restrict__ h1h)
{
    __shared__ float sbuf[32];
    int t = blockIdx.x, tid = threadIdx.x;
    float w = wp[0];
    const float* xr = xin + (size_t)t * 1024;
    const float* ar = spart + (size_t)t * 1023;
    float xs[4], as[4];
    float sa = 0.f;
    #pragma unroll
    for (int j = 0; j < 4; j++) {
        int i = tid + j * 256;
        xs[j] = 0.f; as[j] = 0.f;
        if (i < 1023) { xs[j] = xr[1 + i]; as[j] = ar[i]; sa += as[j] * as[j]; }
    }
    sa = blk_sum(sa, sbuf);
    float axt = sqrtf(sa + 1.f);
    float zt = xr[0] + w * axt;
    float sz = 0.f;
    #pragma unroll
    for (int j = 0; j < 4; j++) {
        int i = tid + j * 256;
        if (i < 1023) { xs[j] = xs[j] + w * as[j]; sz += xs[j] * xs[j]; }
    }
    sz = blk_sum(sz, sbuf);
    float inv = rsqrtf(fmaxf(zt * zt - sz, 1e-8f));
    // x1 values
    float s1 = 0.f, s2 = 0.f;
    #pragma unroll
    for (int j = 0; j < 4; j++) {
        int i = tid + j * 256;
        if (i < 1023) {
            xs[j] *= inv;
            x1[(size_t)t * 1024 + 1 + i] = xs[j];
            s1 += xs[j]; s2 += xs[j] * xs[j];
        }
    }
    if (tid == 0) x1[(size_t)t * 1024] = zt * inv;
    // LN2 on xs
    s1 = blk_sum(s1, sbuf);
    s2 = blk_sum(s2, sbuf);
    float mu = s1 * (1.f / 1023.f);
    float var = s2 * (1.f / 1023.f) - mu * mu;
    float rstd = rsqrtf(var + 1e-5f);
    float q = 0.f;
    float yv[4];
    #pragma unroll
    for (int j = 0; j < 4; j++) {
        int i = tid + j * 256;
        yv[j] = 0.f;
        if (i < 1023) {
            yv[j] = (xs[j] - mu) * rstd * g2[i] + b2[i];
            q += yv[j] * yv[j];
        }
    }
    q = blk_sum(q, sbuf);
    size_t base = (size_t)t * 1024;
    #pragma unroll
    for (int j = 0; j < 4; j++) {
        int i = tid + j * 256;
        if (i < 1023) h1h[base + 1 + i] = __float2half(yv[j]);
    }
    if (tid == 0) h1h[base] = __float2half(sqrtf(q + 1.f));
}

// ===================== host =====================
extern "C" void kernel_launch(void* const* d_in, const int* in_sizes, int n_in,
                              void* d_out, int out_size)
{
    const float* x   = (const float*)d_in[0];
    const float* g1  = (const float*)d_in[1];
    const float* b1  = (const float*)d_in[2];
    const float* Wq  = (const float*)d_in[3];
    const float* bq  = (const float*)d_in[4];
    const float* Wk  = (const float*)d_in[5];
    const float* bk  = (const float*)d_in[6];
    const float* Wv  = (const float*)d_in[7];
    const float* bv  = (const float*)d_in[8];
    const float* Wo  = (const float*)d_in[9];
    const float* bo  = (const float*)d_in[10];
    const float* g2  = (const float*)d_in[11];
    const float* b2  = (const float*)d_in[12];
    const float* Wfc = (const float*)d_in[13];
    const float* bfc = (const float*)d_in[14];
    const float* Wpj = (const float*)d_in[15];
    const float* bpj = (const float*)d_in[16];
    const float* w1  = (const float*)d_in[17];
    const float* w2  = (const float*)d_in[18];
    float* out = (float*)d_out;

    cudaFuncSetAttribute(gemm1p<float>, cudaFuncAttributeMaxDynamicSharedMemorySize, SMEM_1P64);
    cudaFuncSetAttribute(gemm1p<f16>, cudaFuncAttributeMaxDynamicSharedMemorySize, SMEM_1P64);
    cudaFuncSetAttribute(gemm1p_lift, cudaFuncAttributeMaxDynamicSharedMemorySize, SMEM_1P64);
    cudaFuncSetAttribute(gemm1p_gelu, cudaFuncAttributeMaxDynamicSharedMemorySize, SMEM_1P64);
    cudaFuncSetAttribute(flash_attn, cudaFuncAttributeMaxDynamicSharedMemorySize, FSM_TOTAL);

    #define SYM(p, s) do { void* _t; cudaGetSymbolAddress(&_t, s); p = decltype(p)(_t); } while (0)
    f16 *lxh, *WqTh, *WkTh, *WvTh, *WoTh, *WfcTh, *WpjTh;
    f16 *vs16, *qhh, *khh, *vTh, *cath, *h1h, *fch;
    float *axs, *x1, *qsum, *pjs;
    SYM(lxh, g_lxh);
    SYM(WqTh, g_WqTh); SYM(WkTh, g_WkTh); SYM(WvTh, g_WvTh);
    SYM(WoTh, g_WoTh);
    SYM(WfcTh, g_WfcTh); SYM(WpjTh, g_WpjTh);
    SYM(vs16, g_vs16);
    SYM(qhh, g_qhh); SYM(khh, g_khh);
    SYM(vTh, g_vTh);
    SYM(cath, g_cath);
    SYM(axs, g_axs); SYM(x1, g_x1); SYM(h1h, g_h1h);
    SYM(fch, g_fch); SYM(qsum, g_qsum); SYM(pjs, g_pjs);

    dim3 tb(32, 8);
    k_tsplit_h<<<dim3(32, 32), tb>>>(Wq, WqTh, 1024, 1024, 1024);
    k_tsplit_h<<<dim3(32, 32), tb>>>(Wk, WkTh, 1024, 1024, 1024);
    k_tsplit_h<<<dim3(32, 32), tb>>>(Wv, WvTh, 1024, 1024, 1024);
    k_tsplit_h<<<dim3(32, 33), tb>>>(Wo, WoTh, 1040, 1023, 1088);
    k_ln<<<TT, 256>>>(x, g1, b1, lxh);

    // QKV: q/k with fused lift, v to fp16
    {
        dim3 grid(8, 32, 1);
        gemm1p_lift<<<grid, 256, SMEM_1P64>>>(lxh, WqTh, bq, qhh, -1.f);
        gemm1p_lift<<<grid, 256, SMEM_1P64>>>(lxh, WkTh, bk, khh, 1.f);
        gemm1p<f16><<<grid, 256, SMEM_1P64>>>(lxh, WvTh, bv, vs16, 1024, 1024, 1024, 1024, 1024);
    }

    // remaining weight transposes + qsum zero
    k_tsplit_h<<<dim3(128, 32), tb>>>(Wfc, WfcTh, 1024, 4095, 1024);
    k_tsplit_h<<<dim3(32, 128), tb>>>(Wpj, WpjTh, 4096, 1023, 4096);
    k_zero<<<TT / 256, 256>>>(qsum, TT);

    // v lift+transpose
    k_liftT<<<BHN * 32, tb>>>(vs16, vTh);

    // fused flash attention -> cat
    flash_attn<<<dim3(8, BHN), 256, FSM_TOTAL>>>(qhh, khh, vTh, cath);

    // Wo
    gemm1p<float><<<dim3(8, 32, 1), 256, SMEM_1P64>>>(cath, WoTh, bo, axs,
        1088, 1088, 1023, 1023, 1088);

    // fused residual1 + LN2
    k_lresnet_ln<<<TT, 256>>>(x, axs, w1, g2, b2, x1, h1h);

    // Wfc with fused GELU, then time column
    gemm1p_gelu<<<dim3(32, 32, 1), 256, SMEM_1P64>>>(h1h, WfcTh, bfc, fch, qsum, 4095);
    k_time<<<TT / 256, 256>>>(qsum, fch);

    // Wpj
    gemm1p<float><<<dim3(8, 32, 1), 256, SMEM_1P64>>>(fch, WpjTh, bpj, pjs,
        4096, 4096, 1023, 1023, 4096);

    // residual 2
    k_lresnet<<<TT, 256>>>(x1, pjs, w2, out);
}

// round 17
// speedup vs baseline: 4.5476x; 1.0335x over previous
#include <cuda_runtime.h>
#include <cuda_bf16.h>
#include <cuda_fp16.h>
#include <math.h>
#include <stdint.h>

// Problem constants
#define BB 4
#define NNTOK 1024
#define DDIM 1024
#define HH 16
#define TT (BB*NNTOK)     // 4096 tokens
#define BHN (BB*HH)       // 64
#define QKLD 80           // padded lifted q/k leading dim (65 -> 80)

typedef __half f16;

// ===================== scratch (device globals; zero-initialized at load) =====================
__device__ __align__(128) f16   g_lxh [TT*1024];
__device__ __align__(128) f16   g_WqTh[1024*1024];
__device__ __align__(128) f16   g_WkTh[1024*1024];
__device__ __align__(128) f16   g_WvTh[1024*1024];
__device__ __align__(128) f16   g_WoTh[1024*1088];
__device__ __align__(128) f16   g_WfcTh[4096*1024];
__device__ __align__(128) f16   g_WpjTh[1024*4096];
__device__ __align__(128) f16   g_vs16[TT*1024];
__device__ __align__(128) f16   g_qhh [(size_t)BHN*1024*QKLD];  // pads 65..79 stay zero
__device__ __align__(128) f16   g_khh [(size_t)BHN*1024*QKLD];
__device__ __align__(128) f16   g_vTh [(size_t)BHN*72*1024];
__device__ __align__(128) f16   g_cath[TT*1088];
__device__ __align__(128) float g_axs [TT*1023];
__device__ __align__(128) float g_x1  [TT*1024];
__device__ __align__(128) f16   g_h1h [TT*1024];
__device__ __align__(128) f16   g_fch [(size_t)TT*4096];
__device__ __align__(128) float g_qsum[TT];
__device__ __align__(128) float g_pjs [TT*1023];

// ===================== PTX helpers =====================
__device__ __forceinline__ uint32_t smem_u32(const void* p) {
    uint32_t a;
    asm("{ .reg .u64 t; cvta.to.shared.u64 t, %1; cvt.u32.u64 %0, t; }" : "=r"(a) : "l"(p));
    return a;
}

#define CP_ASYNC16(dst, src) \
    asm volatile("cp.async.cg.shared.global [%0], [%1], 16;" :: "r"(dst), "l"(src))
#define CP_COMMIT() asm volatile("cp.async.commit_group;")
#define CP_WAIT1()  asm volatile("cp.async.wait_group 1;")
#define CP_WAIT0()  asm volatile("cp.async.wait_group 0;")

__device__ __forceinline__ void mma16816h(float* c, const uint32_t* a, const uint32_t* b) {
    asm volatile(
        "mma.sync.aligned.m16n8k16.row.col.f32.f16.f16.f32 "
        "{%0,%1,%2,%3}, {%4,%5,%6,%7}, {%8,%9}, {%0,%1,%2,%3};"
        : "+f"(c[0]), "+f"(c[1]), "+f"(c[2]), "+f"(c[3])
        : "r"(a[0]), "r"(a[1]), "r"(a[2]), "r"(a[3]), "r"(b[0]), "r"(b[1]));
}

__device__ __forceinline__ uint32_t pack_hi2h(float a, float b) {
    __half2 r = __floats2half2_rn(a, b);
    return *(uint32_t*)&r;
}

// ===================== block reductions =====================
__device__ __forceinline__ float blk_sum(float v, float* sbuf) {
    int tid = threadIdx.x;
    #pragma unroll
    for (int o = 16; o > 0; o >>= 1) v += __shfl_down_sync(0xffffffffu, v, o);
    if ((tid & 31) == 0) sbuf[tid >> 5] = v;
    __syncthreads();
    if (tid < 32) {
        int nw = (blockDim.x + 31) >> 5;
        float x = (tid < nw) ? sbuf[tid] : 0.f;
        #pragma unroll
        for (int o = 16; o > 0; o >>= 1) x += __shfl_down_sync(0xffffffffu, x, o);
        if (tid == 0) sbuf[0] = x;
    }
    __syncthreads();
    float r = sbuf[0];
    __syncthreads();
    return r;
}

// ===================== shared GEMM mainloop =====================
#define GEMM_KC 64
#define GEMM_ROWB 144
#define GEMM_STGMAT (128*GEMM_ROWB)
#define GEMM_STGSZ (2*GEMM_STGMAT)
#define SMEM_1P64 (2*GEMM_STGSZ)   // 73728

#define GEMM_MAINLOOP(Ah, Bh, lda, ldb, K)                                          \
    constexpr int KC = GEMM_KC;                                                     \
    constexpr int ROWB = GEMM_ROWB;                                                 \
    constexpr int STG_MAT = GEMM_STGMAT;                                            \
    constexpr int STG_SZ = GEMM_STGSZ;                                              \
    constexpr int CPR = KC / 8;                                                     \
    constexpr int LPT = KC / 8;                                                     \
    extern __shared__ char smem[];                                                  \
    int tid = threadIdx.x, w = tid >> 5, lane = tid & 31;                           \
    int m0 = blockIdx.y * 128, n0 = blockIdx.x * 128;                               \
    const int NC = (K) / KC;                                                        \
    auto load_stage = [&](int kofs, int s) {                                        \
        char* stg = smem + s * STG_SZ;                                              \
        _Pragma("unroll")                                                           \
        for (int i = 0; i < LPT; i++) {                                             \
            int idx = tid + i * 256;                                                \
            int mat = idx / (16 * KC);                                              \
            int cc  = idx % (16 * KC);                                              \
            int row = cc / CPR, kc = cc % CPR;                                      \
            uint32_t dst = smem_u32(stg + mat * STG_MAT + row * ROWB + kc * 16);    \
            const f16* p = (mat == 0) ? (Ah) : (Bh);                                \
            int b0 = (mat == 0) ? m0 : n0;                                          \
            int ld = (mat == 0) ? (lda) : (ldb);                                    \
            CP_ASYNC16(dst, p + (size_t)(b0 + row) * ld + kofs + kc * 8);           \
        }                                                                           \
        CP_COMMIT();                                                                \
    };                                                                              \
    load_stage(0, 0);                                                               \
    if (NC > 1) load_stage(KC, 1);                                                  \
    int g = lane >> 2, t = lane & 3;                                                \
    int wm = (w & 3) * 32, wn = (w >> 2) * 64;                                      \
    float acc[2][8][4];                                                             \
    _Pragma("unroll")                                                               \
    for (int mt = 0; mt < 2; mt++)                                                  \
        _Pragma("unroll")                                                           \
        for (int nt = 0; nt < 8; nt++)                                              \
            _Pragma("unroll")                                                       \
            for (int r = 0; r < 4; r++) acc[mt][nt][r] = 0.f;                       \
    for (int kc = 0; kc < NC; kc++) {                                               \
        if (kc + 1 < NC) { CP_WAIT1(); } else { CP_WAIT0(); }                       \
        __syncthreads();                                                            \
        const char* stg = smem + (kc & 1) * STG_SZ;                                 \
        const char* pAh = stg;                                                      \
        const char* pBh = stg + STG_MAT;                                            \
        _Pragma("unroll")                                                           \
        for (int ko = 0; ko < KC; ko += 16) {                                       \
            uint32_t aH[2][4], b[8][2];                                             \
            _Pragma("unroll")                                                       \
            for (int mt = 0; mt < 2; mt++) {                                        \
                int r0 = (wm + mt * 16 + g) * ROWB + (ko + t * 2) * 2;              \
                aH[mt][0] = *(const uint32_t*)(pAh + r0);                           \
                aH[mt][1] = *(const uint32_t*)(pAh + r0 + 8 * ROWB);                \
                aH[mt][2] = *(const uint32_t*)(pAh + r0 + 16);                      \
                aH[mt][3] = *(const uint32_t*)(pAh + r0 + 8 * ROWB + 16);           \
            }                                                                       \
            _Pragma("unroll")                                                       \
            for (int nt = 0; nt < 8; nt++) {                                        \
                int r0 = (wn + nt * 8 + g) * ROWB + (ko + t * 2) * 2;               \
                b[nt][0] = *(const uint32_t*)(pBh + r0);                            \
                b[nt][1] = *(const uint32_t*)(pBh + r0 + 16);                       \
            }                                                                       \
            _Pragma("unroll")                                                       \
            for (int mt = 0; mt < 2; mt++)                                          \
                _Pragma("unroll")                                                   \
                for (int nt = 0; nt < 8; nt++)                                      \
                    mma16816h(acc[mt][nt], aH[mt], b[nt]);                          \
        }                                                                           \
        __syncthreads();                                                            \
        if (kc + 2 < NC) load_stage((kc + 2) * KC, kc & 1);                         \
    }

// ===================== fp16 1-pass GEMM, templated output type =====================
template<typename OutT>
__global__ __launch_bounds__(256)
void gemm1p(const f16* __restrict__ Ah, const f16* __restrict__ Bh,
            const float* __restrict__ bias, OutT* __restrict__ C,
            int lda, int ldb, int ldc, int Nreal, int K)
{
    GEMM_MAINLOOP(Ah, Bh, lda, ldb, K)

    #pragma unroll
    for (int mt = 0; mt < 2; mt++) {
        int r0 = m0 + wm + mt * 16 + g;
        OutT* c0p = C + (size_t)r0 * ldc;
        OutT* c1p = C + (size_t)(r0 + 8) * ldc;
        #pragma unroll
        for (int nt = 0; nt < 8; nt++) {
            int n = n0 + wn + nt * 8 + t * 2;
            if (n < Nreal) {
                float bv = bias ? bias[n] : 0.f;
                c0p[n] = (OutT)(acc[mt][nt][0] + bv);
                c1p[n] = (OutT)(acc[mt][nt][2] + bv);
            }
            if (n + 1 < Nreal) {
                float bv = bias ? bias[n + 1] : 0.f;
                c0p[n + 1] = (OutT)(acc[mt][nt][1] + bv);
                c1p[n + 1] = (OutT)(acc[mt][nt][3] + bv);
            }
        }
    }
}

// ===================== merged QKV GEMM (z=0:q lift -1, z=1:k lift +1, z=2:v plain) =====================
__global__ __launch_bounds__(256)
void gemm_qkv(const f16* __restrict__ Ah,
              const f16* __restrict__ Wq, const f16* __restrict__ Wk, const f16* __restrict__ Wv,
              const float* __restrict__ bq, const float* __restrict__ bk, const float* __restrict__ bv,
              f16* __restrict__ qhh, f16* __restrict__ khh, f16* __restrict__ vs16)
{
    int z = blockIdx.z;
    const f16* Bsel = (z == 0) ? Wq : (z == 1) ? Wk : Wv;
    const float* bias = (z == 0) ? bq : (z == 1) ? bk : bv;

    GEMM_MAINLOOP(Ah, Bsel, 1024, 1024, 1024)

    if (z == 2) {
        #pragma unroll
        for (int mt = 0; mt < 2; mt++) {
            int r0 = m0 + wm + mt * 16 + g;
            f16* c0p = vs16 + (size_t)r0 * 1024;
            f16* c1p = vs16 + (size_t)(r0 + 8) * 1024;
            #pragma unroll
            for (int nt = 0; nt < 8; nt++) {
                int n = n0 + wn + nt * 8 + t * 2;
                float b0v = bias[n], b1v = bias[n + 1];
                c0p[n] = __float2half(acc[mt][nt][0] + b0v);
                c0p[n + 1] = __float2half(acc[mt][nt][1] + b1v);
                c1p[n] = __float2half(acc[mt][nt][2] + b0v);
                c1p[n + 1] = __float2half(acc[mt][nt][3] + b1v);
            }
        }
        return;
    }

    f16* Out = (z == 0) ? qhh : khh;
    float sign = (z == 0) ? -1.f : 1.f;
    int h = (n0 + wn) >> 6;
    #pragma unroll
    for (int mt = 0; mt < 2; mt++) {
        int row = m0 + wm + mt * 16 + g;
        float v[2][16];
        float s0 = 0.f, s1 = 0.f;
        #pragma unroll
        for (int nt = 0; nt < 8; nt++) {
            int n = n0 + wn + nt * 8 + t * 2;
            float b0v = bias[n], b1v = bias[n + 1];
            v[0][2 * nt]     = acc[mt][nt][0] + b0v;
            v[0][2 * nt + 1] = acc[mt][nt][1] + b1v;
            v[1][2 * nt]     = acc[mt][nt][2] + b0v;
            v[1][2 * nt + 1] = acc[mt][nt][3] + b1v;
            s0 += v[0][2 * nt] * v[0][2 * nt] + v[0][2 * nt + 1] * v[0][2 * nt + 1];
            s1 += v[1][2 * nt] * v[1][2 * nt] + v[1][2 * nt + 1] * v[1][2 * nt + 1];
        }
        s0 += __shfl_xor_sync(0xffffffffu, s0, 1);
        s0 += __shfl_xor_sync(0xffffffffu, s0, 2);
        s1 += __shfl_xor_sync(0xffffffffu, s1, 1);
        s1 += __shfl_xor_sync(0xffffffffu, s1, 2);
        #pragma unroll
        for (int rr = 0; rr < 2; rr++) {
            int r = row + rr * 8;
            int b = r >> 10, tok = r & 1023;
            size_t base = ((size_t)(b * HH + h) * 1024 + tok) * QKLD;
            #pragma unroll
            for (int nt = 0; nt < 8; nt++) {
                int d = nt * 8 + t * 2;
                Out[base + 1 + d] = __float2half(v[rr][2 * nt]);
                Out[base + 2 + d] = __float2half(v[rr][2 * nt + 1]);
            }
            if (t == 0)
                Out[base] = __float2half(sign * sqrtf((rr ? s1 : s0) + 1.f));
        }
    }
}

// ===================== Wfc GEMM with fused GELU + row sum-of-squares =====================
__global__ __launch_bounds__(256)
void gemm1p_gelu(const f16* __restrict__ Ah, const f16* __restrict__ Bh,
                 const float* __restrict__ bias, f16* __restrict__ Cf,
                 float* __restrict__ qsum, int Nreal)
{
    GEMM_MAINLOOP(Ah, Bh, 1024, 1024, 1024)

    #pragma unroll
    for (int mt = 0; mt < 2; mt++) {
        int r0 = m0 + wm + mt * 16 + g;
        f16* c0p = Cf + (size_t)r0 * 4096 + 1;
        f16* c1p = Cf + (size_t)(r0 + 8) * 4096 + 1;
        float s0 = 0.f, s1 = 0.f;
        #pragma unroll
        for (int nt = 0; nt < 8; nt++) {
            int n = n0 + wn + nt * 8 + t * 2;
            if (n < Nreal) {
                float bv = bias[n];
                float v0 = acc[mt][nt][0] + bv;
                float v2 = acc[mt][nt][2] + bv;
                float g0 = 0.5f * v0 * (1.f + erff(v0 * 0.70710678118654752f));
                float g2 = 0.5f * v2 * (1.f + erff(v2 * 0.70710678118654752f));
                c0p[n] = __float2half(g0); s0 += g0 * g0;
                c1p[n] = __float2half(g2); s1 += g2 * g2;
            }
            if (n + 1 < Nreal) {
                float bv = bias[n + 1];
                float v1 = acc[mt][nt][1] + bv;
                float v3 = acc[mt][nt][3] + bv;
                float g1 = 0.5f * v1 * (1.f + erff(v1 * 0.70710678118654752f));
                float g3 = 0.5f * v3 * (1.f + erff(v3 * 0.70710678118654752f));
                c0p[n + 1] = __float2half(g1); s0 += g1 * g1;
                c1p[n + 1] = __float2half(g3); s1 += g3 * g3;
            }
        }
        s0 += __shfl_xor_sync(0xffffffffu, s0, 1);
        s0 += __shfl_xor_sync(0xffffffffu, s0, 2);
        s1 += __shfl_xor_sync(0xffffffffu, s1, 1);
        s1 += __shfl_xor_sync(0xffffffffu, s1, 2);
        if (t == 0) {
            atomicAdd(&qsum[r0], s0);
            atomicAdd(&qsum[r0 + 8], s1);
        }
    }
}

__global__ void k_zero(float* __restrict__ p, int n) {
    int i = blockIdx.x * 256 + threadIdx.x;
    if (i < n) p[i] = 0.f;
}
__global__ void k_time(const float* __restrict__ qsum, f16* __restrict__ fch) {
    int i = blockIdx.x * 256 + threadIdx.x;
    if (i < TT) fch[(size_t)i * 4096] = __float2half(sqrtf(qsum[i] + 1.f));
}

// ===================== fused flash attention (no-max softmax; scores provably <= -0.25) =====================
#define FQ_ROWB 176
#define FV_ROWB 144
#define FSM_QMAT (128*FQ_ROWB)
#define FSM_K0   FSM_QMAT
#define FSM_KSTG (64*FQ_ROWB)
#define FSM_V0   (FSM_K0 + 2*FSM_KSTG)
#define FSM_VSTG (72*FV_ROWB)
#define FSM_TOTAL (FSM_V0 + 2*FSM_VSTG)   // 65792

__global__ __launch_bounds__(256)
void flash_attn(const f16* __restrict__ qhh,
                const f16* __restrict__ khh,
                const f16* __restrict__ vth,
                f16* __restrict__ cath)
{
    extern __shared__ char smem[];
    int tid = threadIdx.x, w = tid >> 5, lane = tid & 31;
    int g = lane >> 2, t = lane & 3;
    int bh = blockIdx.y;
    int q0 = blockIdx.x * 128;

    {
        #pragma unroll
        for (int i = 0; i < 5; i++) {
            int idx = tid + i * 256;
            int row = idx / 10, ch = idx % 10;
            const f16* src = qhh + ((size_t)bh * 1024 + q0 + row) * QKLD + ch * 8;
            uint32_t dst = smem_u32(smem + row * FQ_ROWB + ch * 16);
            CP_ASYNC16(dst, src);
        }
        CP_COMMIT();
    }

    auto load_kv = [&](int kt, int s) {
        char* kb = smem + FSM_K0 + s * FSM_KSTG;
        char* vb = smem + FSM_V0 + s * FSM_VSTG;
        #pragma unroll
        for (int i = 0; i < 5; i++) {
            int idx = tid + i * 256;
            if (idx < 640) {
                int row = idx / 10, ch = idx % 10;
                const f16* src = khh + ((size_t)bh * 1024 + kt * 64 + row) * QKLD + ch * 8;
                uint32_t dst = smem_u32(kb + row * FQ_ROWB + ch * 16);
                CP_ASYNC16(dst, src);
            } else if (idx < 1216) {
                int cc = idx - 640;
                int row = cc / 8, ch = cc % 8;
                const f16* src = vth + ((size_t)bh * 72 + row) * 1024 + kt * 64 + ch * 8;
                uint32_t dst = smem_u32(vb + row * FV_ROWB + ch * 16);
                CP_ASYNC16(dst, src);
            }
        }
        CP_COMMIT();
    };

    load_kv(0, 0);

    float O[9][4];
    #pragma unroll
    for (int nv = 0; nv < 9; nv++)
        #pragma unroll
        for (int r = 0; r < 4; r++) O[nv][r] = 0.f;
    float l0 = 0.f, l1 = 0.f;

    for (int kt = 0; kt < 16; kt++) {
        if (kt + 1 < 16) { load_kv(kt + 1, (kt + 1) & 1); CP_WAIT1(); }
        else { CP_WAIT0(); }
        __syncthreads();
        const char* pK = smem + FSM_K0 + (kt & 1) * FSM_KSTG;
        const char* pV = smem + FSM_V0 + (kt & 1) * FSM_VSTG;

        float S[8][4];
        #pragma unroll
        for (int nt = 0; nt < 8; nt++)
            #pragma unroll
            for (int r = 0; r < 4; r++) S[nt][r] = 0.f;

        #pragma unroll
        for (int kk = 0; kk < 5; kk++) {
            uint32_t aH[4], b[2];
            int r0 = (w * 16 + g) * FQ_ROWB + (kk * 16 + t * 2) * 2;
            aH[0] = *(const uint32_t*)(smem + r0);
            aH[1] = *(const uint32_t*)(smem + r0 + 8 * FQ_ROWB);
            aH[2] = *(const uint32_t*)(smem + r0 + 16);
            aH[3] = *(const uint32_t*)(smem + r0 + 8 * FQ_ROWB + 16);
            #pragma unroll
            for (int nt = 0; nt < 8; nt++) {
                int rb = (nt * 8 + g) * FQ_ROWB + (kk * 16 + t * 2) * 2;
                b[0] = *(const uint32_t*)(pK + rb);
                b[1] = *(const uint32_t*)(pK + rb + 16);
                mma16816h(S[nt], aH, b);
            }
        }

        // p = exp(0.25*dot); dot <= -1 always (Lorentz) so exponent <= -0.25: no overflow.
        #pragma unroll
        for (int nt = 0; nt < 8; nt++) {
            S[nt][0] = __expf(S[nt][0] * 0.25f);
            S[nt][1] = __expf(S[nt][1] * 0.25f);
            S[nt][2] = __expf(S[nt][2] * 0.25f);
            S[nt][3] = __expf(S[nt][3] * 0.25f);
            l0 += S[nt][0] + S[nt][1];
            l1 += S[nt][2] + S[nt][3];
        }

        #pragma unroll
        for (int ks = 0; ks < 4; ks++) {
            uint32_t pH[4], b[2];
            pH[0] = pack_hi2h(S[2 * ks][0], S[2 * ks][1]);
            pH[1] = pack_hi2h(S[2 * ks][2], S[2 * ks][3]);
            pH[2] = pack_hi2h(S[2 * ks + 1][0], S[2 * ks + 1][1]);
            pH[3] = pack_hi2h(S[2 * ks + 1][2], S[2 * ks + 1][3]);
            #pragma unroll
            for (int nv = 0; nv < 9; nv++) {
                int rb = (nv * 8 + g) * FV_ROWB + (ks * 16 + t * 2) * 2;
                b[0] = *(const uint32_t*)(pV + rb);
                b[1] = *(const uint32_t*)(pV + rb + 16);
                mma16816h(O[nv], pH, b);
            }
        }
        __syncthreads();
    }

    l0 += __shfl_xor_sync(0xffffffffu, l0, 1);
    l0 += __shfl_xor_sync(0xffffffffu, l0, 2);
    l1 += __shfl_xor_sync(0xffffffffu, l1, 1);
    l1 += __shfl_xor_sync(0xffffffffu, l1, 2);
    float r0 = 1.f / l0, r1 = 1.f / l1;
    #pragma unroll
    for (int nv = 0; nv < 9; nv++) {
        O[nv][0] *= r0; O[nv][1] *= r0;
        O[nv][2] *= r1; O[nv][3] *= r1;
    }
    float t0 = __shfl_sync(0xffffffffu, O[0][0], lane & ~3);
    float t1 = __shfl_sync(0xffffffffu, O[0][2], lane & ~3);
    float ss0 = 0.f, ss1 = 0.f;
    #pragma unroll
    for (int nv = 0; nv < 9; nv++) {
        int c = nv * 8 + 2 * t;
        if (c >= 1 && c < 65) { ss0 += O[nv][0] * O[nv][0]; ss1 += O[nv][2] * O[nv][2]; }
        if (c + 1 >= 1 && c + 1 < 65) { ss0 += O[nv][1] * O[nv][1]; ss1 += O[nv][3] * O[nv][3]; }
    }
    ss0 += __shfl_xor_sync(0xffffffffu, ss0, 1);
    ss0 += __shfl_xor_sync(0xffffffffu, ss0, 2);
    ss1 += __shfl_xor_sync(0xffffffffu, ss1, 1);
    ss1 += __shfl_xor_sync(0xffffffffu, ss1, 2);
    float inv0 = rsqrtf(fmaxf(t0 * t0 - ss0, 1e-8f));
    float inv1 = rsqrtf(fmaxf(t1 * t1 - ss1, 1e-8f));

    int b = bh >> 4, h = bh & 15;
    int tr0 = b * 1024 + q0 + w * 16 + g;
    size_t base0 = (size_t)tr0 * 1088 + h * 65;
    size_t base1 = (size_t)(tr0 + 8) * 1088 + h * 65;
    #pragma unroll
    for (int nv = 0; nv < 9; nv++) {
        int c = nv * 8 + 2 * t;
        if (c < 65) {
            cath[base0 + c] = __float2half(O[nv][0] * inv0);
            cath[base1 + c] = __float2half(O[nv][2] * inv1);
        }
        if (c + 1 < 65) {
            cath[base0 + c + 1] = __float2half(O[nv][1] * inv0);
            cath[base1 + c + 1] = __float2half(O[nv][3] * inv1);
        }
    }
}

// ===================== weight transposes =====================
__global__ void k_tsplit_h(const float* __restrict__ W, f16* __restrict__ Th,
                           int K, int N, int Kpad)
{
    __shared__ float t[32][33];
    int nb = blockIdx.x * 32, kb = blockIdx.y * 32;
    int tx = threadIdx.x, ty = threadIdx.y;
    #pragma unroll
    for (int i = 0; i < 32; i += 8) {
        int k = kb + ty + i, n = nb + tx;
        t[ty + i][tx] = (k < K && n < N) ? W[(size_t)k * N + n] : 0.f;
    }
    __syncthreads();
    #pragma unroll
    for (int i = 0; i < 32; i += 8) {
        int n = nb + ty + i, k = kb + tx;
        if (n < N && k < K)
            Th[(size_t)n * Kpad + k] = __float2half(t[tx][ty + i]);
    }
}

// 3 square 1024x1024 transposes merged (z selects)
__global__ void k_tsplit_h3(const float* __restrict__ W0, const float* __restrict__ W1,
                            const float* __restrict__ W2,
                            f16* __restrict__ T0, f16* __restrict__ T1, f16* __restrict__ T2)
{
    int z = blockIdx.z;
    const float* W = (z == 0) ? W0 : (z == 1) ? W1 : W2;
    f16* Th = (z == 0) ? T0 : (z == 1) ? T1 : T2;
    __shared__ float t[32][33];
    int nb = blockIdx.x * 32, kb = blockIdx.y * 32;
    int tx = threadIdx.x, ty = threadIdx.y;
    #pragma unroll
    for (int i = 0; i < 32; i += 8)
        t[ty + i][tx] = W[(size_t)(kb + ty + i) * 1024 + nb + tx];
    __syncthreads();
    #pragma unroll
    for (int i = 0; i < 32; i += 8)
        Th[(size_t)(nb + ty + i) * 1024 + kb + tx] = __float2half(t[tx][ty + i]);
}

// ===================== Lorentz layernorm -> fp16 (hi only) =====================
__global__ __launch_bounds__(256)
void k_ln(const float* __restrict__ x, const float* __restrict__ g,
          const float* __restrict__ b, f16* __restrict__ oh)
{
    __shared__ float sbuf[32];
    int t = blockIdx.x, tid = threadIdx.x;
    const float* xs = x + (size_t)t * 1024 + 1;
    float sv[4]; float s1 = 0.f, s2 = 0.f;
    #pragma unroll
    for (int j = 0; j < 4; j++) {
        int i = tid + j * 256;
        sv[j] = 0.f;
        if (i < 1023) { sv[j] = xs[i]; s1 += sv[j]; s2 += sv[j] * sv[j]; }
    }
    s1 = blk_sum(s1, sbuf);
    s2 = blk_sum(s2, sbuf);
    float mu = s1 * (1.f / 1023.f);
    float var = s2 * (1.f / 1023.f) - mu * mu;
    float rstd = rsqrtf(var + 1e-5f);
    float q = 0.f;
    float yv[4];
    #pragma unroll
    for (int j = 0; j < 4; j++) {
        int i = tid + j * 256;
        yv[j] = 0.f;
        if (i < 1023) {
            yv[j] = (sv[j] - mu) * rstd * g[i] + b[i];
            q += yv[j] * yv[j];
        }
    }
    q = blk_sum(q, sbuf);
    size_t base = (size_t)t * 1024;
    #pragma unroll
    for (int j = 0; j < 4; j++) {
        int i = tid + j * 256;
        if (i < 1023) oh[base + 1 + i] = __float2half(yv[j]);
    }
    if (tid == 0) oh[base] = __float2half(sqrtf(q + 1.f));
}

// ===================== lift+transpose v (fp16 in) -> (BH,72,1024) =====================
__global__ void k_liftT(const f16* __restrict__ vs, f16* __restrict__ Th)
{
    int blk = blockIdx.x;
    int bh = blk >> 5;
    int tg = blk & 31;
    int b = bh >> 4, h = bh & 15;
    __shared__ float sv[32][65];
    __shared__ float stime[32];
    int tx = threadIdx.x, ty = threadIdx.y;
    #pragma unroll
    for (int i = 0; i < 32; i += 8) {
        int tok = i + ty;
        const f16* src = vs + (size_t)(b * 1024 + tg * 32 + tok) * 1024 + h * 64;
        sv[tok][1 + tx] = __half2float(src[tx]);
        sv[tok][33 + tx] = __half2float(src[tx + 32]);
    }
    __syncthreads();
    if (ty == 0) {
        float s = 0.f;
        #pragma unroll
        for (int d = 1; d <= 64; d++) { float x = sv[tx][d]; s += x * x; }
        stime[tx] = sqrtf(s + 1.f);
    }
    __syncthreads();
    size_t base = (size_t)bh * (72 * 1024) + (size_t)(tg * 32);
    for (int d = ty; d < 72; d += 8) {
        float v = (d == 0) ? stime[tx] : (d < 65 ? sv[tx][d] : 0.f);
        Th[base + (size_t)d * 1024 + tx] = __float2half(v);
    }
}

// ===================== Lorentz residual (fp32 out) =====================
__global__ __launch_bounds__(256)
void k_lresnet(const float* __restrict__ xin, const float* __restrict__ spart,
               const float* __restrict__ wp, float* __restrict__ out)
{
    __shared__ float sbuf[32];
    int t = blockIdx.x, tid = threadIdx.x;
    float w = wp[0];
    const float* xr = xin + (size_t)t * 1024;
    const float* ar = spart + (size_t)t * 1023;
    float xs[4], as[4];
    float sa = 0.f;
    #pragma unroll
    for (int j = 0; j < 4; j++) {
        int i = tid + j * 256;
        xs[j] = 0.f; as[j] = 0.f;
        if (i < 1023) { xs[j] = xr[1 + i]; as[j] = ar[i]; sa += as[j] * as[j]; }
    }
    sa = blk_sum(sa, sbuf);
    float axt = sqrtf(sa + 1.f);
    float zt = xr[0] + w * axt;
    float sz = 0.f;
    #pragma unroll
    for (int j = 0; j < 4; j++) {
        int i = tid + j * 256;
        if (i < 1023) { xs[j] = xs[j] + w * as[j]; sz += xs[j] * xs[j]; }
    }
    sz = blk_sum(sz, sbuf);
    float inv = rsqrtf(fmaxf(zt * zt - sz, 1e-8f));
    if (tid == 0) out[(size_t)t * 1024] = zt * inv;
    #pragma unroll
    for (int j = 0; j < 4; j++) {
        int i = tid + j * 256;
        if (i < 1023) out[(size_t)t * 1024 + 1 + i] = xs[j] * inv;
    }
}

// ===================== fused lresnet1 + LN2 =====================
__global__ __launch_bounds__(256)
void k_lresnet_ln(const float* __restrict__ xin, const float* __restrict__ spart,
                  const float* __restrict__ wp,
                  const float* __restrict__ g2, const float* __restrict__ b2,
                  float* __restrict__ x1, f16* __restrict__ h1h)
{
    __shared__ float sbuf[32];
    int t = blockIdx.x, tid = threadIdx.x;
    float w = wp[0];
    const float* xr = xin + (size_t)t * 1024;
    const float* ar = spart + (size_t)t * 1023;
    float xs[4], as[4];
    float sa = 0.f;
    #pragma unroll
    for (int j = 0; j < 4; j++) {
        int i = tid + j * 256;
        xs[j] = 0.f; as[j] = 0.f;
        if (i < 1023) { xs[j] = xr[1 + i]; as[j] = ar[i]; sa += as[j] * as[j]; }
    }
    sa = blk_sum(sa, sbuf);
    float axt = sqrtf(sa + 1.f);
    float zt = xr[0] + w * axt;
    float sz = 0.f;
    #pragma unroll
    for (int j = 0; j < 4; j++) {
        int i = tid + j * 256;
        if (i < 1023) { xs[j] = xs[j] + w * as[j]; sz += xs[j] * xs[j]; }
    }
    sz = blk_sum(sz, sbuf);
    float inv = rsqrtf(fmaxf(zt * zt - sz, 1e-8f));
    float s1 = 0.f, s2 = 0.f;
    #pragma unroll
    for (int j = 0; j < 4; j++) {
        int i = tid + j * 256;
        if (i < 1023) {
            xs[j] *= inv;
            x1[(size_t)t * 1024 + 1 + i] = xs[j];
            s1 += xs[j]; s2 += xs[j] * xs[j];
        }
    }
    if (tid == 0) x1[(size_t)t * 1024] = zt * inv;
    s1 = blk_sum(s1, sbuf);
    s2 = blk_sum(s2, sbuf);
    float mu = s1 * (1.f / 1023.f);
    float var = s2 * (1.f / 1023.f) - mu * mu;
    float rstd = rsqrtf(var + 1e-5f);
    float q = 0.f;
    float yv[4];
    #pragma unroll
    for (int j = 0; j < 4; j++) {
        int i = tid + j * 256;
        yv[j] = 0.f;
        if (i < 1023) {
            yv[j] = (xs[j] - mu) * rstd * g2[i] + b2[i];
            q += yv[j] * yv[j];
        }
    }
    q = blk_sum(q, sbuf);
    size_t base = (size_t)t * 1024;
    #pragma unroll
    for (int j = 0; j < 4; j++) {
        int i = tid + j * 256;
        if (i < 1023) h1h[base + 1 + i] = __float2half(yv[j]);
    }
    if (tid == 0) h1h[base] = __float2half(sqrtf(q + 1.f));
}

// ===================== host =====================
extern "C" void kernel_launch(void* const* d_in, const int* in_sizes, int n_in,
                              void* d_out, int out_size)
{
    const float* x   = (const float*)d_in[0];
    const float* g1  = (const float*)d_in[1];
    const float* b1  = (const float*)d_in[2];
    const float* Wq  = (const float*)d_in[3];
    const float* bq  = (const float*)d_in[4];
    const float* Wk  = (const float*)d_in[5];
    const float* bk  = (const float*)d_in[6];
    const float* Wv  = (const float*)d_in[7];
    const float* bv  = (const float*)d_in[8];
    const float* Wo  = (const float*)d_in[9];
    const float* bo  = (const float*)d_in[10];
    const float* g2  = (const float*)d_in[11];
    const float* b2  = (const float*)d_in[12];
    const float* Wfc = (const float*)d_in[13];
    const float* bfc = (const float*)d_in[14];
    const float* Wpj = (const float*)d_in[15];
    const float* bpj = (const float*)d_in[16];
    const float* w1  = (const float*)d_in[17];
    const float* w2  = (const float*)d_in[18];
    float* out = (float*)d_out;

    cudaFuncSetAttribute(gemm1p<float>, cudaFuncAttributeMaxDynamicSharedMemorySize, SMEM_1P64);
    cudaFuncSetAttribute(gemm_qkv, cudaFuncAttributeMaxDynamicSharedMemorySize, SMEM_1P64);
    cudaFuncSetAttribute(gemm1p_gelu, cudaFuncAttributeMaxDynamicSharedMemorySize, SMEM_1P64);
    cudaFuncSetAttribute(flash_attn, cudaFuncAttributeMaxDynamicSharedMemorySize, FSM_TOTAL);

    #define SYM(p, s) do { void* _t; cudaGetSymbolAddress(&_t, s); p = decltype(p)(_t); } while (0)
    f16 *lxh, *WqTh, *WkTh, *WvTh, *WoTh, *WfcTh, *WpjTh;
    f16 *vs16, *qhh, *khh, *vTh, *cath, *h1h, *fch;
    float *axs, *x1, *qsum, *pjs;
    SYM(lxh, g_lxh);
    SYM(WqTh, g_WqTh); SYM(WkTh, g_WkTh); SYM(WvTh, g_WvTh);
    SYM(WoTh, g_WoTh);
    SYM(WfcTh, g_WfcTh); SYM(WpjTh, g_WpjTh);
    SYM(vs16, g_vs16);
    SYM(qhh, g_qhh); SYM(khh, g_khh);
    SYM(vTh, g_vTh);
    SYM(cath, g_cath);
    SYM(axs, g_axs); SYM(x1, g_x1); SYM(h1h, g_h1h);
    SYM(fch, g_fch); SYM(qsum, g_qsum); SYM(pjs, g_pjs);

    dim3 tb(32, 8);
    k_tsplit_h3<<<dim3(32, 32, 3), tb>>>(Wq, Wk, Wv, WqTh, WkTh, WvTh);
    k_tsplit_h<<<dim3(32, 33), tb>>>(Wo, WoTh, 1040, 1023, 1088);
    k_ln<<<TT, 256>>>(x, g1, b1, lxh);

    // merged QKV GEMM (q/k fused lift, v plain fp16)
    gemm_qkv<<<dim3(8, 32, 3), 256, SMEM_1P64>>>(lxh, WqTh, WkTh, WvTh,
        bq, bk, bv, qhh, khh, vs16);

    // remaining weight transposes + qsum zero
    k_tsplit_h<<<dim3(128, 32), tb>>>(Wfc, WfcTh, 1024, 4095, 1024);
    k_tsplit_h<<<dim3(32, 128), tb>>>(Wpj, WpjTh, 4096, 1023, 4096);
    k_zero<<<TT / 256, 256>>>(qsum, TT);

    // v lift+transpose
    k_liftT<<<BHN * 32, tb>>>(vs16, vTh);

    // fused flash attention -> cat
    flash_attn<<<dim3(8, BHN), 256, FSM_TOTAL>>>(qhh, khh, vTh, cath);

    // Wo
    gemm1p<float><<<dim3(8, 32, 1), 256, SMEM_1P64>>>(cath, WoTh, bo, axs,
        1088, 1088, 1023, 1023, 1088);

    // fused residual1 + LN2
    k_lresnet_ln<<<TT, 256>>>(x, axs, w1, g2, b2, x1, h1h);

    // Wfc with fused GELU, then time column
    gemm1p_gelu<<<dim3(32, 32, 1), 256, SMEM_1P64>>>(h1h, WfcTh, bfc, fch, qsum, 4095);
    k_time<<<TT / 256, 256>>>(qsum, fch);

    // Wpj
    gemm1p<float><<<dim3(8, 32, 1), 256, SMEM_1P64>>>(fch, WpjTh, bpj, pjs,
        4096, 4096, 1023, 1023, 4096);

    // residual 2
    k_lresnet<<<TT, 256>>>(x1, pjs, w2, out);
}